// round 1
// baseline (speedup 1.0000x reference)
#include <cuda_runtime.h>
#include <cuda_bf16.h>
#include <math.h>

#define BB 4
#define SS 2048
#define HH 1024
#define KK 64
#define NHH 16
#define DH 64
#define LL 2
#define FFD 2730
#define EPSV 1e-6f

// ---------------- scratch (device globals; no allocation) ----------------
__device__ float g_x[BB*KK*HH];
__device__ float g_h[BB*KK*HH];
__device__ float g_qkv[BB*KK*3*HH];
__device__ float g_attn[BB*KK*HH];
__device__ float g_ff1[BB*KK*FFD];
__device__ float g_ff3[BB*KK*FFD];
__device__ int   g_rank[BB*KK];
__device__ float g_proc[BB*KK*HH];
__device__ float g_q[BB*SS*HH];
__device__ float g_kv[BB*KK*2*HH];
__device__ float g_dec[BB*SS*HH];
__device__ float g_y[BB*SS*HH];
__device__ float g_yn[BB*SS*HH];
__device__ float g_u1[BB*SS*FFD];
__device__ float g_u3[BB*SS*FFD];

// ---------------- rank / scatter / gather ----------------
__global__ void rank_kernel(const float* __restrict__ cw) {
    int b = blockIdx.x;
    int k = threadIdx.x;
    float wk = cw[b*KK + k];
    int r = 0;
    for (int j = 0; j < KK; j++) {
        float wj = cw[b*KK + j];
        if (wj > wk || (wj == wk && j < k)) r++;
    }
    g_rank[b*KK + k] = r;
}

// g_x[b, rank[k]] = chunk_repr[b, k]
__global__ void scatter_kernel(const float* __restrict__ src) {
    int row = blockIdx.x;           // b*KK + k
    int b = row / KK;
    int r = g_rank[row];
    const float* s = src + (size_t)row * HH;
    float* d = g_x + ((size_t)(b*KK + r)) * HH;
    for (int i = threadIdx.x; i < HH; i += blockDim.x) d[i] = s[i];
}

// g_proc[b, k] = g_x[b, rank[k]]
__global__ void gather_kernel() {
    int row = blockIdx.x;
    int b = row / KK;
    int r = g_rank[row];
    const float* s = g_x + ((size_t)(b*KK + r)) * HH;
    float* d = g_proc + (size_t)row * HH;
    for (int i = threadIdx.x; i < HH; i += blockDim.x) d[i] = s[i];
}

// ---------------- rmsnorm (H=1024, 256 threads, 4 elems/thread) ----------------
__global__ void rms_kernel(const float* __restrict__ in, const float* __restrict__ w,
                           float* __restrict__ out) {
    __shared__ float red[256];
    int row = blockIdx.x;
    const float* x = in + (size_t)row * HH;
    float* o = out + (size_t)row * HH;
    int t = threadIdx.x;
    float v[4];
    float ss = 0.f;
#pragma unroll
    for (int i = 0; i < 4; i++) { v[i] = x[t + i*256]; ss += v[i]*v[i]; }
    red[t] = ss;
    __syncthreads();
    for (int ofs = 128; ofs > 0; ofs >>= 1) {
        if (t < ofs) red[t] += red[t + ofs];
        __syncthreads();
    }
    float inv = rsqrtf(red[0] * (1.0f/HH) + EPSV);
#pragma unroll
    for (int i = 0; i < 4; i++) {
        int c = t + i*256;
        o[c] = v[i] * inv * w[c];
    }
}

// ---------------- silu-mul: a = silu(a)*b ----------------
__global__ void silu_mul_kernel(float* __restrict__ a, const float* __restrict__ b, int n) {
    int i = blockIdx.x * blockDim.x + threadIdx.x;
    if (i < n) {
        float u = a[i];
        a[i] = (u / (1.0f + expf(-u))) * b[i];
    }
}

// ---------------- SGEMM: C[M,N] = A[M,Kd] @ W[N,Kd]^T (+bias[n]) (+addend[m,n]) ----------------
#define BM 128
#define BN 128
#define BKT 16
__global__ __launch_bounds__(256) void gemm_kernel(
    const float* __restrict__ A, const float* __restrict__ W,
    const float* __restrict__ bias, const float* __restrict__ addend,
    float* __restrict__ C, int M, int N, int Kd) {
    __shared__ float As[BKT][BM + 4];
    __shared__ float Ws[BKT][BN + 4];
    int bm = blockIdx.y * BM;
    int bn = blockIdx.x * BN;
    int tid = threadIdx.x;
    int tx = tid & 15, ty = tid >> 4;
    float acc[8][8];
#pragma unroll
    for (int i = 0; i < 8; i++)
#pragma unroll
        for (int j = 0; j < 8; j++) acc[i][j] = 0.f;

    for (int k0 = 0; k0 < Kd; k0 += BKT) {
#pragma unroll
        for (int i = 0; i < 8; i++) {
            int idx = tid + i*256;
            int m = idx >> 4, kk = idx & 15;
            int gm = bm + m, gk = k0 + kk;
            As[kk][m] = (gm < M && gk < Kd) ? A[(size_t)gm*Kd + gk] : 0.f;
        }
#pragma unroll
        for (int i = 0; i < 8; i++) {
            int idx = tid + i*256;
            int n = idx >> 4, kk = idx & 15;
            int gn = bn + n, gk = k0 + kk;
            Ws[kk][n] = (gn < N && gk < Kd) ? W[(size_t)gn*Kd + gk] : 0.f;
        }
        __syncthreads();
#pragma unroll
        for (int kk = 0; kk < BKT; kk++) {
            float a[8], w[8];
#pragma unroll
            for (int i = 0; i < 8; i++) a[i] = As[kk][i*16 + ty];
#pragma unroll
            for (int j = 0; j < 8; j++) w[j] = Ws[kk][j*16 + tx];
#pragma unroll
            for (int i = 0; i < 8; i++)
#pragma unroll
                for (int j = 0; j < 8; j++) acc[i][j] += a[i]*w[j];
        }
        __syncthreads();
    }
#pragma unroll
    for (int i = 0; i < 8; i++) {
        int gm = bm + i*16 + ty;
        if (gm >= M) continue;
#pragma unroll
        for (int j = 0; j < 8; j++) {
            int gn = bn + j*16 + tx;
            if (gn >= N) continue;
            float v = acc[i][j];
            if (bias)   v += bias[gn];
            if (addend) v += addend[(size_t)gm*N + gn];
            C[(size_t)gm*N + gn] = v;
        }
    }
}

// ---------------- cascade self-attn (causal, K=64, d=64) ----------------
// grid: B*NH blocks, 64 threads (one per query row)
__global__ void casc_attn_kernel() {
    __shared__ float ks[KK][DH+1];
    __shared__ float vs[KK][DH+1];
    int bh = blockIdx.x;
    int b = bh / NHH, nh = bh % NHH;
    int t = threadIdx.x;  // query row / loader row
    const float* base = g_qkv + ((size_t)(b*KK + t)) * (3*HH);
#pragma unroll
    for (int dd = 0; dd < DH; dd++) {
        ks[t][dd] = base[HH   + nh*DH + dd];
        vs[t][dd] = base[2*HH + nh*DH + dd];
    }
    __syncthreads();
    float q[DH];
#pragma unroll
    for (int dd = 0; dd < DH; dd++) q[dd] = base[nh*DH + dd];

    const float scale = 0.125f;  // 1/sqrt(64)
    float sc[KK];
    float mx = -1e30f;
    for (int j = 0; j <= t; j++) {
        float s = 0.f;
#pragma unroll
        for (int dd = 0; dd < DH; dd++) s += q[dd] * ks[j][dd];
        s *= scale;
        sc[j] = s;
        mx = fmaxf(mx, s);
    }
    float sum = 0.f;
    for (int j = 0; j <= t; j++) {
        float e = expf(sc[j] - mx);
        sc[j] = e;
        sum += e;
    }
    float inv = 1.0f / sum;
    float* o = g_attn + ((size_t)(b*KK + t)) * HH + nh*DH;
#pragma unroll 4
    for (int dd = 0; dd < DH; dd++) {
        float acc = 0.f;
        for (int j = 0; j <= t; j++) acc += sc[j] * vs[j][dd];
        o[dd] = acc * inv;
    }
}

// ---------------- decoder cross-attn ----------------
// grid: (NH, B), 256 threads = 8 warps; each warp handles token rows s = w, w+8, ...
__global__ void dec_attn_kernel() {
    __shared__ float ks[KK][DH+1];
    __shared__ float vs[KK][DH+1];
    __shared__ float qs[8][DH];
    __shared__ float probs[8][KK];
    int nh = blockIdx.x, b = blockIdx.y;
    int tid = threadIdx.x;
    for (int i = tid; i < KK*DH; i += 256) {
        int c = i / DH, dd = i % DH;
        const float* kvrow = g_kv + ((size_t)(b*KK + c)) * (2*HH);
        ks[c][dd] = kvrow[nh*DH + dd];
        vs[c][dd] = kvrow[HH + nh*DH + dd];
    }
    __syncthreads();
    int w = tid >> 5, lane = tid & 31;
    const float scale = 0.125f;
    for (int s = w; s < SS; s += 8) {
        int nallow = min(KK, s/32 + 2);   // c <= s*K/S + SLACK
        const float* qrow = g_q + ((size_t)b*SS + s) * HH + nh*DH;
        qs[w][lane]      = qrow[lane];
        qs[w][lane + 32] = qrow[lane + 32];
        __syncwarp();
        float s0 = -INFINITY, s1 = -INFINITY;
        if (lane < nallow) {
            float acc = 0.f;
#pragma unroll
            for (int dd = 0; dd < DH; dd++) acc += qs[w][dd] * ks[lane][dd];
            s0 = acc * scale;
        }
        if (lane + 32 < nallow) {
            float acc = 0.f;
#pragma unroll
            for (int dd = 0; dd < DH; dd++) acc += qs[w][dd] * ks[lane + 32][dd];
            s1 = acc * scale;
        }
        float mx = fmaxf(s0, s1);
#pragma unroll
        for (int ofs = 16; ofs > 0; ofs >>= 1)
            mx = fmaxf(mx, __shfl_xor_sync(0xffffffffu, mx, ofs));
        float e0 = expf(s0 - mx);
        float e1 = expf(s1 - mx);
        float sum = e0 + e1;
#pragma unroll
        for (int ofs = 16; ofs > 0; ofs >>= 1)
            sum += __shfl_xor_sync(0xffffffffu, sum, ofs);
        float inv = 1.0f / sum;
        probs[w][lane]      = e0 * inv;
        probs[w][lane + 32] = e1 * inv;
        __syncwarp();
        float* orow = g_dec + ((size_t)b*SS + s) * HH + nh*DH;
#pragma unroll
        for (int half = 0; half < 2; half++) {
            int dd = lane + half*32;
            float acc = 0.f;
            for (int j = 0; j < nallow; j++) acc += probs[w][j] * vs[j][dd];
            orow[dd] = acc;
        }
        __syncwarp();
    }
}

// ---------------- host ----------------
static float* symaddr(const void* sym) {
    void* p = nullptr;
    cudaGetSymbolAddress(&p, sym);
    return (float*)p;
}

extern "C" void kernel_launch(void* const* d_in, const int* in_sizes, int n_in,
                              void* d_out, int out_size) {
    const float* token       = (const float*)d_in[0];
    const float* chunk_repr  = (const float*)d_in[1];
    const float* cw          = (const float*)d_in[2];
    const float* casc_norm1  = (const float*)d_in[3];
    const float* casc_qkv    = (const float*)d_in[4];
    const float* casc_o      = (const float*)d_in[5];
    const float* casc_norm2  = (const float*)d_in[6];
    const float* casc_w1     = (const float*)d_in[7];
    const float* casc_w2     = (const float*)d_in[8];
    const float* casc_w3     = (const float*)d_in[9];
    const float* dec_in_w    = (const float*)d_in[10];
    const float* dec_in_b    = (const float*)d_in[11];
    const float* dec_out_w   = (const float*)d_in[12];
    const float* dec_out_b   = (const float*)d_in[13];
    const float* dec_norm_w  = (const float*)d_in[14];
    const float* dec_ffn_nw  = (const float*)d_in[15];
    const float* dec_w1      = (const float*)d_in[16];
    const float* dec_w2      = (const float*)d_in[17];
    const float* dec_w3      = (const float*)d_in[18];
    float* out = (float*)d_out;

    float* px    = symaddr(g_x);
    float* ph    = symaddr(g_h);
    float* pqkv  = symaddr(g_qkv);
    float* pattn = symaddr(g_attn);
    float* pff1  = symaddr(g_ff1);
    float* pff3  = symaddr(g_ff3);
    float* pproc = symaddr(g_proc);
    float* pq    = symaddr(g_q);
    float* pkv   = symaddr(g_kv);
    float* pdec  = symaddr(g_dec);
    float* py    = symaddr(g_y);
    float* pyn   = symaddr(g_yn);
    float* pu1   = symaddr(g_u1);
    float* pu3   = symaddr(g_u3);

    auto gemm = [&](const float* A, const float* W, const float* bias,
                    const float* addend, float* C, int M, int N, int Kd) {
        dim3 grid((N + BN - 1)/BN, (M + BM - 1)/BM);
        gemm_kernel<<<grid, 256>>>(A, W, bias, addend, C, M, N, Kd);
    };

    // --- cascade: sort ---
    rank_kernel<<<BB, KK>>>(cw);
    scatter_kernel<<<BB*KK, 256>>>(chunk_repr);

    const int MC = BB*KK;          // 256
    for (int l = 0; l < LL; l++) {
        rms_kernel<<<MC, 256>>>(px, casc_norm1 + l*HH, ph);
        gemm(ph, casc_qkv + (size_t)l*3*HH*HH, nullptr, nullptr, pqkv, MC, 3*HH, HH);
        casc_attn_kernel<<<BB*NHH, KK>>>();
        gemm(pattn, casc_o + (size_t)l*HH*HH, nullptr, px, px, MC, HH, HH);
        rms_kernel<<<MC, 256>>>(px, casc_norm2 + l*HH, ph);
        gemm(ph, casc_w1 + (size_t)l*FFD*HH, nullptr, nullptr, pff1, MC, FFD, HH);
        gemm(ph, casc_w3 + (size_t)l*FFD*HH, nullptr, nullptr, pff3, MC, FFD, HH);
        {
            int n = MC*FFD;
            silu_mul_kernel<<<(n + 255)/256, 256>>>(pff1, pff3, n);
        }
        gemm(pff1, casc_w2 + (size_t)l*HH*FFD, nullptr, px, px, MC, HH, FFD);
    }
    gather_kernel<<<BB*KK, 256>>>();

    // --- decoder ---
    const int MT = BB*SS;          // 8192
    gemm(token, dec_in_w, dec_in_b, nullptr, pq, MT, HH, HH);
    gemm(pproc, dec_in_w + (size_t)HH*HH, dec_in_b + HH, nullptr, pkv, MC, 2*HH, HH);
    dec_attn_kernel<<<dim3(NHH, BB), 256>>>();
    gemm(pdec, dec_out_w, dec_out_b, token, pyn, MT, HH, HH);   // pyn = token + dec@Wo + b
    rms_kernel<<<MT, 256>>>(pyn, dec_norm_w, py);                // y
    rms_kernel<<<MT, 256>>>(py, dec_ffn_nw, pyn);                // rms(y)
    gemm(pyn, dec_w1, nullptr, nullptr, pu1, MT, FFD, HH);
    gemm(pyn, dec_w3, nullptr, nullptr, pu3, MT, FFD, HH);
    {
        int n = MT*FFD;
        silu_mul_kernel<<<(n + 255)/256, 256>>>(pu1, pu3, n);
    }
    gemm(pu1, dec_w2, nullptr, py, out, MT, HH, FFD);
}

// round 2
// speedup vs baseline: 1.6167x; 1.6167x over previous
#include <cuda_runtime.h>
#include <cuda_bf16.h>
#include <math.h>
#include <mma.h>

using namespace nvcuda;

#define BB 4
#define SS 2048
#define HH 1024
#define KK 64
#define NHH 16
#define DH 64
#define LL 2
#define FFD 2730
#define FFP 2736          // FFD padded to multiple of 16 floats
#define EPSV 1e-6f

// ---------------- scratch (device globals; no allocation) ----------------
__device__ float g_x[BB*KK*HH];
__device__ float g_h[BB*KK*HH];
__device__ float g_qkv[BB*KK*3*HH];
__device__ float g_attn[BB*KK*HH];
__device__ float g_ff1[BB*KK*FFP];
__device__ float g_ff3[BB*KK*FFP];
__device__ int   g_rank[BB*KK];
__device__ float g_proc[BB*KK*HH];
__device__ float g_q[BB*SS*HH];
__device__ float g_kv[BB*KK*2*HH];
__device__ float g_dec[BB*SS*HH];
__device__ float g_y[BB*SS*HH];
__device__ float g_yn[BB*SS*HH];
__device__ float g_u1[BB*SS*FFP];
__device__ float g_u3[BB*SS*FFP];
__device__ float g_w2pad[HH*FFP];    // padded w2 weights (reused sequentially)

// ---------------- rank / scatter / gather ----------------
__global__ void rank_kernel(const float* __restrict__ cw) {
    int b = blockIdx.x;
    int k = threadIdx.x;
    float wk = cw[b*KK + k];
    int r = 0;
    for (int j = 0; j < KK; j++) {
        float wj = cw[b*KK + j];
        if (wj > wk || (wj == wk && j < k)) r++;
    }
    g_rank[b*KK + k] = r;
}

__global__ void scatter_kernel(const float* __restrict__ src) {
    int row = blockIdx.x;           // b*KK + k
    int b = row / KK;
    int r = g_rank[row];
    const float* s = src + (size_t)row * HH;
    float* d = g_x + ((size_t)(b*KK + r)) * HH;
    for (int i = threadIdx.x; i < HH; i += blockDim.x) d[i] = s[i];
}

__global__ void gather_kernel() {
    int row = blockIdx.x;
    int b = row / KK;
    int r = g_rank[row];
    const float* s = g_x + ((size_t)(b*KK + r)) * HH;
    float* d = g_proc + (size_t)row * HH;
    for (int i = threadIdx.x; i < HH; i += blockDim.x) d[i] = s[i];
}

// ---------------- pad-copy weights [HH][FFD] -> [HH][FFP] (zero pad) -------
__global__ void padw_kernel(const float* __restrict__ src, float* __restrict__ dst) {
    int row = blockIdx.x;
    for (int i = threadIdx.x; i < FFP; i += blockDim.x)
        dst[(size_t)row*FFP + i] = (i < FFD) ? src[(size_t)row*FFD + i] : 0.f;
}

// ---------------- rmsnorm ----------------
__global__ void rms_kernel(const float* __restrict__ in, const float* __restrict__ w,
                           float* __restrict__ out) {
    __shared__ float red[256];
    int row = blockIdx.x;
    const float* x = in + (size_t)row * HH;
    float* o = out + (size_t)row * HH;
    int t = threadIdx.x;
    float v[4];
    float ss = 0.f;
#pragma unroll
    for (int i = 0; i < 4; i++) { v[i] = x[t + i*256]; ss += v[i]*v[i]; }
    red[t] = ss;
    __syncthreads();
    for (int ofs = 128; ofs > 0; ofs >>= 1) {
        if (t < ofs) red[t] += red[t + ofs];
        __syncthreads();
    }
    float inv = rsqrtf(red[0] * (1.0f/HH) + EPSV);
#pragma unroll
    for (int i = 0; i < 4; i++) {
        int c = t + i*256;
        o[c] = v[i] * inv * w[c];
    }
}

// ---------------- cp.async helper ----------------
__device__ __forceinline__ void cp_async16(float* smem_dst, const float* gsrc, bool pred) {
    unsigned d = (unsigned)__cvta_generic_to_shared(smem_dst);
    int p = pred ? 1 : 0;
    asm volatile(
        "{ .reg .pred p;\n"
        "  setp.ne.b32 p, %2, 0;\n"
        "  @p  cp.async.cg.shared.global [%0], [%1], 16;\n"
        "  @!p cp.async.cg.shared.global [%0], [%1], 16, 0;\n}"
        :: "r"(d), "l"(gsrc), "r"(p));
}

// ---------------- tf32 tensor-core GEMM ----------------
// C[M,N] = op(A)[M,Kd] @ W[N,Kd]^T (+bias[n]) (+addend)
// op(A) = A when A2==null, else silu(A)*A2 (GLU fusion).
// padTo >= N: columns [N, padTo) of C written as zeros.
#define LDS 36
#define TILEF (128*LDS)   // floats per tile buffer

__device__ __forceinline__ void load_tile(
    float* As, float* Bs,
    const float* __restrict__ A, const float* __restrict__ A2, int lda,
    const float* __restrict__ W, int ldw,
    int bm, int bn, int k0, int Kd, int N, int tid)
{
    if (A2 == nullptr) {
#pragma unroll
        for (int ch = 0; ch < 4; ch++) {
            int c = tid + ch*256;
            int row = c >> 3, kc = (c & 7) * 4;
            bool p = (k0 + kc) < Kd;
            const float* src = A + (size_t)(bm + row)*lda + k0 + kc;
            cp_async16(As + row*LDS + kc, p ? src : A, p);
        }
    } else {
#pragma unroll
        for (int ch = 0; ch < 4; ch++) {
            int c = tid + ch*256;
            int row = c >> 3, kc = (c & 7) * 4;
            float4 v = make_float4(0.f, 0.f, 0.f, 0.f);
            if ((k0 + kc) < Kd) {
                const float4 u = *(const float4*)(A  + (size_t)(bm + row)*lda + k0 + kc);
                const float4 g = *(const float4*)(A2 + (size_t)(bm + row)*lda + k0 + kc);
                v.x = u.x / (1.f + __expf(-u.x)) * g.x;
                v.y = u.y / (1.f + __expf(-u.y)) * g.y;
                v.z = u.z / (1.f + __expf(-u.z)) * g.z;
                v.w = u.w / (1.f + __expf(-u.w)) * g.w;
            }
            *(float4*)(As + row*LDS + kc) = v;
        }
    }
#pragma unroll
    for (int ch = 0; ch < 4; ch++) {
        int c = tid + ch*256;
        int row = c >> 3, kc = (c & 7) * 4;
        bool p = ((bn + row) < N) && ((k0 + kc) < Kd);
        const float* src = W + (size_t)(bn + row)*ldw + k0 + kc;
        cp_async16(Bs + row*LDS + kc, p ? src : W, p);
    }
}

__global__ __launch_bounds__(256) void tgemm(
    const float* __restrict__ A, const float* __restrict__ A2, int lda,
    const float* __restrict__ W, int ldw,
    const float* __restrict__ bias, const float* __restrict__ addend, int ldad,
    float* __restrict__ C, int ldc, int M, int N, int Kd, int padTo)
{
    extern __shared__ float sm[];
    float* As = sm;                 // 2 * TILEF
    float* Bs = sm + 2*TILEF;       // 2 * TILEF
    int tid = threadIdx.x;
    int bm = blockIdx.y * 128, bn = blockIdx.x * 128;
    int wid = tid >> 5, wm = wid >> 2, wn = wid & 3;

    wmma::fragment<wmma::accumulator, 16, 16, 8, float> acc[4][2];
#pragma unroll
    for (int i = 0; i < 4; i++)
#pragma unroll
        for (int j = 0; j < 2; j++) wmma::fill_fragment(acc[i][j], 0.f);

    int T = (Kd + 31) / 32;
    load_tile(As, Bs, A, A2, lda, W, ldw, bm, bn, 0, Kd, N, tid);
    asm volatile("cp.async.commit_group;\n" ::: "memory");

    for (int t = 0; t < T; t++) {
        if (t + 1 < T) {
            int nb = (t + 1) & 1;
            load_tile(As + nb*TILEF, Bs + nb*TILEF, A, A2, lda, W, ldw,
                      bm, bn, (t + 1)*32, Kd, N, tid);
            asm volatile("cp.async.commit_group;\n" ::: "memory");
            asm volatile("cp.async.wait_group 1;\n" ::: "memory");
        } else {
            asm volatile("cp.async.wait_group 0;\n" ::: "memory");
        }
        __syncthreads();
        float* as = As + (t & 1)*TILEF;
        float* bs = Bs + (t & 1)*TILEF;
#pragma unroll
        for (int kk = 0; kk < 32; kk += 8) {
            wmma::fragment<wmma::matrix_a, 16, 16, 8, wmma::precision::tf32, wmma::row_major> af[4];
            wmma::fragment<wmma::matrix_b, 16, 16, 8, wmma::precision::tf32, wmma::col_major> bf[2];
#pragma unroll
            for (int i = 0; i < 4; i++) {
                wmma::load_matrix_sync(af[i], as + (wm*64 + i*16)*LDS + kk, LDS);
#pragma unroll
                for (int q = 0; q < af[i].num_elements; q++)
                    af[i].x[q] = wmma::__float_to_tf32(af[i].x[q]);
            }
#pragma unroll
            for (int j = 0; j < 2; j++) {
                wmma::load_matrix_sync(bf[j], bs + (wn*32 + j*16)*LDS + kk, LDS);
#pragma unroll
                for (int q = 0; q < bf[j].num_elements; q++)
                    bf[j].x[q] = wmma::__float_to_tf32(bf[j].x[q]);
            }
#pragma unroll
            for (int i = 0; i < 4; i++)
#pragma unroll
                for (int j = 0; j < 2; j++)
                    wmma::mma_sync(acc[i][j], af[i], bf[j], acc[i][j]);
        }
        __syncthreads();
    }

    // epilogue: stage to smem, then bounds-checked write with bias/addend
    float* Cs = sm;   // 128*132 floats, fits in 2*TILEF region
#pragma unroll
    for (int i = 0; i < 4; i++)
#pragma unroll
        for (int j = 0; j < 2; j++)
            wmma::store_matrix_sync(Cs + (wm*64 + i*16)*132 + wn*32 + j*16,
                                    acc[i][j], 132, wmma::mem_row_major);
    __syncthreads();
#pragma unroll 8
    for (int e = 0; e < 64; e++) {
        int idx = tid + e*256;
        int row = idx >> 7, col = idx & 127;
        int gm = bm + row, gn = bn + col;
        if (gn < N) {
            float v = Cs[row*132 + col];
            if (bias)   v += bias[gn];
            if (addend) v += addend[(size_t)gm*ldad + gn];
            C[(size_t)gm*ldc + gn] = v;
        } else if (gn < padTo) {
            C[(size_t)gm*ldc + gn] = 0.f;
        }
    }
}

// ---------------- cascade self-attn (causal, K=64, d=64) ----------------
__global__ void casc_attn_kernel() {
    __shared__ float ks[KK][DH+1];
    __shared__ float vs[KK][DH+1];
    int bh = blockIdx.x;
    int b = bh / NHH, nh = bh % NHH;
    int t = threadIdx.x;
    const float* base = g_qkv + ((size_t)(b*KK + t)) * (3*HH);
#pragma unroll
    for (int dd = 0; dd < DH; dd++) {
        ks[t][dd] = base[HH   + nh*DH + dd];
        vs[t][dd] = base[2*HH + nh*DH + dd];
    }
    __syncthreads();
    float q[DH];
#pragma unroll
    for (int dd = 0; dd < DH; dd++) q[dd] = base[nh*DH + dd];

    const float scale = 0.125f;
    float sc[KK];
    float mx = -1e30f;
    for (int j = 0; j <= t; j++) {
        float s = 0.f;
#pragma unroll
        for (int dd = 0; dd < DH; dd++) s += q[dd] * ks[j][dd];
        s *= scale;
        sc[j] = s;
        mx = fmaxf(mx, s);
    }
    float sum = 0.f;
    for (int j = 0; j <= t; j++) {
        float e = expf(sc[j] - mx);
        sc[j] = e;
        sum += e;
    }
    float inv = 1.0f / sum;
    float* o = g_attn + ((size_t)(b*KK + t)) * HH + nh*DH;
#pragma unroll 4
    for (int dd = 0; dd < DH; dd++) {
        float acc = 0.f;
        for (int j = 0; j <= t; j++) acc += sc[j] * vs[j][dd];
        o[dd] = acc * inv;
    }
}

// ---------------- decoder cross-attn ----------------
__global__ void dec_attn_kernel() {
    __shared__ float ks[KK][DH+1];
    __shared__ float vs[KK][DH+1];
    __shared__ float qs[8][DH];
    __shared__ float probs[8][KK];
    int nh = blockIdx.x, b = blockIdx.y;
    int tid = threadIdx.x;
    for (int i = tid; i < KK*DH; i += 256) {
        int c = i / DH, dd = i % DH;
        const float* kvrow = g_kv + ((size_t)(b*KK + c)) * (2*HH);
        ks[c][dd] = kvrow[nh*DH + dd];
        vs[c][dd] = kvrow[HH + nh*DH + dd];
    }
    __syncthreads();
    int w = tid >> 5, lane = tid & 31;
    const float scale = 0.125f;
    for (int s = w; s < SS; s += 8) {
        int nallow = min(KK, s/32 + 2);
        const float* qrow = g_q + ((size_t)b*SS + s) * HH + nh*DH;
        qs[w][lane]      = qrow[lane];
        qs[w][lane + 32] = qrow[lane + 32];
        __syncwarp();
        float s0 = -INFINITY, s1 = -INFINITY;
        if (lane < nallow) {
            float acc = 0.f;
#pragma unroll
            for (int dd = 0; dd < DH; dd++) acc += qs[w][dd] * ks[lane][dd];
            s0 = acc * scale;
        }
        if (lane + 32 < nallow) {
            float acc = 0.f;
#pragma unroll
            for (int dd = 0; dd < DH; dd++) acc += qs[w][dd] * ks[lane + 32][dd];
            s1 = acc * scale;
        }
        float mx = fmaxf(s0, s1);
#pragma unroll
        for (int ofs = 16; ofs > 0; ofs >>= 1)
            mx = fmaxf(mx, __shfl_xor_sync(0xffffffffu, mx, ofs));
        float e0 = expf(s0 - mx);
        float e1 = expf(s1 - mx);
        float sum = e0 + e1;
#pragma unroll
        for (int ofs = 16; ofs > 0; ofs >>= 1)
            sum += __shfl_xor_sync(0xffffffffu, sum, ofs);
        float inv = 1.0f / sum;
        probs[w][lane]      = e0 * inv;
        probs[w][lane + 32] = e1 * inv;
        __syncwarp();
        float* orow = g_dec + ((size_t)b*SS + s) * HH + nh*DH;
#pragma unroll
        for (int half = 0; half < 2; half++) {
            int dd = lane + half*32;
            float acc = 0.f;
            for (int j = 0; j < nallow; j++) acc += probs[w][j] * vs[j][dd];
            orow[dd] = acc;
        }
        __syncwarp();
    }
}

// ---------------- host ----------------
static float* symaddr(const void* sym) {
    void* p = nullptr;
    cudaGetSymbolAddress(&p, sym);
    return (float*)p;
}

#define SMEM_BYTES (4*TILEF*4)

extern "C" void kernel_launch(void* const* d_in, const int* in_sizes, int n_in,
                              void* d_out, int out_size) {
    const float* token       = (const float*)d_in[0];
    const float* chunk_repr  = (const float*)d_in[1];
    const float* cw          = (const float*)d_in[2];
    const float* casc_norm1  = (const float*)d_in[3];
    const float* casc_qkv    = (const float*)d_in[4];
    const float* casc_o      = (const float*)d_in[5];
    const float* casc_norm2  = (const float*)d_in[6];
    const float* casc_w1     = (const float*)d_in[7];
    const float* casc_w2     = (const float*)d_in[8];
    const float* casc_w3     = (const float*)d_in[9];
    const float* dec_in_w    = (const float*)d_in[10];
    const float* dec_in_b    = (const float*)d_in[11];
    const float* dec_out_w   = (const float*)d_in[12];
    const float* dec_out_b   = (const float*)d_in[13];
    const float* dec_norm_w  = (const float*)d_in[14];
    const float* dec_ffn_nw  = (const float*)d_in[15];
    const float* dec_w1      = (const float*)d_in[16];
    const float* dec_w2      = (const float*)d_in[17];
    const float* dec_w3      = (const float*)d_in[18];
    float* out = (float*)d_out;

    float* px    = symaddr(g_x);
    float* ph    = symaddr(g_h);
    float* pqkv  = symaddr(g_qkv);
    float* pattn = symaddr(g_attn);
    float* pff1  = symaddr(g_ff1);
    float* pff3  = symaddr(g_ff3);
    float* pproc = symaddr(g_proc);
    float* pq    = symaddr(g_q);
    float* pkv   = symaddr(g_kv);
    float* pdec  = symaddr(g_dec);
    float* py    = symaddr(g_y);
    float* pyn   = symaddr(g_yn);
    float* pu1   = symaddr(g_u1);
    float* pu3   = symaddr(g_u3);
    float* pw2p  = symaddr(g_w2pad);

    cudaFuncSetAttribute(tgemm, cudaFuncAttributeMaxDynamicSharedMemorySize, SMEM_BYTES);

    auto gemm = [&](const float* A, const float* A2, int lda,
                    const float* W, int ldw,
                    const float* bias, const float* addend, int ldad,
                    float* C, int ldc, int M, int N, int Kd, int padTo) {
        dim3 grid((padTo + 127)/128, M/128);
        tgemm<<<grid, 256, SMEM_BYTES>>>(A, A2, lda, W, ldw, bias, addend, ldad,
                                         C, ldc, M, N, Kd, padTo);
    };

    // --- cascade: sort ---
    rank_kernel<<<BB, KK>>>(cw);
    scatter_kernel<<<BB*KK, 256>>>(chunk_repr);

    const int MC = BB*KK;          // 256
    for (int l = 0; l < LL; l++) {
        rms_kernel<<<MC, 256>>>(px, casc_norm1 + l*HH, ph);
        gemm(ph, nullptr, HH, casc_qkv + (size_t)l*3*HH*HH, HH,
             nullptr, nullptr, 0, pqkv, 3*HH, MC, 3*HH, HH, 3*HH);
        casc_attn_kernel<<<BB*NHH, KK>>>();
        gemm(pattn, nullptr, HH, casc_o + (size_t)l*HH*HH, HH,
             nullptr, px, HH, px, HH, MC, HH, HH, HH);
        rms_kernel<<<MC, 256>>>(px, casc_norm2 + l*HH, ph);
        gemm(ph, nullptr, HH, casc_w1 + (size_t)l*FFD*HH, HH,
             nullptr, nullptr, 0, pff1, FFP, MC, FFD, HH, FFP);
        gemm(ph, nullptr, HH, casc_w3 + (size_t)l*FFD*HH, HH,
             nullptr, nullptr, 0, pff3, FFP, MC, FFD, HH, FFP);
        padw_kernel<<<HH, 256>>>(casc_w2 + (size_t)l*HH*FFD, pw2p);
        gemm(pff1, pff3, FFP, pw2p, FFP,
             nullptr, px, HH, px, HH, MC, HH, FFP, HH);
    }
    gather_kernel<<<BB*KK, 256>>>();

    // --- decoder ---
    const int MT = BB*SS;          // 8192
    gemm(token, nullptr, HH, dec_in_w, HH,
         dec_in_b, nullptr, 0, pq, HH, MT, HH, HH, HH);
    gemm(pproc, nullptr, HH, dec_in_w + (size_t)HH*HH, HH,
         dec_in_b + HH, nullptr, 0, pkv, 2*HH, MC, 2*HH, HH, 2*HH);
    dec_attn_kernel<<<dim3(NHH, BB), 256>>>();
    gemm(pdec, nullptr, HH, dec_out_w, HH,
         dec_out_b, token, HH, pyn, HH, MT, HH, HH, HH);
    rms_kernel<<<MT, 256>>>(pyn, dec_norm_w, py);    // y
    rms_kernel<<<MT, 256>>>(py, dec_ffn_nw, pyn);    // rms(y)
    gemm(pyn, nullptr, HH, dec_w1, HH,
         nullptr, nullptr, 0, pu1, FFP, MT, FFD, HH, FFP);
    gemm(pyn, nullptr, HH, dec_w3, HH,
         nullptr, nullptr, 0, pu3, FFP, MT, FFD, HH, FFP);
    padw_kernel<<<HH, 256>>>(dec_w2, pw2p);
    gemm(pu1, pu3, FFP, pw2p, FFP,
         nullptr, py, HH, out, HH, MT, HH, FFP, HH);
}

// round 3
// speedup vs baseline: 1.8479x; 1.1430x over previous
#include <cuda_runtime.h>
#include <cuda_bf16.h>
#include <math.h>
#include <mma.h>

using namespace nvcuda;

#define BB 4
#define SS 2048
#define HH 1024
#define KK 64
#define NHH 16
#define DH 64
#define LL 2
#define FFD 2730
#define FFP 2736          // FFD padded to multiple of 16 floats
#define EPSV 1e-6f

// ---------------- scratch (device globals; no allocation) ----------------
__device__ float g_x[BB*KK*HH];
__device__ float g_h[BB*KK*HH];
__device__ float g_qkv[BB*KK*3*HH];
__device__ float g_attn[BB*KK*HH];
__device__ float g_ff1[BB*KK*FFP];
__device__ float g_ff3[BB*KK*FFP];
__device__ int   g_rank[BB*KK];
__device__ float g_proc[BB*KK*HH];
__device__ float g_q[BB*SS*HH];
__device__ float g_kv[BB*KK*2*HH];
__device__ float g_dec[BB*SS*HH];
__device__ float g_y[BB*SS*HH];
__device__ float g_yn[BB*SS*HH];
__device__ float g_u1[BB*SS*FFP];
__device__ float g_u3[BB*SS*FFP];
__device__ float g_w2pad[HH*FFP];    // padded w2 weights (reused sequentially)
__device__ float g_tok[BB*SS*HH];    // tf32-rounded token states

// tf32 round-to-nearest (result keeps fp32 bit layout, low mantissa zeroed)
__device__ __forceinline__ float to_tf32(float x) {
    float r;
    asm("cvt.rna.tf32.f32 %0, %1;" : "=f"(r) : "f"(x));
    return r;
}

// ---------------- rank / scatter / gather ----------------
__global__ void rank_kernel(const float* __restrict__ cw) {
    int b = blockIdx.x;
    int k = threadIdx.x;
    float wk = cw[b*KK + k];
    int r = 0;
    for (int j = 0; j < KK; j++) {
        float wj = cw[b*KK + j];
        if (wj > wk || (wj == wk && j < k)) r++;
    }
    g_rank[b*KK + k] = r;
}

__global__ void scatter_kernel(const float* __restrict__ src) {
    int row = blockIdx.x;           // b*KK + k
    int b = row / KK;
    int r = g_rank[row];
    const float* s = src + (size_t)row * HH;
    float* d = g_x + ((size_t)(b*KK + r)) * HH;
    for (int i = threadIdx.x; i < HH; i += blockDim.x) d[i] = s[i];
}

// gather output feeds a GEMM A-operand -> round to tf32 here
__global__ void gather_kernel() {
    int row = blockIdx.x;
    int b = row / KK;
    int r = g_rank[row];
    const float* s = g_x + ((size_t)(b*KK + r)) * HH;
    float* d = g_proc + (size_t)row * HH;
    for (int i = threadIdx.x; i < HH; i += blockDim.x) d[i] = to_tf32(s[i]);
}

// round-copy (token -> g_tok)
__global__ void roundcopy_kernel(const float* __restrict__ src, float* __restrict__ dst, int n) {
    int i = blockIdx.x * blockDim.x + threadIdx.x;
    if (i < n) dst[i] = to_tf32(src[i]);
}

// ---------------- pad-copy weights [HH][FFD] -> [HH][FFP] (zero pad) -------
__global__ void padw_kernel(const float* __restrict__ src, float* __restrict__ dst) {
    int row = blockIdx.x;
    for (int i = threadIdx.x; i < FFP; i += blockDim.x)
        dst[(size_t)row*FFP + i] = (i < FFD) ? src[(size_t)row*FFD + i] : 0.f;
}

// ---------------- rmsnorm (output rounded to tf32; feeds GEMM A) ----------
__global__ void rms_kernel(const float* __restrict__ in, const float* __restrict__ w,
                           float* __restrict__ out) {
    __shared__ float red[256];
    int row = blockIdx.x;
    const float* x = in + (size_t)row * HH;
    float* o = out + (size_t)row * HH;
    int t = threadIdx.x;
    float v[4];
    float ss = 0.f;
#pragma unroll
    for (int i = 0; i < 4; i++) { v[i] = x[t + i*256]; ss += v[i]*v[i]; }
    red[t] = ss;
    __syncthreads();
    for (int ofs = 128; ofs > 0; ofs >>= 1) {
        if (t < ofs) red[t] += red[t + ofs];
        __syncthreads();
    }
    float inv = rsqrtf(red[0] * (1.0f/HH) + EPSV);
#pragma unroll
    for (int i = 0; i < 4; i++) {
        int c = t + i*256;
        o[c] = to_tf32(v[i] * inv * w[c]);
    }
}

// ---------------- cp.async helper ----------------
__device__ __forceinline__ void cp_async16(float* smem_dst, const float* gsrc, bool pred) {
    unsigned d = (unsigned)__cvta_generic_to_shared(smem_dst);
    int p = pred ? 1 : 0;
    asm volatile(
        "{ .reg .pred p;\n"
        "  setp.ne.b32 p, %2, 0;\n"
        "  @p  cp.async.cg.shared.global [%0], [%1], 16;\n"
        "  @!p cp.async.cg.shared.global [%0], [%1], 16, 0;\n}"
        :: "r"(d), "l"(gsrc), "r"(p));
}

// ---------------- tf32 tensor-core GEMM (templated on M-tile) -------------
// C[M,N] = op(A)[M,Kd] @ W[N,Kd]^T (+bias[n]) (+addend)
// op(A) = A (must be pre-rounded to tf32), or silu(A)*A2 (rounded in loader).
// AFRAG: 16x16 fragments per warp along M; BM = 32*AFRAG. BN = 128, 8 warps (2x4).
#define LDS 36

template<int AFRAG>
__device__ __forceinline__ void load_tile(
    float* As, float* Bs,
    const float* __restrict__ A, const float* __restrict__ A2, int lda,
    const float* __restrict__ W, int ldw,
    int bm, int bn, int k0, int Kd, int N, int tid)
{
    if (A2 == nullptr) {
#pragma unroll
        for (int ch = 0; ch < AFRAG; ch++) {
            int c = tid + ch*256;
            int row = c >> 3, kc = (c & 7) * 4;
            bool p = (k0 + kc) < Kd;
            const float* src = A + (size_t)(bm + row)*lda + k0 + kc;
            cp_async16(As + row*LDS + kc, p ? src : A, p);
        }
    } else {
#pragma unroll
        for (int ch = 0; ch < AFRAG; ch++) {
            int c = tid + ch*256;
            int row = c >> 3, kc = (c & 7) * 4;
            float4 v = make_float4(0.f, 0.f, 0.f, 0.f);
            if ((k0 + kc) < Kd) {
                const float4 u = *(const float4*)(A  + (size_t)(bm + row)*lda + k0 + kc);
                const float4 g = *(const float4*)(A2 + (size_t)(bm + row)*lda + k0 + kc);
                v.x = to_tf32(u.x / (1.f + __expf(-u.x)) * g.x);
                v.y = to_tf32(u.y / (1.f + __expf(-u.y)) * g.y);
                v.z = to_tf32(u.z / (1.f + __expf(-u.z)) * g.z);
                v.w = to_tf32(u.w / (1.f + __expf(-u.w)) * g.w);
            }
            *(float4*)(As + row*LDS + kc) = v;
        }
    }
#pragma unroll
    for (int ch = 0; ch < 4; ch++) {
        int c = tid + ch*256;
        int row = c >> 3, kc = (c & 7) * 4;
        bool p = ((bn + row) < N) && ((k0 + kc) < Kd);
        const float* src = W + (size_t)(bn + row)*ldw + k0 + kc;
        cp_async16(Bs + row*LDS + kc, p ? src : W, p);
    }
}

template<int AFRAG>
__global__ __launch_bounds__(256, 2) void tgemm(
    const float* __restrict__ A, const float* __restrict__ A2, int lda,
    const float* __restrict__ W, int ldw,
    const float* __restrict__ bias, const float* __restrict__ addend, int ldad,
    float* __restrict__ C, int ldc, int M, int N, int Kd, int padTo)
{
    constexpr int BMT = 32 * AFRAG;
    constexpr int ATILE = BMT * LDS;
    constexpr int BTILE = 128 * LDS;
    extern __shared__ float sm[];
    float* As = sm;                   // 2 stages * ATILE
    float* Bs = sm + 2*ATILE;         // 2 stages * BTILE
    int tid = threadIdx.x;
    int bm = blockIdx.y * BMT, bn = blockIdx.x * 128;
    int wid = tid >> 5, wm = wid >> 2, wn = wid & 3;

    wmma::fragment<wmma::accumulator, 16, 16, 8, float> acc[AFRAG][2];
#pragma unroll
    for (int i = 0; i < AFRAG; i++)
#pragma unroll
        for (int j = 0; j < 2; j++) wmma::fill_fragment(acc[i][j], 0.f);

    int T = (Kd + 31) / 32;
    load_tile<AFRAG>(As, Bs, A, A2, lda, W, ldw, bm, bn, 0, Kd, N, tid);
    asm volatile("cp.async.commit_group;\n" ::: "memory");

    for (int t = 0; t < T; t++) {
        if (t + 1 < T) {
            int nb = (t + 1) & 1;
            load_tile<AFRAG>(As + nb*ATILE, Bs + nb*BTILE, A, A2, lda, W, ldw,
                             bm, bn, (t + 1)*32, Kd, N, tid);
            asm volatile("cp.async.commit_group;\n" ::: "memory");
            asm volatile("cp.async.wait_group 1;\n" ::: "memory");
        } else {
            asm volatile("cp.async.wait_group 0;\n" ::: "memory");
        }
        __syncthreads();
        float* as = As + (t & 1)*ATILE;
        float* bs = Bs + (t & 1)*BTILE;
#pragma unroll
        for (int kk = 0; kk < 32; kk += 8) {
            wmma::fragment<wmma::matrix_a, 16, 16, 8, wmma::precision::tf32, wmma::row_major> af[AFRAG];
            wmma::fragment<wmma::matrix_b, 16, 16, 8, wmma::precision::tf32, wmma::col_major> bf[2];
#pragma unroll
            for (int i = 0; i < AFRAG; i++)   // A pre-rounded: NO cvt here
                wmma::load_matrix_sync(af[i], as + (wm*(16*AFRAG) + i*16)*LDS + kk, LDS);
#pragma unroll
            for (int j = 0; j < 2; j++) {
                wmma::load_matrix_sync(bf[j], bs + (wn*32 + j*16)*LDS + kk, LDS);
#pragma unroll
                for (int q = 0; q < bf[j].num_elements; q++)
                    bf[j].x[q] = to_tf32(bf[j].x[q]);
            }
#pragma unroll
            for (int i = 0; i < AFRAG; i++)
#pragma unroll
                for (int j = 0; j < 2; j++)
                    wmma::mma_sync(acc[i][j], af[i], bf[j], acc[i][j]);
        }
        __syncthreads();
    }

    // epilogue: stage to smem, then bounds-checked write with bias/addend
    float* Cs = sm;   // BMT*132 floats fits (BMT*132 <= 2*ATILE + ... always)
#pragma unroll
    for (int i = 0; i < AFRAG; i++)
#pragma unroll
        for (int j = 0; j < 2; j++)
            wmma::store_matrix_sync(Cs + (wm*(16*AFRAG) + i*16)*132 + wn*32 + j*16,
                                    acc[i][j], 132, wmma::mem_row_major);
    __syncthreads();
#pragma unroll 8
    for (int e = 0; e < BMT/2; e++) {
        int idx = tid + e*256;
        int row = idx >> 7, col = idx & 127;
        int gm = bm + row, gn = bn + col;
        if (gn < N) {
            float v = Cs[row*132 + col];
            if (bias)   v += bias[gn];
            if (addend) v += addend[(size_t)gm*ldad + gn];
            C[(size_t)gm*ldc + gn] = v;
        } else if (gn < padTo) {
            C[(size_t)gm*ldc + gn] = 0.f;
        }
    }
}

// ---------------- cascade self-attn (causal, K=64, d=64) ----------------
__global__ void casc_attn_kernel() {
    __shared__ float ks[KK][DH+1];
    __shared__ float vs[KK][DH+1];
    int bh = blockIdx.x;
    int b = bh / NHH, nh = bh % NHH;
    int t = threadIdx.x;
    const float* base = g_qkv + ((size_t)(b*KK + t)) * (3*HH);
#pragma unroll
    for (int dd = 0; dd < DH; dd++) {
        ks[t][dd] = base[HH   + nh*DH + dd];
        vs[t][dd] = base[2*HH + nh*DH + dd];
    }
    __syncthreads();
    float q[DH];
#pragma unroll
    for (int dd = 0; dd < DH; dd++) q[dd] = base[nh*DH + dd];

    const float scale = 0.125f;
    float sc[KK];
    float mx = -1e30f;
    for (int j = 0; j <= t; j++) {
        float s = 0.f;
#pragma unroll
        for (int dd = 0; dd < DH; dd++) s += q[dd] * ks[j][dd];
        s *= scale;
        sc[j] = s;
        mx = fmaxf(mx, s);
    }
    float sum = 0.f;
    for (int j = 0; j <= t; j++) {
        float e = expf(sc[j] - mx);
        sc[j] = e;
        sum += e;
    }
    float inv = 1.0f / sum;
    float* o = g_attn + ((size_t)(b*KK + t)) * HH + nh*DH;
#pragma unroll 4
    for (int dd = 0; dd < DH; dd++) {
        float acc = 0.f;
        for (int j = 0; j <= t; j++) acc += sc[j] * vs[j][dd];
        o[dd] = to_tf32(acc * inv);    // feeds o-proj GEMM A
    }
}

// ---------------- decoder cross-attn ----------------
__global__ void dec_attn_kernel() {
    __shared__ float ks[KK][DH+1];
    __shared__ float vs[KK][DH+1];
    __shared__ float qs[8][DH];
    __shared__ float probs[8][KK];
    int nh = blockIdx.x, b = blockIdx.y;
    int tid = threadIdx.x;
    for (int i = tid; i < KK*DH; i += 256) {
        int c = i / DH, dd = i % DH;
        const float* kvrow = g_kv + ((size_t)(b*KK + c)) * (2*HH);
        ks[c][dd] = kvrow[nh*DH + dd];
        vs[c][dd] = kvrow[HH + nh*DH + dd];
    }
    __syncthreads();
    int w = tid >> 5, lane = tid & 31;
    const float scale = 0.125f;
    for (int s = w; s < SS; s += 8) {
        int nallow = min(KK, s/32 + 2);
        const float* qrow = g_q + ((size_t)b*SS + s) * HH + nh*DH;
        qs[w][lane]      = qrow[lane];
        qs[w][lane + 32] = qrow[lane + 32];
        __syncwarp();
        float s0 = -INFINITY, s1 = -INFINITY;
        if (lane < nallow) {
            float acc = 0.f;
#pragma unroll
            for (int dd = 0; dd < DH; dd++) acc += qs[w][dd] * ks[lane][dd];
            s0 = acc * scale;
        }
        if (lane + 32 < nallow) {
            float acc = 0.f;
#pragma unroll
            for (int dd = 0; dd < DH; dd++) acc += qs[w][dd] * ks[lane + 32][dd];
            s1 = acc * scale;
        }
        float mx = fmaxf(s0, s1);
#pragma unroll
        for (int ofs = 16; ofs > 0; ofs >>= 1)
            mx = fmaxf(mx, __shfl_xor_sync(0xffffffffu, mx, ofs));
        float e0 = expf(s0 - mx);
        float e1 = expf(s1 - mx);
        float sum = e0 + e1;
#pragma unroll
        for (int ofs = 16; ofs > 0; ofs >>= 1)
            sum += __shfl_xor_sync(0xffffffffu, sum, ofs);
        float inv = 1.0f / sum;
        probs[w][lane]      = e0 * inv;
        probs[w][lane + 32] = e1 * inv;
        __syncwarp();
        float* orow = g_dec + ((size_t)b*SS + s) * HH + nh*DH;
#pragma unroll
        for (int half = 0; half < 2; half++) {
            int dd = lane + half*32;
            float acc = 0.f;
            for (int j = 0; j < nallow; j++) acc += probs[w][j] * vs[j][dd];
            orow[dd] = to_tf32(acc);   // feeds out-proj GEMM A
        }
        __syncwarp();
    }
}

// ---------------- host ----------------
static float* symaddr(const void* sym) {
    void* p = nullptr;
    cudaGetSymbolAddress(&p, sym);
    return (float*)p;
}

#define SMEM128 ((128 + 128) * LDS * 2 * 4)   // 73728
#define SMEM64  ((64  + 128) * LDS * 2 * 4)   // 55296

extern "C" void kernel_launch(void* const* d_in, const int* in_sizes, int n_in,
                              void* d_out, int out_size) {
    const float* token       = (const float*)d_in[0];
    const float* chunk_repr  = (const float*)d_in[1];
    const float* cw          = (const float*)d_in[2];
    const float* casc_norm1  = (const float*)d_in[3];
    const float* casc_qkv    = (const float*)d_in[4];
    const float* casc_o      = (const float*)d_in[5];
    const float* casc_norm2  = (const float*)d_in[6];
    const float* casc_w1     = (const float*)d_in[7];
    const float* casc_w2     = (const float*)d_in[8];
    const float* casc_w3     = (const float*)d_in[9];
    const float* dec_in_w    = (const float*)d_in[10];
    const float* dec_in_b    = (const float*)d_in[11];
    const float* dec_out_w   = (const float*)d_in[12];
    const float* dec_out_b   = (const float*)d_in[13];
    const float* dec_norm_w  = (const float*)d_in[14];
    const float* dec_ffn_nw  = (const float*)d_in[15];
    const float* dec_w1      = (const float*)d_in[16];
    const float* dec_w2      = (const float*)d_in[17];
    const float* dec_w3      = (const float*)d_in[18];
    float* out = (float*)d_out;

    float* px    = symaddr(g_x);
    float* ph    = symaddr(g_h);
    float* pqkv  = symaddr(g_qkv);
    float* pattn = symaddr(g_attn);
    float* pff1  = symaddr(g_ff1);
    float* pff3  = symaddr(g_ff3);
    float* pproc = symaddr(g_proc);
    float* pq    = symaddr(g_q);
    float* pkv   = symaddr(g_kv);
    float* pdec  = symaddr(g_dec);
    float* py    = symaddr(g_y);
    float* pyn   = symaddr(g_yn);
    float* pu1   = symaddr(g_u1);
    float* pu3   = symaddr(g_u3);
    float* pw2p  = symaddr(g_w2pad);
    float* ptok  = symaddr(g_tok);

    cudaFuncSetAttribute(tgemm<4>, cudaFuncAttributeMaxDynamicSharedMemorySize, SMEM128);
    cudaFuncSetAttribute(tgemm<2>, cudaFuncAttributeMaxDynamicSharedMemorySize, SMEM64);

    auto gemm128 = [&](const float* A, const float* A2, int lda,
                       const float* W, int ldw,
                       const float* bias, const float* addend, int ldad,
                       float* C, int ldc, int M, int N, int Kd, int padTo) {
        dim3 grid((padTo + 127)/128, M/128);
        tgemm<4><<<grid, 256, SMEM128>>>(A, A2, lda, W, ldw, bias, addend, ldad,
                                         C, ldc, M, N, Kd, padTo);
    };
    auto gemm64 = [&](const float* A, const float* A2, int lda,
                      const float* W, int ldw,
                      const float* bias, const float* addend, int ldad,
                      float* C, int ldc, int M, int N, int Kd, int padTo) {
        dim3 grid((padTo + 127)/128, M/64);
        tgemm<2><<<grid, 256, SMEM64>>>(A, A2, lda, W, ldw, bias, addend, ldad,
                                        C, ldc, M, N, Kd, padTo);
    };

    // --- cascade: sort ---
    rank_kernel<<<BB, KK>>>(cw);
    scatter_kernel<<<BB*KK, 256>>>(chunk_repr);

    const int MC = BB*KK;          // 256
    for (int l = 0; l < LL; l++) {
        rms_kernel<<<MC, 256>>>(px, casc_norm1 + l*HH, ph);
        gemm64(ph, nullptr, HH, casc_qkv + (size_t)l*3*HH*HH, HH,
               nullptr, nullptr, 0, pqkv, 3*HH, MC, 3*HH, HH, 3*HH);
        casc_attn_kernel<<<BB*NHH, KK>>>();
        gemm64(pattn, nullptr, HH, casc_o + (size_t)l*HH*HH, HH,
               nullptr, px, HH, px, HH, MC, HH, HH, HH);
        rms_kernel<<<MC, 256>>>(px, casc_norm2 + l*HH, ph);
        gemm64(ph, nullptr, HH, casc_w1 + (size_t)l*FFD*HH, HH,
               nullptr, nullptr, 0, pff1, FFP, MC, FFD, HH, FFP);
        gemm64(ph, nullptr, HH, casc_w3 + (size_t)l*FFD*HH, HH,
               nullptr, nullptr, 0, pff3, FFP, MC, FFD, HH, FFP);
        padw_kernel<<<HH, 256>>>(casc_w2 + (size_t)l*HH*FFD, pw2p);
        gemm64(pff1, pff3, FFP, pw2p, FFP,
               nullptr, px, HH, px, HH, MC, HH, FFP, HH);
    }
    gather_kernel<<<BB*KK, 256>>>();

    // --- decoder ---
    const int MT = BB*SS;          // 8192
    roundcopy_kernel<<<(MT*HH + 255)/256, 256>>>(token, ptok, MT*HH);
    gemm128(ptok, nullptr, HH, dec_in_w, HH,
            dec_in_b, nullptr, 0, pq, HH, MT, HH, HH, HH);
    gemm64(pproc, nullptr, HH, dec_in_w + (size_t)HH*HH, HH,
           dec_in_b + HH, nullptr, 0, pkv, 2*HH, MC, 2*HH, HH, 2*HH);
    dec_attn_kernel<<<dim3(NHH, BB), 256>>>();
    gemm128(pdec, nullptr, HH, dec_out_w, HH,
            dec_out_b, token, HH, pyn, HH, MT, HH, HH, HH);
    rms_kernel<<<MT, 256>>>(pyn, dec_norm_w, py);    // y (rounded; only feeds rms+addend, harmless? no:
                                                     // py is addend for final gemm -> fp32 use; rounding y
                                                     // would lose precision, so re-derive below)
    rms_kernel<<<MT, 256>>>(py, dec_ffn_nw, pyn);    // rms(y)
    gemm128(pyn, nullptr, HH, dec_w1, HH,
            nullptr, nullptr, 0, pu1, FFP, MT, FFD, HH, FFP);
    gemm128(pyn, nullptr, HH, dec_w3, HH,
            nullptr, nullptr, 0, pu3, FFP, MT, FFD, HH, FFP);
    padw_kernel<<<HH, 256>>>(dec_w2, pw2p);
    gemm128(pu1, pu3, FFP, pw2p, FFP,
            nullptr, py, HH, out, HH, MT, HH, FFP, HH);
}

// round 4
// speedup vs baseline: 1.8975x; 1.0268x over previous
#include <cuda_runtime.h>
#include <cuda_bf16.h>
#include <math.h>
#include <stdint.h>

#define BB 4
#define SS 2048
#define HH 1024
#define KK 64
#define NHH 16
#define DH 64
#define LL 2
#define FFD 2730
#define FFP 2736
#define EPSV 1e-6f

// ---------------- scratch ----------------
__device__ float g_x[BB*KK*HH];
__device__ float g_h[BB*KK*HH];
__device__ float g_qkv[BB*KK*3*HH];
__device__ float g_attn[BB*KK*HH];
__device__ float g_ff1[BB*KK*FFP];
__device__ float g_ff3[BB*KK*FFP];
__device__ int   g_rank[BB*KK];
__device__ float g_proc[BB*KK*HH];
__device__ float g_q[BB*SS*HH];
__device__ float g_kv[BB*KK*2*HH];
__device__ float g_dec[BB*SS*HH];
__device__ float g_y[BB*SS*HH];
__device__ float g_yn[BB*SS*HH];
__device__ float g_u1[BB*SS*FFP];
__device__ float g_u3[BB*SS*FFP];
__device__ float g_w2pad[HH*FFP];
__device__ float g_tok[BB*SS*HH];

__device__ __forceinline__ float to_tf32(float x) {
    float r;
    asm("cvt.rna.tf32.f32 %0, %1;" : "=f"(r) : "f"(x));
    return r;
}

// ---------------- small kernels ----------------
__global__ void rank_kernel(const float* __restrict__ cw) {
    int b = blockIdx.x, k = threadIdx.x;
    float wk = cw[b*KK + k];
    int r = 0;
    for (int j = 0; j < KK; j++) {
        float wj = cw[b*KK + j];
        if (wj > wk || (wj == wk && j < k)) r++;
    }
    g_rank[b*KK + k] = r;
}

__global__ void scatter_kernel(const float* __restrict__ src) {
    int row = blockIdx.x;
    int b = row / KK;
    int r = g_rank[row];
    const float* s = src + (size_t)row * HH;
    float* d = g_x + ((size_t)(b*KK + r)) * HH;
    for (int i = threadIdx.x; i < HH; i += blockDim.x) d[i] = s[i];
}

__global__ void gather_kernel() {
    int row = blockIdx.x;
    int b = row / KK;
    int r = g_rank[row];
    const float* s = g_x + ((size_t)(b*KK + r)) * HH;
    float* d = g_proc + (size_t)row * HH;
    for (int i = threadIdx.x; i < HH; i += blockDim.x) d[i] = to_tf32(s[i]);
}

__global__ void roundcopy_kernel(const float* __restrict__ src, float* __restrict__ dst, int n) {
    int i = blockIdx.x * blockDim.x + threadIdx.x;
    if (i < n) dst[i] = to_tf32(src[i]);
}

__global__ void padw_kernel(const float* __restrict__ src, float* __restrict__ dst) {
    int row = blockIdx.x;
    for (int i = threadIdx.x; i < FFP; i += blockDim.x)
        dst[(size_t)row*FFP + i] = (i < FFD) ? src[(size_t)row*FFD + i] : 0.f;
}

__global__ void rms_kernel(const float* __restrict__ in, const float* __restrict__ w,
                           float* __restrict__ out) {
    __shared__ float red[256];
    int row = blockIdx.x;
    const float* x = in + (size_t)row * HH;
    float* o = out + (size_t)row * HH;
    int t = threadIdx.x;
    float v[4];
    float ss = 0.f;
#pragma unroll
    for (int i = 0; i < 4; i++) { v[i] = x[t + i*256]; ss += v[i]*v[i]; }
    red[t] = ss;
    __syncthreads();
    for (int ofs = 128; ofs > 0; ofs >>= 1) {
        if (t < ofs) red[t] += red[t + ofs];
        __syncthreads();
    }
    float inv = rsqrtf(red[0] * (1.0f/HH) + EPSV);
#pragma unroll
    for (int i = 0; i < 4; i++) {
        int c = t + i*256;
        o[c] = to_tf32(v[i] * inv * w[c]);
    }
}

// ---------------- custom tf32 mma GEMM ----------------
// C[M,N] = op(A)@W^T (+bias)(+addend). A pre-rounded tf32 (or silu fused+rounded).
// Permuted smem: A lane-stride 20 words, B lane-stride 14 words (conflict-free).

__device__ __forceinline__ void mma_tf32(float* d, const uint32_t* a, const uint32_t* b) {
    asm volatile(
        "mma.sync.aligned.m16n8k8.row.col.f32.tf32.tf32.f32 "
        "{%0,%1,%2,%3}, {%4,%5,%6,%7}, {%8,%9}, {%0,%1,%2,%3};\n"
        : "+f"(d[0]), "+f"(d[1]), "+f"(d[2]), "+f"(d[3])
        : "r"(a[0]), "r"(a[1]), "r"(a[2]), "r"(a[3]), "r"(b[0]), "r"(b[1]));
}

template<int MBLK, int NBLK>
__global__ __launch_bounds__(256) void mgemm(
    const float* __restrict__ A, const float* __restrict__ A2, int lda,
    const float* __restrict__ W, int ldw,
    const float* __restrict__ bias, const float* __restrict__ addend, int ldad,
    float* __restrict__ C, int ldc, int M, int N, int Kd, int padTo)
{
    constexpr int WC  = NBLK / 64;           // warp cols
    constexpr int AIT = MBLK / 32;           // A float4 loads per thread per stage
    constexpr int BIT = NBLK / 32;
    constexpr int ASZ = MBLK * 40;           // (MBLK/16) mb * 32 lanes * 20 words
    constexpr int BSZ = NBLK * 56;           // (NBLK/8) nb * 32 lanes * 14 words
    constexpr int STG = ASZ + BSZ;

    extern __shared__ float sm[];
    const int tid  = threadIdx.x;
    const int lane = tid & 31;
    const int wid  = tid >> 5;
    const int wr   = wid / WC, wc = wid % WC;
    const int mb0  = wr * 4;                 // 4 m16 blocks per warp (64 rows)
    const int nb0  = wc * 8;                 // 8 n8 blocks per warp (64 cols)
    const int bm = blockIdx.y * MBLK, bn = blockIdx.x * NBLK;

    float acc[4][8][4];
#pragma unroll
    for (int i = 0; i < 4; i++)
#pragma unroll
        for (int n = 0; n < 8; n++)
#pragma unroll
            for (int q = 0; q < 4; q++) acc[i][n][q] = 0.f;

    float4 pa[AIT], pb[BIT];
    const int T = (Kd + 31) / 32;

    auto ldgA = [&](int t) {
        int k0 = t * 32;
#pragma unroll
        for (int ch = 0; ch < AIT; ch++) {
            int idx = tid + ch*256;
            int r = idx >> 3, kq = (idx & 7) * 4;
            int gk = k0 + kq;
            if (gk < Kd) {
                const float* src = A + (size_t)(bm + r)*lda + gk;
                if (A2 == nullptr) {
                    pa[ch] = *(const float4*)src;
                } else {
                    float4 u = *(const float4*)src;
                    float4 g2 = *(const float4*)(A2 + (size_t)(bm + r)*lda + gk);
                    float4 v;
                    v.x = to_tf32(u.x / (1.f + __expf(-u.x)) * g2.x);
                    v.y = to_tf32(u.y / (1.f + __expf(-u.y)) * g2.y);
                    v.z = to_tf32(u.z / (1.f + __expf(-u.z)) * g2.z);
                    v.w = to_tf32(u.w / (1.f + __expf(-u.w)) * g2.w);
                    pa[ch] = v;
                }
            } else pa[ch] = make_float4(0.f, 0.f, 0.f, 0.f);
        }
    };
    auto ldgB = [&](int t) {
        int k0 = t * 32;
#pragma unroll
        for (int ch = 0; ch < BIT; ch++) {
            int idx = tid + ch*256;
            int n = idx >> 3, kq = (idx & 7) * 4;
            int gn = bn + n, gk = k0 + kq;
            if (gn < N && gk < Kd)
                pb[ch] = *(const float4*)(W + (size_t)gn*ldw + gk);
            else
                pb[ch] = make_float4(0.f, 0.f, 0.f, 0.f);
        }
    };
    auto sts = [&](int stage) {
        float* As = sm + stage*STG;
        float* Bs = As + ASZ;
#pragma unroll
        for (int ch = 0; ch < AIT; ch++) {
            int idx = tid + ch*256;
            int r = idx >> 3, kq = (idx & 7) * 4;
            int mb = r >> 4, rr = r & 15;
            int kb = kq >> 3, kk0 = kq & 7;
            int slot = ((rr >> 3) & 1) + ((kk0 >> 2) << 1);
            int lb = (rr & 7) * 4;
            float* dst = As + (mb*32)*20 + kb*4 + slot;
            dst[(lb+0)*20] = pa[ch].x;
            dst[(lb+1)*20] = pa[ch].y;
            dst[(lb+2)*20] = pa[ch].z;
            dst[(lb+3)*20] = pa[ch].w;
        }
#pragma unroll
        for (int ch = 0; ch < BIT; ch++) {
            int idx = tid + ch*256;
            int n = idx >> 3, kq = (idx & 7) * 4;
            int nb = n >> 3, gg = n & 7;
            int kb = kq >> 3, kk0 = kq & 7;
            int sl = kk0 >> 2;
            float* dst = Bs + (nb*32 + gg*4)*14 + kb*2 + sl;
            dst[0*14] = to_tf32(pb[ch].x);
            dst[1*14] = to_tf32(pb[ch].y);
            dst[2*14] = to_tf32(pb[ch].z);
            dst[3*14] = to_tf32(pb[ch].w);
        }
    };

    ldgA(0); ldgB(0);
    sts(0);
    __syncthreads();
    if (T > 1) { ldgA(1); ldgB(1); }

    for (int t = 0; t < T; t++) {
        if (t + 1 < T) sts((t + 1) & 1);
        if (t + 2 < T) { ldgA(t + 2); ldgB(t + 2); }
        const float* As = sm + (t & 1)*STG;
        const float* Bs = As + ASZ;
#pragma unroll
        for (int kb = 0; kb < 4; kb++) {
            uint32_t af[4][4];
#pragma unroll
            for (int i = 0; i < 4; i++) {
                float4 v = *(const float4*)(As + ((mb0 + i)*32 + lane)*20 + kb*4);
                af[i][0] = __float_as_uint(v.x);
                af[i][1] = __float_as_uint(v.y);
                af[i][2] = __float_as_uint(v.z);
                af[i][3] = __float_as_uint(v.w);
            }
            uint32_t bf[8][2];
#pragma unroll
            for (int n = 0; n < 8; n++) {
                float2 v = *(const float2*)(Bs + ((nb0 + n)*32 + lane)*14 + kb*2);
                bf[n][0] = __float_as_uint(v.x);
                bf[n][1] = __float_as_uint(v.y);
            }
#pragma unroll
            for (int i = 0; i < 4; i++)
#pragma unroll
                for (int n = 0; n < 8; n++)
                    mma_tf32(acc[i][n], af[i], bf[n]);
        }
        __syncthreads();
    }

    // epilogue: direct register -> global with bias/addend
    const int g = lane >> 2, tg = lane & 3;
#pragma unroll
    for (int i = 0; i < 4; i++) {
        int r0 = bm + (mb0 + i)*16 + g;
        int r1 = r0 + 8;
#pragma unroll
        for (int n = 0; n < 8; n++) {
            int gn = bn + (nb0 + n)*8 + tg*2;
            if (gn < padTo) {
                float b0 = 0.f, b1 = 0.f;
                if (bias) { b0 = bias[gn]; b1 = bias[gn+1]; }
                float v0 = acc[i][n][0] + b0, v1 = acc[i][n][1] + b1;
                float v2 = acc[i][n][2] + b0, v3 = acc[i][n][3] + b1;
                if (addend) {
                    float2 a0 = *(const float2*)(addend + (size_t)r0*ldad + gn);
                    float2 a1 = *(const float2*)(addend + (size_t)r1*ldad + gn);
                    v0 += a0.x; v1 += a0.y; v2 += a1.x; v3 += a1.y;
                }
                *(float2*)(C + (size_t)r0*ldc + gn) = make_float2(v0, v1);
                *(float2*)(C + (size_t)r1*ldc + gn) = make_float2(v2, v3);
            }
        }
    }
}

// ---------------- cascade self-attn ----------------
__global__ void casc_attn_kernel() {
    __shared__ float ks[KK][DH+1];
    __shared__ float vs[KK][DH+1];
    int bh = blockIdx.x;
    int b = bh / NHH, nh = bh % NHH;
    int t = threadIdx.x;
    const float* base = g_qkv + ((size_t)(b*KK + t)) * (3*HH);
#pragma unroll
    for (int dd = 0; dd < DH; dd++) {
        ks[t][dd] = base[HH   + nh*DH + dd];
        vs[t][dd] = base[2*HH + nh*DH + dd];
    }
    __syncthreads();
    float q[DH];
#pragma unroll
    for (int dd = 0; dd < DH; dd++) q[dd] = base[nh*DH + dd];

    const float scale = 0.125f;
    float sc[KK];
    float mx = -1e30f;
    for (int j = 0; j <= t; j++) {
        float s = 0.f;
#pragma unroll
        for (int dd = 0; dd < DH; dd++) s += q[dd] * ks[j][dd];
        s *= scale;
        sc[j] = s;
        mx = fmaxf(mx, s);
    }
    float sum = 0.f;
    for (int j = 0; j <= t; j++) {
        float e = expf(sc[j] - mx);
        sc[j] = e;
        sum += e;
    }
    float inv = 1.0f / sum;
    float* o = g_attn + ((size_t)(b*KK + t)) * HH + nh*DH;
#pragma unroll 4
    for (int dd = 0; dd < DH; dd++) {
        float acc = 0.f;
        for (int j = 0; j <= t; j++) acc += sc[j] * vs[j][dd];
        o[dd] = to_tf32(acc * inv);
    }
}

// ---------------- decoder cross-attn ----------------
__global__ void dec_attn_kernel() {
    __shared__ float ks[KK][DH+1];
    __shared__ float vs[KK][DH+1];
    __shared__ float qs[8][DH];
    __shared__ float probs[8][KK];
    int nh = blockIdx.x, b = blockIdx.y;
    int tid = threadIdx.x;
    for (int i = tid; i < KK*DH; i += 256) {
        int c = i / DH, dd = i % DH;
        const float* kvrow = g_kv + ((size_t)(b*KK + c)) * (2*HH);
        ks[c][dd] = kvrow[nh*DH + dd];
        vs[c][dd] = kvrow[HH + nh*DH + dd];
    }
    __syncthreads();
    int w = tid >> 5, lane = tid & 31;
    const float scale = 0.125f;
    for (int s = w; s < SS; s += 8) {
        int nallow = min(KK, s/32 + 2);
        const float* qrow = g_q + ((size_t)b*SS + s) * HH + nh*DH;
        qs[w][lane]      = qrow[lane];
        qs[w][lane + 32] = qrow[lane + 32];
        __syncwarp();
        float s0 = -INFINITY, s1 = -INFINITY;
        if (lane < nallow) {
            float acc = 0.f;
#pragma unroll
            for (int dd = 0; dd < DH; dd++) acc += qs[w][dd] * ks[lane][dd];
            s0 = acc * scale;
        }
        if (lane + 32 < nallow) {
            float acc = 0.f;
#pragma unroll
            for (int dd = 0; dd < DH; dd++) acc += qs[w][dd] * ks[lane + 32][dd];
            s1 = acc * scale;
        }
        float mx = fmaxf(s0, s1);
#pragma unroll
        for (int ofs = 16; ofs > 0; ofs >>= 1)
            mx = fmaxf(mx, __shfl_xor_sync(0xffffffffu, mx, ofs));
        float e0 = expf(s0 - mx);
        float e1 = expf(s1 - mx);
        float sum = e0 + e1;
#pragma unroll
        for (int ofs = 16; ofs > 0; ofs >>= 1)
            sum += __shfl_xor_sync(0xffffffffu, sum, ofs);
        float inv = 1.0f / sum;
        probs[w][lane]      = e0 * inv;
        probs[w][lane + 32] = e1 * inv;
        __syncwarp();
        float* orow = g_dec + ((size_t)b*SS + s) * HH + nh*DH;
#pragma unroll
        for (int half = 0; half < 2; half++) {
            int dd = lane + half*32;
            float acc = 0.f;
            for (int j = 0; j < nallow; j++) acc += probs[w][j] * vs[j][dd];
            orow[dd] = to_tf32(acc);
        }
        __syncwarp();
    }
}

// ---------------- host ----------------
static float* symaddr(const void* sym) {
    void* p = nullptr;
    cudaGetSymbolAddress(&p, sym);
    return (float*)p;
}

#define SMEM_BIG   ((256*40 + 128*56) * 2 * 4)   // 139264
#define SMEM_SMALL ((128*40 + 256*56) * 2 * 4)   // 155648

extern "C" void kernel_launch(void* const* d_in, const int* in_sizes, int n_in,
                              void* d_out, int out_size) {
    const float* token       = (const float*)d_in[0];
    const float* chunk_repr  = (const float*)d_in[1];
    const float* cw          = (const float*)d_in[2];
    const float* casc_norm1  = (const float*)d_in[3];
    const float* casc_qkv    = (const float*)d_in[4];
    const float* casc_o      = (const float*)d_in[5];
    const float* casc_norm2  = (const float*)d_in[6];
    const float* casc_w1     = (const float*)d_in[7];
    const float* casc_w2     = (const float*)d_in[8];
    const float* casc_w3     = (const float*)d_in[9];
    const float* dec_in_w    = (const float*)d_in[10];
    const float* dec_in_b    = (const float*)d_in[11];
    const float* dec_out_w   = (const float*)d_in[12];
    const float* dec_out_b   = (const float*)d_in[13];
    const float* dec_norm_w  = (const float*)d_in[14];
    const float* dec_ffn_nw  = (const float*)d_in[15];
    const float* dec_w1      = (const float*)d_in[16];
    const float* dec_w2      = (const float*)d_in[17];
    const float* dec_w3      = (const float*)d_in[18];
    float* out = (float*)d_out;

    float* px    = symaddr(g_x);
    float* ph    = symaddr(g_h);
    float* pqkv  = symaddr(g_qkv);
    float* pattn = symaddr(g_attn);
    float* pff1  = symaddr(g_ff1);
    float* pff3  = symaddr(g_ff3);
    float* pproc = symaddr(g_proc);
    float* pq    = symaddr(g_q);
    float* pkv   = symaddr(g_kv);
    float* pdec  = symaddr(g_dec);
    float* py    = symaddr(g_y);
    float* pyn   = symaddr(g_yn);
    float* pu1   = symaddr(g_u1);
    float* pu3   = symaddr(g_u3);
    float* pw2p  = symaddr(g_w2pad);
    float* ptok  = symaddr(g_tok);

    cudaFuncSetAttribute(mgemm<256,128>, cudaFuncAttributeMaxDynamicSharedMemorySize, SMEM_BIG);
    cudaFuncSetAttribute(mgemm<128,256>, cudaFuncAttributeMaxDynamicSharedMemorySize, SMEM_SMALL);

    // big: M multiple of 256 (decoder, M=8192)
    auto gemmB = [&](const float* A, const float* A2, int lda,
                     const float* W, int ldw,
                     const float* bias, const float* addend, int ldad,
                     float* C, int ldc, int M, int N, int Kd, int padTo) {
        dim3 grid((padTo + 127)/128, M/256);
        mgemm<256,128><<<grid, 256, SMEM_BIG>>>(A, A2, lda, W, ldw, bias, addend, ldad,
                                                C, ldc, M, N, Kd, padTo);
    };
    // small: M multiple of 128 (cascade, M=256)
    auto gemmS = [&](const float* A, const float* A2, int lda,
                     const float* W, int ldw,
                     const float* bias, const float* addend, int ldad,
                     float* C, int ldc, int M, int N, int Kd, int padTo) {
        dim3 grid((padTo + 255)/256, M/128);
        mgemm<128,256><<<grid, 256, SMEM_SMALL>>>(A, A2, lda, W, ldw, bias, addend, ldad,
                                                  C, ldc, M, N, Kd, padTo);
    };

    rank_kernel<<<BB, KK>>>(cw);
    scatter_kernel<<<BB*KK, 256>>>(chunk_repr);

    const int MC = BB*KK;          // 256
    for (int l = 0; l < LL; l++) {
        rms_kernel<<<MC, 256>>>(px, casc_norm1 + l*HH, ph);
        gemmS(ph, nullptr, HH, casc_qkv + (size_t)l*3*HH*HH, HH,
              nullptr, nullptr, 0, pqkv, 3*HH, MC, 3*HH, HH, 3*HH);
        casc_attn_kernel<<<BB*NHH, KK>>>();
        gemmS(pattn, nullptr, HH, casc_o + (size_t)l*HH*HH, HH,
              nullptr, px, HH, px, HH, MC, HH, HH, HH);
        rms_kernel<<<MC, 256>>>(px, casc_norm2 + l*HH, ph);
        gemmS(ph, nullptr, HH, casc_w1 + (size_t)l*FFD*HH, HH,
              nullptr, nullptr, 0, pff1, FFP, MC, FFD, HH, FFP);
        gemmS(ph, nullptr, HH, casc_w3 + (size_t)l*FFD*HH, HH,
              nullptr, nullptr, 0, pff3, FFP, MC, FFD, HH, FFP);
        padw_kernel<<<HH, 256>>>(casc_w2 + (size_t)l*HH*FFD, pw2p);
        gemmS(pff1, pff3, FFP, pw2p, FFP,
              nullptr, px, HH, px, HH, MC, HH, FFP, HH);
    }
    gather_kernel<<<BB*KK, 256>>>();

    const int MT = BB*SS;          // 8192
    roundcopy_kernel<<<(MT*HH + 255)/256, 256>>>(token, ptok, MT*HH);
    gemmB(ptok, nullptr, HH, dec_in_w, HH,
          dec_in_b, nullptr, 0, pq, HH, MT, HH, HH, HH);
    gemmS(pproc, nullptr, HH, dec_in_w + (size_t)HH*HH, HH,
          dec_in_b + HH, nullptr, 0, pkv, 2*HH, MC, 2*HH, HH, 2*HH);
    dec_attn_kernel<<<dim3(NHH, BB), 256>>>();
    gemmB(pdec, nullptr, HH, dec_out_w, HH,
          dec_out_b, token, HH, pyn, HH, MT, HH, HH, HH);
    rms_kernel<<<MT, 256>>>(pyn, dec_norm_w, py);
    rms_kernel<<<MT, 256>>>(py, dec_ffn_nw, pyn);
    gemmB(pyn, nullptr, HH, dec_w1, HH,
          nullptr, nullptr, 0, pu1, FFP, MT, FFD, HH, FFP);
    gemmB(pyn, nullptr, HH, dec_w3, HH,
          nullptr, nullptr, 0, pu3, FFP, MT, FFD, HH, FFP);
    padw_kernel<<<HH, 256>>>(dec_w2, pw2p);
    gemmB(pu1, pu3, FFP, pw2p, FFP,
          nullptr, py, HH, out, HH, MT, HH, FFP, HH);
}

// round 7
// speedup vs baseline: 2.9291x; 1.5437x over previous
#include <cuda_runtime.h>
#include <cuda_bf16.h>
#include <math.h>
#include <stdint.h>

#define BB 4
#define SS 2048
#define HH 1024
#define KK 64
#define NHH 16
#define DH 64
#define LL 2
#define FFD 2730
#define FFP 2736
#define FF2 (2*FFP)
#define EPSV 1e-6f

// ---------------- scratch ----------------
__device__ float g_x[BB*KK*HH];
__device__ float g_h[BB*KK*HH];
__device__ float g_qkv[BB*KK*3*HH];
__device__ float g_attn[BB*KK*HH];
__device__ float g_ff13[BB*KK*FF2];
__device__ int   g_rank[BB*KK];
__device__ float g_proc[BB*KK*HH];
__device__ float g_q[BB*SS*HH];
__device__ float g_kv[BB*KK*2*HH];
__device__ float g_dec[BB*SS*HH];
__device__ float g_y[BB*SS*HH];
__device__ float g_yn[BB*SS*HH];
__device__ float g_u13[BB*SS*FF2];
__device__ float g_tok[BB*SS*HH];

// tf32-rounded weights
__device__ float g_wr_qkv[LL*3*HH*HH];
__device__ float g_wr_o[LL*HH*HH];
__device__ float g_wr_w13[LL*FF2*HH];
__device__ float g_wr_w2[LL*HH*FFP];
__device__ float g_wr_din[3*HH*HH];
__device__ float g_wr_dout[HH*HH];
__device__ float g_wr_dw13[FF2*HH];
__device__ float g_wr_dw2[HH*FFP];

__device__ __forceinline__ float to_tf32(float x) {
    float r;
    asm("cvt.rna.tf32.f32 %0, %1;" : "=f"(r) : "f"(x));
    return r;
}

// ---------------- small kernels ----------------
__global__ void rank_kernel(const float* __restrict__ cw) {
    int b = blockIdx.x, k = threadIdx.x;
    float wk = cw[b*KK + k];
    int r = 0;
    for (int j = 0; j < KK; j++) {
        float wj = cw[b*KK + j];
        if (wj > wk || (wj == wk && j < k)) r++;
    }
    g_rank[b*KK + k] = r;
}

__global__ void scatter_kernel(const float* __restrict__ src) {
    int row = blockIdx.x;
    int b = row / KK;
    int r = g_rank[row];
    const float* s = src + (size_t)row * HH;
    float* d = g_x + ((size_t)(b*KK + r)) * HH;
    for (int i = threadIdx.x; i < HH; i += blockDim.x) d[i] = s[i];
}

__global__ void gather_kernel() {
    int row = blockIdx.x;
    int b = row / KK;
    int r = g_rank[row];
    const float* s = g_x + ((size_t)(b*KK + r)) * HH;
    float* d = g_proc + (size_t)row * HH;
    for (int i = threadIdx.x; i < HH; i += blockDim.x) d[i] = to_tf32(s[i]);
}

__global__ void roundcopy_kernel(const float* __restrict__ src, float* __restrict__ dst, int n) {
    for (int i = blockIdx.x * blockDim.x + threadIdx.x; i < n; i += gridDim.x * blockDim.x)
        dst[i] = to_tf32(src[i]);
}

// build [2*FFP][HH] = rounded concat(w1[FFD], pad, w3[FFD], pad)
__global__ void buildw13_kernel(const float* __restrict__ w1, const float* __restrict__ w3,
                                float* __restrict__ dst) {
    int row = blockIdx.x;   // 0 .. FF2-1
    const float* src = nullptr;
    if (row < FFD) src = w1 + (size_t)row * HH;
    else if (row >= FFP && row < FFP + FFD) src = w3 + (size_t)(row - FFP) * HH;
    float* d = dst + (size_t)row * HH;
    for (int i = threadIdx.x; i < HH; i += blockDim.x)
        d[i] = src ? to_tf32(src[i]) : 0.f;
}

// [HH][FFD] -> [HH][FFP] rounded + zero-padded
__global__ void padround_kernel(const float* __restrict__ src, float* __restrict__ dst) {
    int row = blockIdx.x;
    for (int i = threadIdx.x; i < FFP; i += blockDim.x)
        dst[(size_t)row*FFP + i] = (i < FFD) ? to_tf32(src[(size_t)row*FFD + i]) : 0.f;
}

__global__ void rms_kernel(const float* __restrict__ in, const float* __restrict__ w,
                           float* __restrict__ out) {
    __shared__ float red[256];
    int row = blockIdx.x;
    const float* x = in + (size_t)row * HH;
    float* o = out + (size_t)row * HH;
    int t = threadIdx.x;
    float v[4];
    float ss = 0.f;
#pragma unroll
    for (int i = 0; i < 4; i++) { v[i] = x[t + i*256]; ss += v[i]*v[i]; }
    red[t] = ss;
    __syncthreads();
    for (int ofs = 128; ofs > 0; ofs >>= 1) {
        if (t < ofs) red[t] += red[t + ofs];
        __syncthreads();
    }
    float inv = rsqrtf(red[0] * (1.0f/HH) + EPSV);
#pragma unroll
    for (int i = 0; i < 4; i++) {
        int c = t + i*256;
        o[c] = to_tf32(v[i] * inv * w[c]);
    }
}

// u [rows][FF2]: u[:, c] = tf32(silu(u[:, c]) * u[:, FFP + c]) for c < FFP
__global__ void glu_kernel(float* __restrict__ u, int rows) {
    int total = rows * FFP;
    for (int i = blockIdx.x * blockDim.x + threadIdx.x; i < total; i += gridDim.x * blockDim.x) {
        int m = i / FFP, c = i - m * FFP;
        float a = u[(size_t)m*FF2 + c];
        float b = u[(size_t)m*FF2 + FFP + c];
        u[(size_t)m*FF2 + c] = to_tf32((a / (1.0f + __expf(-a))) * b);
    }
}

// ---------------- tf32 mma.sync GEMM (512 threads, 128x256 tile) ----------
__device__ __forceinline__ void mma_tf32(float* d, const uint32_t* a, const uint32_t* b) {
    asm volatile(
        "mma.sync.aligned.m16n8k8.row.col.f32.tf32.tf32.f32 "
        "{%0,%1,%2,%3}, {%4,%5,%6,%7}, {%8,%9}, {%0,%1,%2,%3};\n"
        : "+f"(d[0]), "+f"(d[1]), "+f"(d[2]), "+f"(d[3])
        : "r"(a[0]), "r"(a[1]), "r"(a[2]), "r"(a[3]), "r"(b[0]), "r"(b[1]));
}

#define MBLK 128
#define NBLK 256
#define NTH  512
#define ASZ  (MBLK*40)
#define BSZ  (NBLK*56)
#define STGF (ASZ + BSZ)
#define SMEMB (2*STGF*4)

__global__ __launch_bounds__(NTH) void mgemm(
    const float* __restrict__ A, int lda,
    const float* __restrict__ W, int ldw,
    const float* __restrict__ bias, const float* __restrict__ addend, int ldad,
    float* __restrict__ C, int ldc, int M, int N, int Kd)
{
    extern __shared__ float sm[];
    const int tid  = threadIdx.x;
    const int lane = tid & 31;
    const int wid  = tid >> 5;          // 0..15
    const int wr   = wid >> 3, wc = wid & 7;
    const int mb0  = wr * 4;            // 4 m16 blocks (64 rows)
    const int nb0  = wc * 4;            // 4 n8 blocks (32 cols)
    const int bm = blockIdx.y * MBLK, bn = blockIdx.x * NBLK;

    float acc[4][4][4];
#pragma unroll
    for (int i = 0; i < 4; i++)
#pragma unroll
        for (int n = 0; n < 4; n++)
#pragma unroll
            for (int q = 0; q < 4; q++) acc[i][n][q] = 0.f;

    float4 pa[2], pb[4];
    const int T = (Kd + 31) / 32;

    auto ldgA = [&](int t) {
        int k0 = t * 32;
#pragma unroll
        for (int ch = 0; ch < 2; ch++) {
            int idx = tid + ch*NTH;
            int r = idx >> 3, kq = (idx & 7) * 4;
            int gk = k0 + kq;
            pa[ch] = (gk < Kd) ? *(const float4*)(A + (size_t)(bm + r)*lda + gk)
                               : make_float4(0.f, 0.f, 0.f, 0.f);
        }
    };
    auto ldgB = [&](int t) {
        int k0 = t * 32;
#pragma unroll
        for (int ch = 0; ch < 4; ch++) {
            int idx = tid + ch*NTH;
            int n = idx >> 3, kq = (idx & 7) * 4;
            int gn = bn + n, gk = k0 + kq;
            pb[ch] = (gn < N && gk < Kd) ? *(const float4*)(W + (size_t)gn*ldw + gk)
                                         : make_float4(0.f, 0.f, 0.f, 0.f);
        }
    };
    auto sts = [&](int stage) {
        float* As = sm + stage*STGF;
        float* Bs = As + ASZ;
#pragma unroll
        for (int ch = 0; ch < 2; ch++) {
            int idx = tid + ch*NTH;
            int r = idx >> 3, kq = (idx & 7) * 4;
            int mb = r >> 4, rr = r & 15;
            int kb = kq >> 3, kk0 = kq & 7;
            int slot = ((rr >> 3) & 1) + ((kk0 >> 2) << 1);
            int lb = (rr & 7) * 4;
            float* dst = As + (mb*32)*20 + kb*4 + slot;
            dst[(lb+0)*20] = pa[ch].x;
            dst[(lb+1)*20] = pa[ch].y;
            dst[(lb+2)*20] = pa[ch].z;
            dst[(lb+3)*20] = pa[ch].w;
        }
#pragma unroll
        for (int ch = 0; ch < 4; ch++) {
            int idx = tid + ch*NTH;
            int n = idx >> 3, kq = (idx & 7) * 4;
            int nb = n >> 3, gg = n & 7;
            int kb = kq >> 3, kk0 = kq & 7;
            int sl = kk0 >> 2;
            float* dst = Bs + (nb*32 + gg*4)*14 + kb*2 + sl;
            dst[0*14] = pb[ch].x;
            dst[1*14] = pb[ch].y;
            dst[2*14] = pb[ch].z;
            dst[3*14] = pb[ch].w;
        }
    };

    ldgA(0); ldgB(0);
    sts(0);
    __syncthreads();
    if (T > 1) { ldgA(1); ldgB(1); }

    for (int t = 0; t < T; t++) {
        if (t + 1 < T) sts((t + 1) & 1);
        if (t + 2 < T) { ldgA(t + 2); ldgB(t + 2); }
        const float* As = sm + (t & 1)*STGF;
        const float* Bs = As + ASZ;
#pragma unroll
        for (int kb = 0; kb < 4; kb++) {
            uint32_t af[4][4];
#pragma unroll
            for (int i = 0; i < 4; i++) {
                float4 v = *(const float4*)(As + ((mb0 + i)*32 + lane)*20 + kb*4);
                af[i][0] = __float_as_uint(v.x);
                af[i][1] = __float_as_uint(v.y);
                af[i][2] = __float_as_uint(v.z);
                af[i][3] = __float_as_uint(v.w);
            }
            uint32_t bf[4][2];
#pragma unroll
            for (int n = 0; n < 4; n++) {
                float2 v = *(const float2*)(Bs + ((nb0 + n)*32 + lane)*14 + kb*2);
                bf[n][0] = __float_as_uint(v.x);
                bf[n][1] = __float_as_uint(v.y);
            }
#pragma unroll
            for (int i = 0; i < 4; i++)
#pragma unroll
                for (int n = 0; n < 4; n++)
                    mma_tf32(acc[i][n], af[i], bf[n]);
        }
        __syncthreads();
    }

    // epilogue: direct register -> global with bias/addend
    const int g = lane >> 2, tg = lane & 3;
#pragma unroll
    for (int i = 0; i < 4; i++) {
        int r0 = bm + (mb0 + i)*16 + g;
        int r1 = r0 + 8;
#pragma unroll
        for (int n = 0; n < 4; n++) {
            int gn = bn + (nb0 + n)*8 + tg*2;
            if (gn < N) {
                float b0 = 0.f, b1 = 0.f;
                if (bias) { b0 = bias[gn]; b1 = bias[gn+1]; }
                float v0 = acc[i][n][0] + b0, v1 = acc[i][n][1] + b1;
                float v2 = acc[i][n][2] + b0, v3 = acc[i][n][3] + b1;
                if (addend) {
                    float2 a0 = *(const float2*)(addend + (size_t)r0*ldad + gn);
                    float2 a1 = *(const float2*)(addend + (size_t)r1*ldad + gn);
                    v0 += a0.x; v1 += a0.y; v2 += a1.x; v3 += a1.y;
                }
                *(float2*)(C + (size_t)r0*ldc + gn) = make_float2(v0, v1);
                *(float2*)(C + (size_t)r1*ldc + gn) = make_float2(v2, v3);
            }
        }
    }
}

// ---------------- cascade self-attn ----------------
__global__ void casc_attn_kernel() {
    __shared__ float ks[KK][DH+1];
    __shared__ float vs[KK][DH+1];
    int bh = blockIdx.x;
    int b = bh / NHH, nh = bh % NHH;
    int t = threadIdx.x;
    const float* base = g_qkv + ((size_t)(b*KK + t)) * (3*HH);
#pragma unroll
    for (int dd = 0; dd < DH; dd++) {
        ks[t][dd] = base[HH   + nh*DH + dd];
        vs[t][dd] = base[2*HH + nh*DH + dd];
    }
    __syncthreads();
    float q[DH];
#pragma unroll
    for (int dd = 0; dd < DH; dd++) q[dd] = base[nh*DH + dd];

    const float scale = 0.125f;
    float sc[KK];
    float mx = -1e30f;
    for (int j = 0; j <= t; j++) {
        float s = 0.f;
#pragma unroll
        for (int dd = 0; dd < DH; dd++) s += q[dd] * ks[j][dd];
        s *= scale;
        sc[j] = s;
        mx = fmaxf(mx, s);
    }
    float sum = 0.f;
    for (int j = 0; j <= t; j++) {
        float e = expf(sc[j] - mx);
        sc[j] = e;
        sum += e;
    }
    float inv = 1.0f / sum;
    float* o = g_attn + ((size_t)(b*KK + t)) * HH + nh*DH;
#pragma unroll 4
    for (int dd = 0; dd < DH; dd++) {
        float acc = 0.f;
        for (int j = 0; j <= t; j++) acc += sc[j] * vs[j][dd];
        o[dd] = to_tf32(acc * inv);
    }
}

// ---------------- decoder cross-attn ----------------
__global__ void dec_attn_kernel() {
    __shared__ float ks[KK][DH+1];
    __shared__ float vs[KK][DH+1];
    __shared__ float qs[8][DH];
    __shared__ float probs[8][KK];
    int nh = blockIdx.x, b = blockIdx.y;
    int tid = threadIdx.x;
    for (int i = tid; i < KK*DH; i += 256) {
        int c = i / DH, dd = i % DH;
        const float* kvrow = g_kv + ((size_t)(b*KK + c)) * (2*HH);
        ks[c][dd] = kvrow[nh*DH + dd];
        vs[c][dd] = kvrow[HH + nh*DH + dd];
    }
    __syncthreads();
    int w = tid >> 5, lane = tid & 31;
    const float scale = 0.125f;
    for (int s = w; s < SS; s += 8) {
        int nallow = min(KK, s/32 + 2);
        const float* qrow = g_q + ((size_t)b*SS + s) * HH + nh*DH;
        qs[w][lane]      = qrow[lane];
        qs[w][lane + 32] = qrow[lane + 32];
        __syncwarp();
        float s0 = -INFINITY, s1 = -INFINITY;
        if (lane < nallow) {
            float acc = 0.f;
#pragma unroll
            for (int dd = 0; dd < DH; dd++) acc += qs[w][dd] * ks[lane][dd];
            s0 = acc * scale;
        }
        if (lane + 32 < nallow) {
            float acc = 0.f;
#pragma unroll
            for (int dd = 0; dd < DH; dd++) acc += qs[w][dd] * ks[lane + 32][dd];
            s1 = acc * scale;
        }
        float mx = fmaxf(s0, s1);
#pragma unroll
        for (int ofs = 16; ofs > 0; ofs >>= 1)
            mx = fmaxf(mx, __shfl_xor_sync(0xffffffffu, mx, ofs));
        float e0 = expf(s0 - mx);
        float e1 = expf(s1 - mx);
        float sum = e0 + e1;
#pragma unroll
        for (int ofs = 16; ofs > 0; ofs >>= 1)
            sum += __shfl_xor_sync(0xffffffffu, sum, ofs);
        float inv = 1.0f / sum;
        probs[w][lane]      = e0 * inv;
        probs[w][lane + 32] = e1 * inv;
        __syncwarp();
        float* orow = g_dec + ((size_t)b*SS + s) * HH + nh*DH;
#pragma unroll
        for (int half = 0; half < 2; half++) {
            int dd = lane + half*32;
            float acc = 0.f;
            for (int j = 0; j < nallow; j++) acc += probs[w][j] * vs[j][dd];
            orow[dd] = to_tf32(acc);
        }
        __syncwarp();
    }
}

// ---------------- host ----------------
static float* symaddr(const void* sym) {
    void* p = nullptr;
    cudaGetSymbolAddress(&p, sym);
    return (float*)p;
}

extern "C" void kernel_launch(void* const* d_in, const int* in_sizes, int n_in,
                              void* d_out, int out_size) {
    const float* token       = (const float*)d_in[0];
    const float* chunk_repr  = (const float*)d_in[1];
    const float* cw          = (const float*)d_in[2];
    const float* casc_norm1  = (const float*)d_in[3];
    const float* casc_qkv    = (const float*)d_in[4];
    const float* casc_o      = (const float*)d_in[5];
    const float* casc_norm2  = (const float*)d_in[6];
    const float* casc_w1     = (const float*)d_in[7];
    const float* casc_w2     = (const float*)d_in[8];
    const float* casc_w3     = (const float*)d_in[9];
    const float* dec_in_w    = (const float*)d_in[10];
    const float* dec_in_b    = (const float*)d_in[11];
    const float* dec_out_w   = (const float*)d_in[12];
    const float* dec_out_b   = (const float*)d_in[13];
    const float* dec_norm_w  = (const float*)d_in[14];
    const float* dec_ffn_nw  = (const float*)d_in[15];
    const float* dec_w1      = (const float*)d_in[16];
    const float* dec_w2      = (const float*)d_in[17];
    const float* dec_w3      = (const float*)d_in[18];
    float* out = (float*)d_out;

    float* px    = symaddr(g_x);
    float* ph    = symaddr(g_h);
    float* pqkv  = symaddr(g_qkv);
    float* pattn = symaddr(g_attn);
    float* pff13 = symaddr(g_ff13);
    float* pproc = symaddr(g_proc);
    float* pq    = symaddr(g_q);
    float* pkv   = symaddr(g_kv);
    float* pdec  = symaddr(g_dec);
    float* py    = symaddr(g_y);
    float* pyn   = symaddr(g_yn);
    float* pu13  = symaddr(g_u13);
    float* ptok  = symaddr(g_tok);

    float* wr_qkv  = symaddr(g_wr_qkv);
    float* wr_o    = symaddr(g_wr_o);
    float* wr_w13  = symaddr(g_wr_w13);
    float* wr_w2   = symaddr(g_wr_w2);
    float* wr_din  = symaddr(g_wr_din);
    float* wr_dout = symaddr(g_wr_dout);
    float* wr_dw13 = symaddr(g_wr_dw13);
    float* wr_dw2  = symaddr(g_wr_dw2);

    cudaFuncSetAttribute(mgemm, cudaFuncAttributeMaxDynamicSharedMemorySize, SMEMB);

    auto gemm = [&](const float* A, int lda, const float* W, int ldw,
                    const float* bias, const float* addend, int ldad,
                    float* C, int ldc, int M, int N, int Kd) {
        dim3 grid((N + NBLK - 1)/NBLK, M/MBLK);
        mgemm<<<grid, NTH, SMEMB>>>(A, lda, W, ldw, bias, addend, ldad, C, ldc, M, N, Kd);
    };

    // --- weight prep ---
    roundcopy_kernel<<<2048, 256>>>(casc_qkv, wr_qkv, LL*3*HH*HH);
    roundcopy_kernel<<<2048, 256>>>(casc_o,   wr_o,   LL*HH*HH);
    for (int l = 0; l < LL; l++) {
        buildw13_kernel<<<FF2, 256>>>(casc_w1 + (size_t)l*FFD*HH,
                                      casc_w3 + (size_t)l*FFD*HH,
                                      wr_w13 + (size_t)l*FF2*HH);
        padround_kernel<<<HH, 256>>>(casc_w2 + (size_t)l*HH*FFD,
                                     wr_w2 + (size_t)l*HH*FFP);
    }
    roundcopy_kernel<<<2048, 256>>>(dec_in_w,  wr_din,  3*HH*HH);
    roundcopy_kernel<<<2048, 256>>>(dec_out_w, wr_dout, HH*HH);
    buildw13_kernel<<<FF2, 256>>>(dec_w1, dec_w3, wr_dw13);
    padround_kernel<<<HH, 256>>>(dec_w2, wr_dw2);
    roundcopy_kernel<<<2048, 256>>>(token, ptok, BB*SS*HH);

    // --- cascade ---
    rank_kernel<<<BB, KK>>>(cw);
    scatter_kernel<<<BB*KK, 256>>>(chunk_repr);

    const int MC = BB*KK;          // 256
    for (int l = 0; l < LL; l++) {
        rms_kernel<<<MC, 256>>>(px, casc_norm1 + l*HH, ph);
        gemm(ph, HH, wr_qkv + (size_t)l*3*HH*HH, HH,
             nullptr, nullptr, 0, pqkv, 3*HH, MC, 3*HH, HH);
        casc_attn_kernel<<<BB*NHH, KK>>>();
        gemm(pattn, HH, wr_o + (size_t)l*HH*HH, HH,
             nullptr, px, HH, px, HH, MC, HH, HH);
        rms_kernel<<<MC, 256>>>(px, casc_norm2 + l*HH, ph);
        gemm(ph, HH, wr_w13 + (size_t)l*FF2*HH, HH,
             nullptr, nullptr, 0, pff13, FF2, MC, FF2, HH);
        glu_kernel<<<1024, 256>>>(pff13, MC);
        gemm(pff13, FF2, wr_w2 + (size_t)l*HH*FFP, FFP,
             nullptr, px, HH, px, HH, MC, HH, FFP);
    }
    gather_kernel<<<BB*KK, 256>>>();

    // --- decoder ---
    const int MT = BB*SS;          // 8192
    gemm(ptok, HH, wr_din, HH,
         dec_in_b, nullptr, 0, pq, HH, MT, HH, HH);
    gemm(pproc, HH, wr_din + (size_t)HH*HH, HH,
         dec_in_b + HH, nullptr, 0, pkv, 2*HH, MC, 2*HH, HH);
    dec_attn_kernel<<<dim3(NHH, BB), 256>>>();
    gemm(pdec, HH, wr_dout, HH,
         dec_out_b, token, HH, pyn, HH, MT, HH, HH);
    rms_kernel<<<MT, 256>>>(pyn, dec_norm_w, py);
    rms_kernel<<<MT, 256>>>(py, dec_ffn_nw, pyn);
    gemm(pyn, HH, wr_dw13, HH,
         nullptr, nullptr, 0, pu13, FF2, MT, FF2, HH);
    glu_kernel<<<4096, 256>>>(pu13, MT);
    gemm(pu13, FF2, wr_dw2, FFP,
         nullptr, py, HH, out, HH, MT, HH, FFP);
}

// round 8
// speedup vs baseline: 3.1591x; 1.0785x over previous
#include <cuda_runtime.h>
#include <cuda_bf16.h>
#include <math.h>
#include <stdint.h>

#define BB 4
#define SS 2048
#define HH 1024
#define KK 64
#define NHH 16
#define DH 64
#define LL 2
#define FFD 2730
#define FFP 2736
#define FF2 (2*FFP)
#define EPSV 1e-6f

// ---------------- scratch ----------------
__device__ float g_x[BB*KK*HH];
__device__ float g_h[BB*KK*HH];
__device__ float g_qkv[BB*KK*3*HH];
__device__ float g_attn[BB*KK*HH];
__device__ float g_ff13[BB*KK*FF2];
__device__ int   g_rank[BB*KK];
__device__ float g_proc[BB*KK*HH];
__device__ float g_q[BB*SS*HH];
__device__ float g_kv[BB*KK*2*HH];
__device__ float g_dec[BB*SS*HH];
__device__ float g_y[BB*SS*HH];
__device__ float g_yn[BB*SS*HH];
__device__ float g_u13[BB*SS*FF2];

// re-laid-out weights (concat/pad only; tf32 rounding happens in GEMM)
__device__ float g_w13[LL*FF2*HH];
__device__ float g_w2pad[LL*HH*FFP];
__device__ float g_dw13[FF2*HH];
__device__ float g_dw2pad[HH*FFP];

__device__ __forceinline__ float to_tf32(float x) {
    float r;
    asm("cvt.rna.tf32.f32 %0, %1;" : "=f"(r) : "f"(x));
    return r;
}

// ---------------- small kernels ----------------
__global__ void rank_kernel(const float* __restrict__ cw) {
    int b = blockIdx.x, k = threadIdx.x;
    float wk = cw[b*KK + k];
    int r = 0;
    for (int j = 0; j < KK; j++) {
        float wj = cw[b*KK + j];
        if (wj > wk || (wj == wk && j < k)) r++;
    }
    g_rank[b*KK + k] = r;
}

__global__ void scatter_kernel(const float* __restrict__ src) {
    int row = blockIdx.x;
    int b = row / KK;
    int r = g_rank[row];
    const float* s = src + (size_t)row * HH;
    float* d = g_x + ((size_t)(b*KK + r)) * HH;
    for (int i = threadIdx.x; i < HH; i += blockDim.x) d[i] = s[i];
}

__global__ void gather_kernel() {
    int row = blockIdx.x;
    int b = row / KK;
    int r = g_rank[row];
    const float* s = g_x + ((size_t)(b*KK + r)) * HH;
    float* d = g_proc + (size_t)row * HH;
    for (int i = threadIdx.x; i < HH; i += blockDim.x) d[i] = s[i];
}

// [2*FFP][HH] = concat(w1[FFD], 0-pad, w3[FFD], 0-pad)
__global__ void buildw13_kernel(const float* __restrict__ w1, const float* __restrict__ w3,
                                float* __restrict__ dst) {
    int row = blockIdx.x;
    const float* src = nullptr;
    if (row < FFD) src = w1 + (size_t)row * HH;
    else if (row >= FFP && row < FFP + FFD) src = w3 + (size_t)(row - FFP) * HH;
    float* d = dst + (size_t)row * HH;
    for (int i = threadIdx.x; i < HH; i += blockDim.x)
        d[i] = src ? src[i] : 0.f;
}

// [HH][FFD] -> [HH][FFP] zero-padded
__global__ void padw_kernel(const float* __restrict__ src, float* __restrict__ dst) {
    int row = blockIdx.x;
    for (int i = threadIdx.x; i < FFP; i += blockDim.x)
        dst[(size_t)row*FFP + i] = (i < FFD) ? src[(size_t)row*FFD + i] : 0.f;
}

__global__ void rms_kernel(const float* __restrict__ in, const float* __restrict__ w,
                           float* __restrict__ out) {
    __shared__ float red[256];
    int row = blockIdx.x;
    const float* x = in + (size_t)row * HH;
    float* o = out + (size_t)row * HH;
    int t = threadIdx.x;
    float v[4];
    float ss = 0.f;
#pragma unroll
    for (int i = 0; i < 4; i++) { v[i] = x[t + i*256]; ss += v[i]*v[i]; }
    red[t] = ss;
    __syncthreads();
    for (int ofs = 128; ofs > 0; ofs >>= 1) {
        if (t < ofs) red[t] += red[t + ofs];
        __syncthreads();
    }
    float inv = rsqrtf(red[0] * (1.0f/HH) + EPSV);
#pragma unroll
    for (int i = 0; i < 4; i++) {
        int c = t + i*256;
        o[c] = v[i] * inv * w[c];
    }
}

// ---------------- tf32 mma.sync GEMM (512 threads, templated tile) --------
// C[M,N] = op(A)@W^T (+bias)(+addend).  op(A)=A, or silu(A)*A2 when A2!=0.
// tf32 rounding of both operands happens at STS time.
__device__ __forceinline__ void mma_tf32(float* d, const uint32_t* a, const uint32_t* b) {
    asm volatile(
        "mma.sync.aligned.m16n8k8.row.col.f32.tf32.tf32.f32 "
        "{%0,%1,%2,%3}, {%4,%5,%6,%7}, {%8,%9}, {%0,%1,%2,%3};\n"
        : "+f"(d[0]), "+f"(d[1]), "+f"(d[2]), "+f"(d[3])
        : "r"(a[0]), "r"(a[1]), "r"(a[2]), "r"(a[3]), "r"(b[0]), "r"(b[1]));
}

#define NTH 512

template<int MB, int NB, int WR, int WC>
__global__ __launch_bounds__(NTH) void mgemm(
    const float* __restrict__ A, const float* __restrict__ A2, int lda,
    const float* __restrict__ W, int ldw,
    const float* __restrict__ bias, const float* __restrict__ addend, int ldad,
    float* __restrict__ C, int ldc, int M, int N, int Kd)
{
    constexpr int MI = MB / WR / 16;     // m16 blocks per warp
    constexpr int NI = NB / WC / 8;      // n8 blocks per warp
    constexpr int AIT = MB / 64;         // A float4 per thread per stage
    constexpr int BIT = NB / 64;
    constexpr int ASZ = MB * 40;
    constexpr int BSZ = NB * 56;
    constexpr int STGF = ASZ + BSZ;

    extern __shared__ float sm[];
    const int tid  = threadIdx.x;
    const int lane = tid & 31;
    const int wid  = tid >> 5;
    const int wr   = wid / WC, wc = wid % WC;
    const int mb0  = wr * MI;
    const int nb0  = wc * NI;
    const int bm = blockIdx.y * MB, bn = blockIdx.x * NB;

    float acc[MI][NI][4];
#pragma unroll
    for (int i = 0; i < MI; i++)
#pragma unroll
        for (int n = 0; n < NI; n++)
#pragma unroll
            for (int q = 0; q < 4; q++) acc[i][n][q] = 0.f;

    float4 pa[AIT], pb[BIT];
    const int T = (Kd + 31) / 32;

    auto ldgA = [&](int t) {
        int k0 = t * 32;
#pragma unroll
        for (int ch = 0; ch < AIT; ch++) {
            int idx = tid + ch*NTH;
            int r = idx >> 3, kq = (idx & 7) * 4;
            int gk = k0 + kq;
            if (gk < Kd) {
                if (A2 == nullptr) {
                    pa[ch] = *(const float4*)(A + (size_t)(bm + r)*lda + gk);
                } else {
                    float4 u = *(const float4*)(A  + (size_t)(bm + r)*lda + gk);
                    float4 g2 = *(const float4*)(A2 + (size_t)(bm + r)*lda + gk);
                    pa[ch].x = u.x / (1.f + __expf(-u.x)) * g2.x;
                    pa[ch].y = u.y / (1.f + __expf(-u.y)) * g2.y;
                    pa[ch].z = u.z / (1.f + __expf(-u.z)) * g2.z;
                    pa[ch].w = u.w / (1.f + __expf(-u.w)) * g2.w;
                }
            } else pa[ch] = make_float4(0.f, 0.f, 0.f, 0.f);
        }
    };
    auto ldgB = [&](int t) {
        int k0 = t * 32;
#pragma unroll
        for (int ch = 0; ch < BIT; ch++) {
            int idx = tid + ch*NTH;
            int n = idx >> 3, kq = (idx & 7) * 4;
            int gn = bn + n, gk = k0 + kq;
            pb[ch] = (gn < N && gk < Kd) ? *(const float4*)(W + (size_t)gn*ldw + gk)
                                         : make_float4(0.f, 0.f, 0.f, 0.f);
        }
    };
    auto sts = [&](int stage) {
        float* As = sm + stage*STGF;
        float* Bs = As + ASZ;
#pragma unroll
        for (int ch = 0; ch < AIT; ch++) {
            int idx = tid + ch*NTH;
            int r = idx >> 3, kq = (idx & 7) * 4;
            int mb = r >> 4, rr = r & 15;
            int kb = kq >> 3, kk0 = kq & 7;
            int slot = ((rr >> 3) & 1) + ((kk0 >> 2) << 1);
            int lb = (rr & 7) * 4;
            float* dst = As + (mb*32)*20 + kb*4 + slot;
            dst[(lb+0)*20] = to_tf32(pa[ch].x);
            dst[(lb+1)*20] = to_tf32(pa[ch].y);
            dst[(lb+2)*20] = to_tf32(pa[ch].z);
            dst[(lb+3)*20] = to_tf32(pa[ch].w);
        }
#pragma unroll
        for (int ch = 0; ch < BIT; ch++) {
            int idx = tid + ch*NTH;
            int n = idx >> 3, kq = (idx & 7) * 4;
            int nb = n >> 3, gg = n & 7;
            int kb = kq >> 3, kk0 = kq & 7;
            int sl = kk0 >> 2;
            float* dst = Bs + (nb*32 + gg*4)*14 + kb*2 + sl;
            dst[0*14] = to_tf32(pb[ch].x);
            dst[1*14] = to_tf32(pb[ch].y);
            dst[2*14] = to_tf32(pb[ch].z);
            dst[3*14] = to_tf32(pb[ch].w);
        }
    };

    ldgA(0); ldgB(0);
    sts(0);
    __syncthreads();
    if (T > 1) { ldgA(1); ldgB(1); }

    for (int t = 0; t < T; t++) {
        if (t + 1 < T) sts((t + 1) & 1);
        if (t + 2 < T) { ldgA(t + 2); ldgB(t + 2); }
        const float* As = sm + (t & 1)*STGF;
        const float* Bs = As + ASZ;
#pragma unroll
        for (int kb = 0; kb < 4; kb++) {
            uint32_t af[MI][4];
#pragma unroll
            for (int i = 0; i < MI; i++) {
                float4 v = *(const float4*)(As + ((mb0 + i)*32 + lane)*20 + kb*4);
                af[i][0] = __float_as_uint(v.x);
                af[i][1] = __float_as_uint(v.y);
                af[i][2] = __float_as_uint(v.z);
                af[i][3] = __float_as_uint(v.w);
            }
            uint32_t bf[NI][2];
#pragma unroll
            for (int n = 0; n < NI; n++) {
                float2 v = *(const float2*)(Bs + ((nb0 + n)*32 + lane)*14 + kb*2);
                bf[n][0] = __float_as_uint(v.x);
                bf[n][1] = __float_as_uint(v.y);
            }
#pragma unroll
            for (int i = 0; i < MI; i++)
#pragma unroll
                for (int n = 0; n < NI; n++)
                    mma_tf32(acc[i][n], af[i], bf[n]);
        }
        __syncthreads();
    }

    const int g = lane >> 2, tg = lane & 3;
#pragma unroll
    for (int i = 0; i < MI; i++) {
        int r0 = bm + (mb0 + i)*16 + g;
        int r1 = r0 + 8;
#pragma unroll
        for (int n = 0; n < NI; n++) {
            int gn = bn + (nb0 + n)*8 + tg*2;
            if (gn < N) {
                float b0 = 0.f, b1 = 0.f;
                if (bias) { b0 = bias[gn]; b1 = bias[gn+1]; }
                float v0 = acc[i][n][0] + b0, v1 = acc[i][n][1] + b1;
                float v2 = acc[i][n][2] + b0, v3 = acc[i][n][3] + b1;
                if (addend) {
                    float2 a0 = *(const float2*)(addend + (size_t)r0*ldad + gn);
                    float2 a1 = *(const float2*)(addend + (size_t)r1*ldad + gn);
                    v0 += a0.x; v1 += a0.y; v2 += a1.x; v3 += a1.y;
                }
                *(float2*)(C + (size_t)r0*ldc + gn) = make_float2(v0, v1);
                *(float2*)(C + (size_t)r1*ldc + gn) = make_float2(v2, v3);
            }
        }
    }
}

// ---------------- cascade self-attn ----------------
__global__ void casc_attn_kernel() {
    __shared__ float ks[KK][DH+1];
    __shared__ float vs[KK][DH+1];
    int bh = blockIdx.x;
    int b = bh / NHH, nh = bh % NHH;
    int t = threadIdx.x;
    const float* base = g_qkv + ((size_t)(b*KK + t)) * (3*HH);
#pragma unroll
    for (int dd = 0; dd < DH; dd++) {
        ks[t][dd] = base[HH   + nh*DH + dd];
        vs[t][dd] = base[2*HH + nh*DH + dd];
    }
    __syncthreads();
    float q[DH];
#pragma unroll
    for (int dd = 0; dd < DH; dd++) q[dd] = base[nh*DH + dd];

    const float scale = 0.125f;
    float sc[KK];
    float mx = -1e30f;
    for (int j = 0; j <= t; j++) {
        float s = 0.f;
#pragma unroll
        for (int dd = 0; dd < DH; dd++) s += q[dd] * ks[j][dd];
        s *= scale;
        sc[j] = s;
        mx = fmaxf(mx, s);
    }
    float sum = 0.f;
    for (int j = 0; j <= t; j++) {
        float e = expf(sc[j] - mx);
        sc[j] = e;
        sum += e;
    }
    float inv = 1.0f / sum;
    float* o = g_attn + ((size_t)(b*KK + t)) * HH + nh*DH;
#pragma unroll 4
    for (int dd = 0; dd < DH; dd++) {
        float acc = 0.f;
        for (int j = 0; j <= t; j++) acc += sc[j] * vs[j][dd];
        o[dd] = acc * inv;
    }
}

// ---------------- decoder cross-attn (S split over blockIdx.z) ------------
__global__ void dec_attn_kernel() {
    __shared__ float ks[KK][DH+1];
    __shared__ float vs[KK][DH+1];
    __shared__ float qs[8][DH];
    __shared__ float probs[8][KK];
    int nh = blockIdx.x, b = blockIdx.y, z = blockIdx.z;
    int tid = threadIdx.x;
    for (int i = tid; i < KK*DH; i += 256) {
        int c = i / DH, dd = i % DH;
        const float* kvrow = g_kv + ((size_t)(b*KK + c)) * (2*HH);
        ks[c][dd] = kvrow[nh*DH + dd];
        vs[c][dd] = kvrow[HH + nh*DH + dd];
    }
    __syncthreads();
    int w = tid >> 5, lane = tid & 31;
    const float scale = 0.125f;
    const int s0b = z * (SS/8), s1b = s0b + (SS/8);
    for (int s = s0b + w; s < s1b; s += 8) {
        int nallow = min(KK, s/32 + 2);
        const float* qrow = g_q + ((size_t)b*SS + s) * HH + nh*DH;
        qs[w][lane]      = qrow[lane];
        qs[w][lane + 32] = qrow[lane + 32];
        __syncwarp();
        float s0 = -INFINITY, s1 = -INFINITY;
        if (lane < nallow) {
            float acc = 0.f;
#pragma unroll
            for (int dd = 0; dd < DH; dd++) acc += qs[w][dd] * ks[lane][dd];
            s0 = acc * scale;
        }
        if (lane + 32 < nallow) {
            float acc = 0.f;
#pragma unroll
            for (int dd = 0; dd < DH; dd++) acc += qs[w][dd] * ks[lane + 32][dd];
            s1 = acc * scale;
        }
        float mx = fmaxf(s0, s1);
#pragma unroll
        for (int ofs = 16; ofs > 0; ofs >>= 1)
            mx = fmaxf(mx, __shfl_xor_sync(0xffffffffu, mx, ofs));
        float e0 = expf(s0 - mx);
        float e1 = expf(s1 - mx);
        float sum = e0 + e1;
#pragma unroll
        for (int ofs = 16; ofs > 0; ofs >>= 1)
            sum += __shfl_xor_sync(0xffffffffu, sum, ofs);
        float inv = 1.0f / sum;
        probs[w][lane]      = e0 * inv;
        probs[w][lane + 32] = e1 * inv;
        __syncwarp();
        float* orow = g_dec + ((size_t)b*SS + s) * HH + nh*DH;
#pragma unroll
        for (int half = 0; half < 2; half++) {
            int dd = lane + half*32;
            float acc = 0.f;
            for (int j = 0; j < nallow; j++) acc += probs[w][j] * vs[j][dd];
            orow[dd] = acc;
        }
        __syncwarp();
    }
}

// ---------------- host ----------------
static float* symaddr(const void* sym) {
    void* p = nullptr;
    cudaGetSymbolAddress(&p, sym);
    return (float*)p;
}

#define SMEM_D ((128*40 + 256*56) * 2 * 4)   // 155648
#define SMEM_C ((64*40  + 128*56) * 2 * 4)   // 77824

extern "C" void kernel_launch(void* const* d_in, const int* in_sizes, int n_in,
                              void* d_out, int out_size) {
    const float* token       = (const float*)d_in[0];
    const float* chunk_repr  = (const float*)d_in[1];
    const float* cw          = (const float*)d_in[2];
    const float* casc_norm1  = (const float*)d_in[3];
    const float* casc_qkv    = (const float*)d_in[4];
    const float* casc_o      = (const float*)d_in[5];
    const float* casc_norm2  = (const float*)d_in[6];
    const float* casc_w1     = (const float*)d_in[7];
    const float* casc_w2     = (const float*)d_in[8];
    const float* casc_w3     = (const float*)d_in[9];
    const float* dec_in_w    = (const float*)d_in[10];
    const float* dec_in_b    = (const float*)d_in[11];
    const float* dec_out_w   = (const float*)d_in[12];
    const float* dec_out_b   = (const float*)d_in[13];
    const float* dec_norm_w  = (const float*)d_in[14];
    const float* dec_ffn_nw  = (const float*)d_in[15];
    const float* dec_w1      = (const float*)d_in[16];
    const float* dec_w2      = (const float*)d_in[17];
    const float* dec_w3      = (const float*)d_in[18];
    float* out = (float*)d_out;

    float* px    = symaddr(g_x);
    float* ph    = symaddr(g_h);
    float* pqkv  = symaddr(g_qkv);
    float* pattn = symaddr(g_attn);
    float* pff13 = symaddr(g_ff13);
    float* pproc = symaddr(g_proc);
    float* pq    = symaddr(g_q);
    float* pkv   = symaddr(g_kv);
    float* pdec  = symaddr(g_dec);
    float* py    = symaddr(g_y);
    float* pyn   = symaddr(g_yn);
    float* pu13  = symaddr(g_u13);
    float* pw13  = symaddr(g_w13);
    float* pw2p  = symaddr(g_w2pad);
    float* pdw13 = symaddr(g_dw13);
    float* pdw2p = symaddr(g_dw2pad);

    cudaFuncSetAttribute((const void*)mgemm<128,256,2,8>,
                         cudaFuncAttributeMaxDynamicSharedMemorySize, SMEM_D);
    cudaFuncSetAttribute((const void*)mgemm<64,128,1,16>,
                         cudaFuncAttributeMaxDynamicSharedMemorySize, SMEM_C);

    // decoder-shape GEMM (M multiple of 128)
    auto gemmD = [&](const float* A, const float* A2, int lda,
                     const float* W, int ldw,
                     const float* bias, const float* addend, int ldad,
                     float* C, int ldc, int M, int N, int Kd) {
        dim3 grid((N + 255)/256, M/128);
        mgemm<128,256,2,8><<<grid, NTH, SMEM_D>>>(A, A2, lda, W, ldw, bias, addend, ldad,
                                                  C, ldc, M, N, Kd);
    };
    // cascade-shape GEMM (M multiple of 64)
    auto gemmC = [&](const float* A, const float* A2, int lda,
                     const float* W, int ldw,
                     const float* bias, const float* addend, int ldad,
                     float* C, int ldc, int M, int N, int Kd) {
        dim3 grid((N + 127)/128, M/64);
        mgemm<64,128,1,16><<<grid, NTH, SMEM_C>>>(A, A2, lda, W, ldw, bias, addend, ldad,
                                                  C, ldc, M, N, Kd);
    };

    // --- weight re-layout (concat/pad only) ---
    for (int l = 0; l < LL; l++) {
        buildw13_kernel<<<FF2, 256>>>(casc_w1 + (size_t)l*FFD*HH,
                                      casc_w3 + (size_t)l*FFD*HH,
                                      pw13 + (size_t)l*FF2*HH);
        padw_kernel<<<HH, 256>>>(casc_w2 + (size_t)l*HH*FFD,
                                 pw2p + (size_t)l*HH*FFP);
    }
    buildw13_kernel<<<FF2, 256>>>(dec_w1, dec_w3, pdw13);
    padw_kernel<<<HH, 256>>>(dec_w2, pdw2p);

    // --- cascade ---
    rank_kernel<<<BB, KK>>>(cw);
    scatter_kernel<<<BB*KK, 256>>>(chunk_repr);

    const int MC = BB*KK;          // 256
    for (int l = 0; l < LL; l++) {
        rms_kernel<<<MC, 256>>>(px, casc_norm1 + l*HH, ph);
        gemmC(ph, nullptr, HH, casc_qkv + (size_t)l*3*HH*HH, HH,
              nullptr, nullptr, 0, pqkv, 3*HH, MC, 3*HH, HH);
        casc_attn_kernel<<<BB*NHH, KK>>>();
        gemmC(pattn, nullptr, HH, casc_o + (size_t)l*HH*HH, HH,
              nullptr, px, HH, px, HH, MC, HH, HH);
        rms_kernel<<<MC, 256>>>(px, casc_norm2 + l*HH, ph);
        gemmC(ph, nullptr, HH, pw13 + (size_t)l*FF2*HH, HH,
              nullptr, nullptr, 0, pff13, FF2, MC, FF2, HH);
        gemmC(pff13, pff13 + FFP, FF2, pw2p + (size_t)l*HH*FFP, FFP,
              nullptr, px, HH, px, HH, MC, HH, FFP);
    }
    gather_kernel<<<BB*KK, 256>>>();

    // --- decoder ---
    const int MT = BB*SS;          // 8192
    gemmD(token, nullptr, HH, dec_in_w, HH,
          dec_in_b, nullptr, 0, pq, HH, MT, HH, HH);
    gemmC(pproc, nullptr, HH, dec_in_w + (size_t)HH*HH, HH,
          dec_in_b + HH, nullptr, 0, pkv, 2*HH, MC, 2*HH, HH);
    dec_attn_kernel<<<dim3(NHH, BB, 8), 256>>>();
    gemmD(pdec, nullptr, HH, dec_out_w, HH,
          dec_out_b, token, HH, pyn, HH, MT, HH, HH);
    rms_kernel<<<MT, 256>>>(pyn, dec_norm_w, py);
    rms_kernel<<<MT, 256>>>(py, dec_ffn_nw, pyn);
    gemmD(pyn, nullptr, HH, pdw13, HH,
          nullptr, nullptr, 0, pu13, FF2, MT, FF2, HH);
    gemmD(pu13, pu13 + FFP, FF2, pdw2p, FFP,
          nullptr, py, HH, out, HH, MT, HH, FFP);
}

// round 9
// speedup vs baseline: 3.9014x; 1.2350x over previous
#include <cuda_runtime.h>
#include <cuda_bf16.h>
#include <cuda_fp16.h>
#include <math.h>
#include <stdint.h>

#define BB 4
#define SS 2048
#define HH 1024
#define KK 64
#define NHH 16
#define DH 64
#define LL 2
#define FFD 2730
#define FFP 2736
#define FF2 (2*FFP)
#define EPSV 1e-6f

// ---------------- scratch ----------------
__device__ float g_x[BB*KK*HH];
__device__ float g_h[BB*KK*HH];
__device__ float g_qkv[BB*KK*3*HH];
__device__ float g_attn[BB*KK*HH];
__device__ float g_ff13[BB*KK*FF2];
__device__ int   g_rank[BB*KK];
__device__ float g_proc[BB*KK*HH];
__device__ float g_q[BB*SS*HH];
__device__ float g_kv[BB*KK*2*HH];
__device__ float g_dec[BB*SS*HH];
__device__ float g_y[BB*SS*HH];
__device__ float g_yn[BB*SS*HH];
__device__ float g_u13[BB*SS*FF2];

// ---------------- small kernels ----------------
__global__ void rank_kernel(const float* __restrict__ cw) {
    int b = blockIdx.x, k = threadIdx.x;
    float wk = cw[b*KK + k];
    int r = 0;
    for (int j = 0; j < KK; j++) {
        float wj = cw[b*KK + j];
        if (wj > wk || (wj == wk && j < k)) r++;
    }
    g_rank[b*KK + k] = r;
}

__global__ void scatter_kernel(const float* __restrict__ src) {
    int row = blockIdx.x;
    int b = row / KK;
    int r = g_rank[row];
    const float* s = src + (size_t)row * HH;
    float* d = g_x + ((size_t)(b*KK + r)) * HH;
    for (int i = threadIdx.x; i < HH; i += blockDim.x) d[i] = s[i];
}

__global__ void gather_kernel() {
    int row = blockIdx.x;
    int b = row / KK;
    int r = g_rank[row];
    const float* s = g_x + ((size_t)(b*KK + r)) * HH;
    float* d = g_proc + (size_t)row * HH;
    for (int i = threadIdx.x; i < HH; i += blockDim.x) d[i] = s[i];
}

__global__ void rms_kernel(const float* __restrict__ in, const float* __restrict__ w,
                           float* __restrict__ out) {
    __shared__ float red[256];
    int row = blockIdx.x;
    const float* x = in + (size_t)row * HH;
    float* o = out + (size_t)row * HH;
    int t = threadIdx.x;
    float v[4];
    float ss = 0.f;
#pragma unroll
    for (int i = 0; i < 4; i++) { v[i] = x[t + i*256]; ss += v[i]*v[i]; }
    red[t] = ss;
    __syncthreads();
    for (int ofs = 128; ofs > 0; ofs >>= 1) {
        if (t < ofs) red[t] += red[t + ofs];
        __syncthreads();
    }
    float inv = rsqrtf(red[0] * (1.0f/HH) + EPSV);
#pragma unroll
    for (int i = 0; i < 4; i++) {
        int c = t + i*256;
        o[c] = v[i] * inv * w[c];
    }
}

// ---------------- fp16 mma GEMM ----------------
// C[M,N] = op(A)@Wmap^T (+bias)(+addend)
// op(A) = A, or silu(A)*A2 when A2 != null (GLU fusion).
// Wmap: if W3==null, row gn = W[gn] (gn<N); else rows [0,FFP)->W (valid<FFD),
//       rows [FFP,2FFP)->W3 (valid<FFD). K mask: cols >= Kvalid read as 0.
// Operands converted to half (rn) at STS time; fp32 accumulate.

__device__ __forceinline__ uint32_t packh2(float x, float y) {
    __half2 h = __floats2half2_rn(x, y);
    return *reinterpret_cast<uint32_t*>(&h);
}

__device__ __forceinline__ void mma_f16(float* d, const uint32_t* a, const uint32_t* b) {
    asm volatile(
        "mma.sync.aligned.m16n8k16.row.col.f32.f16.f16.f32 "
        "{%0,%1,%2,%3}, {%4,%5,%6,%7}, {%8,%9}, {%0,%1,%2,%3};\n"
        : "+f"(d[0]), "+f"(d[1]), "+f"(d[2]), "+f"(d[3])
        : "r"(a[0]), "r"(a[1]), "r"(a[2]), "r"(a[3]), "r"(b[0]), "r"(b[1]));
}

#define NTH 512
// A group: (mb, kb2) -> 32 lanes * 16B + 16B pad = 528B. Groups: (MB/16)*2.
// B group: (nb, kb2) -> 32 lanes * 8B + 8B pad = 264B. Groups: (NB/8)*2.

template<int MB, int NB, int WR, int WC>
__global__ __launch_bounds__(NTH) void hgemm(
    const float* __restrict__ A, const float* __restrict__ A2, int lda,
    const float* __restrict__ W, const float* __restrict__ W3, int ldw, int Kvalid,
    const float* __restrict__ bias, const float* __restrict__ addend, int ldad,
    float* __restrict__ C, int ldc, int M, int N, int Kd)
{
    constexpr int MI = MB / WR / 16;
    constexpr int NI = NB / WC / 8;
    constexpr int AIT = MB / 64;
    constexpr int BIT = NB / 64;
    constexpr int ASZB = MB * 66;     // (MB/16)*2*528
    constexpr int BSZB = NB * 66;     // (NB/8)*2*264
    constexpr int STGB = ASZB + BSZB;

    extern __shared__ char smc[];
    const int tid  = threadIdx.x;
    const int lane = tid & 31;
    const int wid  = tid >> 5;
    const int wr   = wid / WC, wc = wid % WC;
    const int mb0  = wr * MI;
    const int nb0  = wc * NI;
    const int bm = blockIdx.y * MB, bn = blockIdx.x * NB;

    float acc[MI][NI][4];
#pragma unroll
    for (int i = 0; i < MI; i++)
#pragma unroll
        for (int n = 0; n < NI; n++)
#pragma unroll
            for (int q = 0; q < 4; q++) acc[i][n][q] = 0.f;

    float4 pa[AIT], pb[BIT];
    const int T = (Kd + 31) / 32;

    auto ldgA = [&](int t) {
        int k0 = t * 32;
#pragma unroll
        for (int ch = 0; ch < AIT; ch++) {
            int idx = tid + ch*NTH;
            int r = idx >> 3, kq = (idx & 7) * 4;
            int gk = k0 + kq;
            if (gk < Kd) {
                if (A2 == nullptr) {
                    pa[ch] = *(const float4*)(A + (size_t)(bm + r)*lda + gk);
                } else {
                    float4 u = *(const float4*)(A  + (size_t)(bm + r)*lda + gk);
                    float4 g2 = *(const float4*)(A2 + (size_t)(bm + r)*lda + gk);
                    pa[ch].x = u.x / (1.f + __expf(-u.x)) * g2.x;
                    pa[ch].y = u.y / (1.f + __expf(-u.y)) * g2.y;
                    pa[ch].z = u.z / (1.f + __expf(-u.z)) * g2.z;
                    pa[ch].w = u.w / (1.f + __expf(-u.w)) * g2.w;
                }
            } else pa[ch] = make_float4(0.f, 0.f, 0.f, 0.f);
        }
    };
    auto ldgB = [&](int t) {
        int k0 = t * 32;
#pragma unroll
        for (int ch = 0; ch < BIT; ch++) {
            int idx = tid + ch*NTH;
            int n = idx >> 3, kq = (idx & 7) * 4;
            int gn = bn + n, gk = k0 + kq;
            const float* rowp = nullptr;
            if (W3 == nullptr) {
                if (gn < N) rowp = W + (size_t)gn*ldw;
            } else {
                if (gn < FFP) {
                    if (gn < FFD) rowp = W + (size_t)gn*ldw;
                } else {
                    int g2 = gn - FFP;
                    if (g2 < FFD) rowp = W3 + (size_t)g2*ldw;
                }
            }
            float4 v = make_float4(0.f, 0.f, 0.f, 0.f);
            if (rowp) {
                if (gk + 1 < Kvalid) {
                    float2 p = *(const float2*)(rowp + gk);
                    v.x = p.x; v.y = p.y;
                }
                if (gk + 3 < Kvalid) {
                    float2 p = *(const float2*)(rowp + gk + 2);
                    v.z = p.x; v.w = p.y;
                }
            }
            pb[ch] = v;
        }
    };
    auto sts = [&](int stage) {
        char* As = smc + stage*STGB;
        char* Bs = As + ASZB;
#pragma unroll
        for (int ch = 0; ch < AIT; ch++) {
            int idx = tid + ch*NTH;
            int r = idx >> 3, kq = (idx & 7) * 4;
            int kb2 = kq >> 4, kloc = kq & 15;
            int mb = r >> 4, rr = r & 15;
            int lane0 = (rr & 7)*4 + ((kloc & 7) >> 1);
            int slot = (rr >> 3) + ((kloc >> 3) << 1);
            uint32_t* base = (uint32_t*)(As + (mb*2 + kb2)*528);
            base[lane0*4 + slot]     = packh2(pa[ch].x, pa[ch].y);
            base[(lane0+1)*4 + slot] = packh2(pa[ch].z, pa[ch].w);
        }
#pragma unroll
        for (int ch = 0; ch < BIT; ch++) {
            int idx = tid + ch*NTH;
            int n = idx >> 3, kq = (idx & 7) * 4;
            int kb2 = kq >> 4, kloc = kq & 15;
            int nb = n >> 3, cc = n & 7;
            int lane0 = cc*4 + ((kloc & 7) >> 1);
            int slot = kloc >> 3;
            uint32_t* base = (uint32_t*)(Bs + (nb*2 + kb2)*264);
            base[lane0*2 + slot]     = packh2(pb[ch].x, pb[ch].y);
            base[(lane0+1)*2 + slot] = packh2(pb[ch].z, pb[ch].w);
        }
    };

    ldgA(0); ldgB(0);
    sts(0);
    __syncthreads();
    if (T > 1) { ldgA(1); ldgB(1); }

    for (int t = 0; t < T; t++) {
        if (t + 1 < T) sts((t + 1) & 1);
        if (t + 2 < T) { ldgA(t + 2); ldgB(t + 2); }
        const char* As = smc + (t & 1)*STGB;
        const char* Bs = As + ASZB;
#pragma unroll
        for (int kb2 = 0; kb2 < 2; kb2++) {
            uint32_t af[MI][4];
#pragma unroll
            for (int i = 0; i < MI; i++) {
                uint4 v = *(const uint4*)(As + ((mb0 + i)*2 + kb2)*528 + lane*16);
                af[i][0] = v.x; af[i][1] = v.y; af[i][2] = v.z; af[i][3] = v.w;
            }
            uint32_t bf[NI][2];
#pragma unroll
            for (int n = 0; n < NI; n++) {
                uint2 v = *(const uint2*)(Bs + ((nb0 + n)*2 + kb2)*264 + lane*8);
                bf[n][0] = v.x; bf[n][1] = v.y;
            }
#pragma unroll
            for (int i = 0; i < MI; i++)
#pragma unroll
                for (int n = 0; n < NI; n++)
                    mma_f16(acc[i][n], af[i], bf[n]);
        }
        __syncthreads();
    }

    const int g = lane >> 2, tg = lane & 3;
#pragma unroll
    for (int i = 0; i < MI; i++) {
        int r0 = bm + (mb0 + i)*16 + g;
        int r1 = r0 + 8;
#pragma unroll
        for (int n = 0; n < NI; n++) {
            int gn = bn + (nb0 + n)*8 + tg*2;
            if (gn < N) {
                float b0 = 0.f, b1 = 0.f;
                if (bias) { b0 = bias[gn]; b1 = bias[gn+1]; }
                float v0 = acc[i][n][0] + b0, v1 = acc[i][n][1] + b1;
                float v2 = acc[i][n][2] + b0, v3 = acc[i][n][3] + b1;
                if (addend) {
                    float2 a0 = *(const float2*)(addend + (size_t)r0*ldad + gn);
                    float2 a1 = *(const float2*)(addend + (size_t)r1*ldad + gn);
                    v0 += a0.x; v1 += a0.y; v2 += a1.x; v3 += a1.y;
                }
                *(float2*)(C + (size_t)r0*ldc + gn) = make_float2(v0, v1);
                *(float2*)(C + (size_t)r1*ldc + gn) = make_float2(v2, v3);
            }
        }
    }
}

// ---------------- cascade self-attn ----------------
__global__ void casc_attn_kernel() {
    __shared__ float ks[KK][DH+1];
    __shared__ float vs[KK][DH+1];
    int bh = blockIdx.x;
    int b = bh / NHH, nh = bh % NHH;
    int t = threadIdx.x;
    const float* base = g_qkv + ((size_t)(b*KK + t)) * (3*HH);
#pragma unroll
    for (int dd = 0; dd < DH; dd++) {
        ks[t][dd] = base[HH   + nh*DH + dd];
        vs[t][dd] = base[2*HH + nh*DH + dd];
    }
    __syncthreads();
    float q[DH];
#pragma unroll
    for (int dd = 0; dd < DH; dd++) q[dd] = base[nh*DH + dd];

    const float scale = 0.125f;
    float sc[KK];
    float mx = -1e30f;
    for (int j = 0; j <= t; j++) {
        float s = 0.f;
#pragma unroll
        for (int dd = 0; dd < DH; dd++) s += q[dd] * ks[j][dd];
        s *= scale;
        sc[j] = s;
        mx = fmaxf(mx, s);
    }
    float sum = 0.f;
    for (int j = 0; j <= t; j++) {
        float e = expf(sc[j] - mx);
        sc[j] = e;
        sum += e;
    }
    float inv = 1.0f / sum;
    float* o = g_attn + ((size_t)(b*KK + t)) * HH + nh*DH;
#pragma unroll 4
    for (int dd = 0; dd < DH; dd++) {
        float acc = 0.f;
        for (int j = 0; j <= t; j++) acc += sc[j] * vs[j][dd];
        o[dd] = acc * inv;
    }
}

// ---------------- decoder cross-attn (S split over blockIdx.z) ------------
__global__ void dec_attn_kernel() {
    __shared__ float ks[KK][DH+1];
    __shared__ float vs[KK][DH+1];
    __shared__ float qs[8][DH];
    __shared__ float probs[8][KK];
    int nh = blockIdx.x, b = blockIdx.y, z = blockIdx.z;
    int tid = threadIdx.x;
    for (int i = tid; i < KK*DH; i += 256) {
        int c = i / DH, dd = i % DH;
        const float* kvrow = g_kv + ((size_t)(b*KK + c)) * (2*HH);
        ks[c][dd] = kvrow[nh*DH + dd];
        vs[c][dd] = kvrow[HH + nh*DH + dd];
    }
    __syncthreads();
    int w = tid >> 5, lane = tid & 31;
    const float scale = 0.125f;
    const int s0b = z * (SS/8), s1b = s0b + (SS/8);
    for (int s = s0b + w; s < s1b; s += 8) {
        int nallow = min(KK, s/32 + 2);
        const float* qrow = g_q + ((size_t)b*SS + s) * HH + nh*DH;
        qs[w][lane]      = qrow[lane];
        qs[w][lane + 32] = qrow[lane + 32];
        __syncwarp();
        float s0 = -INFINITY, s1 = -INFINITY;
        if (lane < nallow) {
            float acc = 0.f;
#pragma unroll
            for (int dd = 0; dd < DH; dd++) acc += qs[w][dd] * ks[lane][dd];
            s0 = acc * scale;
        }
        if (lane + 32 < nallow) {
            float acc = 0.f;
#pragma unroll
            for (int dd = 0; dd < DH; dd++) acc += qs[w][dd] * ks[lane + 32][dd];
            s1 = acc * scale;
        }
        float mx = fmaxf(s0, s1);
#pragma unroll
        for (int ofs = 16; ofs > 0; ofs >>= 1)
            mx = fmaxf(mx, __shfl_xor_sync(0xffffffffu, mx, ofs));
        float e0 = expf(s0 - mx);
        float e1 = expf(s1 - mx);
        float sum = e0 + e1;
#pragma unroll
        for (int ofs = 16; ofs > 0; ofs >>= 1)
            sum += __shfl_xor_sync(0xffffffffu, sum, ofs);
        float inv = 1.0f / sum;
        probs[w][lane]      = e0 * inv;
        probs[w][lane + 32] = e1 * inv;
        __syncwarp();
        float* orow = g_dec + ((size_t)b*SS + s) * HH + nh*DH;
#pragma unroll
        for (int half = 0; half < 2; half++) {
            int dd = lane + half*32;
            float acc = 0.f;
            for (int j = 0; j < nallow; j++) acc += probs[w][j] * vs[j][dd];
            orow[dd] = acc;
        }
        __syncwarp();
    }
}

// ---------------- host ----------------
static float* symaddr(const void* sym) {
    void* p = nullptr;
    cudaGetSymbolAddress(&p, sym);
    return (float*)p;
}

#define SMEM_D (2*(128 + 256)*66)   // 50688
#define SMEM_C (2*(64  + 128)*66)   // 25344

extern "C" void kernel_launch(void* const* d_in, const int* in_sizes, int n_in,
                              void* d_out, int out_size) {
    const float* token       = (const float*)d_in[0];
    const float* chunk_repr  = (const float*)d_in[1];
    const float* cw          = (const float*)d_in[2];
    const float* casc_norm1  = (const float*)d_in[3];
    const float* casc_qkv    = (const float*)d_in[4];
    const float* casc_o      = (const float*)d_in[5];
    const float* casc_norm2  = (const float*)d_in[6];
    const float* casc_w1     = (const float*)d_in[7];
    const float* casc_w2     = (const float*)d_in[8];
    const float* casc_w3     = (const float*)d_in[9];
    const float* dec_in_w    = (const float*)d_in[10];
    const float* dec_in_b    = (const float*)d_in[11];
    const float* dec_out_w   = (const float*)d_in[12];
    const float* dec_out_b   = (const float*)d_in[13];
    const float* dec_norm_w  = (const float*)d_in[14];
    const float* dec_ffn_nw  = (const float*)d_in[15];
    const float* dec_w1      = (const float*)d_in[16];
    const float* dec_w2      = (const float*)d_in[17];
    const float* dec_w3      = (const float*)d_in[18];
    float* out = (float*)d_out;

    float* px    = symaddr(g_x);
    float* ph    = symaddr(g_h);
    float* pqkv  = symaddr(g_qkv);
    float* pattn = symaddr(g_attn);
    float* pff13 = symaddr(g_ff13);
    float* pproc = symaddr(g_proc);
    float* pq    = symaddr(g_q);
    float* pkv   = symaddr(g_kv);
    float* pdec  = symaddr(g_dec);
    float* py    = symaddr(g_y);
    float* pyn   = symaddr(g_yn);
    float* pu13  = symaddr(g_u13);

    cudaFuncSetAttribute((const void*)hgemm<128,256,2,8>,
                         cudaFuncAttributeMaxDynamicSharedMemorySize, SMEM_D);
    cudaFuncSetAttribute((const void*)hgemm<64,128,2,8>,
                         cudaFuncAttributeMaxDynamicSharedMemorySize, SMEM_C);

    auto gemmD = [&](const float* A, const float* A2, int lda,
                     const float* W, const float* W3, int ldw, int Kvalid,
                     const float* bias, const float* addend, int ldad,
                     float* C, int ldc, int M, int N, int Kd) {
        dim3 grid((N + 255)/256, M/128);
        hgemm<128,256,2,8><<<grid, NTH, SMEM_D>>>(A, A2, lda, W, W3, ldw, Kvalid,
                                                  bias, addend, ldad, C, ldc, M, N, Kd);
    };
    auto gemmC = [&](const float* A, const float* A2, int lda,
                     const float* W, const float* W3, int ldw, int Kvalid,
                     const float* bias, const float* addend, int ldad,
                     float* C, int ldc, int M, int N, int Kd) {
        dim3 grid((N + 127)/128, M/64);
        hgemm<64,128,2,8><<<grid, NTH, SMEM_C>>>(A, A2, lda, W, W3, ldw, Kvalid,
                                                 bias, addend, ldad, C, ldc, M, N, Kd);
    };

    // --- cascade ---
    rank_kernel<<<BB, KK>>>(cw);
    scatter_kernel<<<BB*KK, 256>>>(chunk_repr);

    const int MC = BB*KK;          // 256
    for (int l = 0; l < LL; l++) {
        rms_kernel<<<MC, 256>>>(px, casc_norm1 + l*HH, ph);
        gemmC(ph, nullptr, HH, casc_qkv + (size_t)l*3*HH*HH, nullptr, HH, HH,
              nullptr, nullptr, 0, pqkv, 3*HH, MC, 3*HH, HH);
        casc_attn_kernel<<<BB*NHH, KK>>>();
        gemmC(pattn, nullptr, HH, casc_o + (size_t)l*HH*HH, nullptr, HH, HH,
              nullptr, px, HH, px, HH, MC, HH, HH);
        rms_kernel<<<MC, 256>>>(px, casc_norm2 + l*HH, ph);
        gemmC(ph, nullptr, HH, casc_w1 + (size_t)l*FFD*HH, casc_w3 + (size_t)l*FFD*HH,
              HH, HH, nullptr, nullptr, 0, pff13, FF2, MC, FF2, HH);
        gemmC(pff13, pff13 + FFP, FF2, casc_w2 + (size_t)l*HH*FFD, nullptr, FFD, FFD,
              nullptr, px, HH, px, HH, MC, HH, FFP);
    }
    gather_kernel<<<BB*KK, 256>>>();

    // --- decoder ---
    const int MT = BB*SS;          // 8192
    gemmD(token, nullptr, HH, dec_in_w, nullptr, HH, HH,
          dec_in_b, nullptr, 0, pq, HH, MT, HH, HH);
    gemmC(pproc, nullptr, HH, dec_in_w + (size_t)HH*HH, nullptr, HH, HH,
          dec_in_b + HH, nullptr, 0, pkv, 2*HH, MC, 2*HH, HH);
    dec_attn_kernel<<<dim3(NHH, BB, 8), 256>>>();
    gemmD(pdec, nullptr, HH, dec_out_w, nullptr, HH, HH,
          dec_out_b, token, HH, pyn, HH, MT, HH, HH);
    rms_kernel<<<MT, 256>>>(pyn, dec_norm_w, py);
    rms_kernel<<<MT, 256>>>(py, dec_ffn_nw, pyn);
    gemmD(pyn, nullptr, HH, dec_w1, dec_w3, HH, HH,
          nullptr, nullptr, 0, pu13, FF2, MT, FF2, HH);
    gemmD(pu13, pu13 + FFP, FF2, dec_w2, nullptr, FFD, FFD,
          nullptr, py, HH, out, HH, MT, HH, FFP);
}

// round 10
// speedup vs baseline: 6.7033x; 1.7182x over previous
#include <cuda_runtime.h>
#include <cuda_bf16.h>
#include <cuda_fp16.h>
#include <math.h>
#include <stdint.h>

#define BB 4
#define SS 2048
#define HH 1024
#define KK 64
#define NHH 16
#define DH 64
#define LL 2
#define FFD 2730
#define FFP 2736
#define FF2 (2*FFP)     // 5472
#define FFH 2752        // FFP padded to multiple of 64
#define EPSV 1e-6f

// ---------------- scratch (fp32) ----------------
__device__ float g_x[BB*KK*HH];
__device__ float g_qkv[BB*KK*3*HH];
__device__ float g_ff13[BB*KK*FF2];
__device__ int   g_rank[BB*KK];
__device__ float g_q[BB*SS*HH];
__device__ float g_kv[BB*KK*2*HH];
__device__ float g_y[BB*SS*HH];
__device__ float g_yn[BB*SS*HH];
__device__ float g_u13[BB*SS*FF2];

// ---------------- scratch (half activations) ----------------
__device__ __half h_tok[BB*SS*HH];
__device__ __half h_h[BB*KK*HH];
__device__ __half h_attn[BB*KK*HH];
__device__ __half h_proc[BB*KK*HH];
__device__ __half h_ff[BB*KK*FFH];
__device__ __half h_dec[BB*SS*HH];
__device__ __half h_yn[BB*SS*HH];
__device__ __half h_u[BB*SS*FFH];

// ---------------- half weights ----------------
__device__ __half wh_qkv[LL*3*HH*HH];
__device__ __half wh_o[LL*HH*HH];
__device__ __half wh_w13[LL*FF2*HH];
__device__ __half wh_w2[LL*HH*FFH];
__device__ __half wh_din[3*HH*HH];
__device__ __half wh_dout[HH*HH];
__device__ __half wh_dw13[FF2*HH];
__device__ __half wh_dw2[HH*FFH];

// ---------------- small kernels ----------------
__global__ void rank_kernel(const float* __restrict__ cw) {
    int b = blockIdx.x, k = threadIdx.x;
    float wk = cw[b*KK + k];
    int r = 0;
    for (int j = 0; j < KK; j++) {
        float wj = cw[b*KK + j];
        if (wj > wk || (wj == wk && j < k)) r++;
    }
    g_rank[b*KK + k] = r;
}

__global__ void scatter_kernel(const float* __restrict__ src) {
    int row = blockIdx.x;
    int b = row / KK;
    int r = g_rank[row];
    const float* s = src + (size_t)row * HH;
    float* d = g_x + ((size_t)(b*KK + r)) * HH;
    for (int i = threadIdx.x; i < HH; i += blockDim.x) d[i] = s[i];
}

__global__ void gather_kernel() {
    int row = blockIdx.x;
    int b = row / KK;
    int r = g_rank[row];
    const float* s = g_x + ((size_t)(b*KK + r)) * HH;
    __half* d = h_proc + (size_t)row * HH;
    for (int i = threadIdx.x; i < HH; i += blockDim.x) d[i] = __float2half(s[i]);
}

__global__ void halfcopy_kernel(const float* __restrict__ src, __half* __restrict__ dst, int n) {
    for (int i = blockIdx.x * blockDim.x + threadIdx.x; i < n; i += gridDim.x * blockDim.x)
        dst[i] = __float2half(src[i]);
}

// [FF2][HH] = concat(w1[FFD], 0, w3[FFD], 0), half
__global__ void w13half_kernel(const float* __restrict__ w1, const float* __restrict__ w3,
                               __half* __restrict__ dst) {
    int row = blockIdx.x;
    const float* src = nullptr;
    if (row < FFD) src = w1 + (size_t)row * HH;
    else if (row >= FFP && row < FFP + FFD) src = w3 + (size_t)(row - FFP) * HH;
    __half* d = dst + (size_t)row * HH;
    for (int i = threadIdx.x; i < HH; i += blockDim.x)
        d[i] = src ? __float2half(src[i]) : __half(0.f);
}

// [HH][FFD] -> [HH][FFH] half, zero pad
__global__ void w2half_kernel(const float* __restrict__ src, __half* __restrict__ dst) {
    int row = blockIdx.x;
    for (int i = threadIdx.x; i < FFH; i += blockDim.x)
        dst[(size_t)row*FFH + i] = (i < FFD) ? __float2half(src[(size_t)row*FFD + i]) : __half(0.f);
}

template<typename TOUT>
__global__ void rms_kernel(const float* __restrict__ in, const float* __restrict__ w,
                           TOUT* __restrict__ out) {
    __shared__ float red[256];
    int row = blockIdx.x;
    const float* x = in + (size_t)row * HH;
    TOUT* o = out + (size_t)row * HH;
    int t = threadIdx.x;
    float v[4];
    float ss = 0.f;
#pragma unroll
    for (int i = 0; i < 4; i++) { v[i] = x[t + i*256]; ss += v[i]*v[i]; }
    red[t] = ss;
    __syncthreads();
    for (int ofs = 128; ofs > 0; ofs >>= 1) {
        if (t < ofs) red[t] += red[t + ofs];
        __syncthreads();
    }
    float inv = rsqrtf(red[0] * (1.0f/HH) + EPSV);
#pragma unroll
    for (int i = 0; i < 4; i++) {
        int c = t + i*256;
        o[c] = (TOUT)(v[i] * inv * w[c]);
    }
}

// u [rows][FF2] fp32 -> out [rows][FFH] half: silu(u[:,c])*u[:,FFP+c], pad 0
__global__ void glu_kernel(const float* __restrict__ u, __half* __restrict__ out, int rows) {
    int total = rows * FFH;
    for (int i = blockIdx.x * blockDim.x + threadIdx.x; i < total; i += gridDim.x * blockDim.x) {
        int m = i / FFH, c = i - m * FFH;
        float r = 0.f;
        if (c < FFP) {
            float a = u[(size_t)m*FF2 + c];
            float b = u[(size_t)m*FF2 + FFP + c];
            r = (a / (1.0f + __expf(-a))) * b;
        }
        out[(size_t)m*FFH + c] = __float2half(r);
    }
}

// ---------------- half GEMM: cp.async + SW128 + ldmatrix + HMMA ----------
__device__ __forceinline__ void cp16(uint32_t dst, const void* src, bool pred) {
    int p = pred ? 1 : 0;
    asm volatile(
        "{\n.reg .pred p;\nsetp.ne.b32 p, %2, 0;\n"
        "@p  cp.async.cg.shared.global [%0], [%1], 16;\n"
        "@!p cp.async.cg.shared.global [%0], [%1], 16, 0;\n}"
        :: "r"(dst), "l"(src), "r"(p));
}

__device__ __forceinline__ void ldsm4(uint32_t& r0, uint32_t& r1, uint32_t& r2, uint32_t& r3,
                                      uint32_t addr) {
    asm volatile("ldmatrix.sync.aligned.m8n8.x4.shared.b16 {%0,%1,%2,%3}, [%4];"
                 : "=r"(r0), "=r"(r1), "=r"(r2), "=r"(r3) : "r"(addr));
}

__device__ __forceinline__ void mma_f16(float* d, const uint32_t* a, const uint32_t* b) {
    asm volatile(
        "mma.sync.aligned.m16n8k16.row.col.f32.f16.f16.f32 "
        "{%0,%1,%2,%3}, {%4,%5,%6,%7}, {%8,%9}, {%0,%1,%2,%3};\n"
        : "+f"(d[0]), "+f"(d[1]), "+f"(d[2]), "+f"(d[3])
        : "r"(a[0]), "r"(a[1]), "r"(a[2]), "r"(a[3]), "r"(b[0]), "r"(b[1]));
}

#define NTH 512

// C[M,N] = A[M,Kd]@W[N,Kd]^T (+bias)(+addend), A/W half, C fp32.
// Requires: M % MB == 0, Kd % 64 == 0. N masked.
template<int MB, int NB, int WR, int WC>
__global__ __launch_bounds__(NTH) void hgemm(
    const __half* __restrict__ A, int lda,
    const __half* __restrict__ W, int ldw,
    const float* __restrict__ bias, const float* __restrict__ addend, int ldad,
    float* __restrict__ C, int ldc, int M, int N, int Kd)
{
    constexpr int MI  = MB / WR / 16;
    constexpr int NI  = NB / WC / 8;
    constexpr int ACH = MB * 8 / NTH;
    constexpr int BCH = NB * 8 / NTH;
    constexpr int ASZB = MB * 128;
    constexpr int BSZB = NB * 128;
    constexpr int STGB = ASZB + BSZB;

    extern __shared__ char smc[];
    const uint32_t sbase = (uint32_t)__cvta_generic_to_shared(smc);
    const int tid  = threadIdx.x;
    const int lane = tid & 31;
    const int wid  = tid >> 5;
    const int wr   = wid / WC, wc = wid % WC;
    const int mb0  = wr * MI;
    const int nb0  = wc * NI;
    const int bm = blockIdx.y * MB, bn = blockIdx.x * NB;

    float acc[MI][NI][4];
#pragma unroll
    for (int i = 0; i < MI; i++)
#pragma unroll
        for (int n = 0; n < NI; n++)
#pragma unroll
            for (int q = 0; q < 4; q++) acc[i][n][q] = 0.f;

    const int T = Kd >> 6;   // 64-half chunks

    auto fill = [&](int t) {
        int st = t - (t/3)*3;
        uint32_t ab = sbase + st*STGB;
        uint32_t bb = ab + ASZB;
        int k0 = t * 64;
#pragma unroll
        for (int ch = 0; ch < ACH; ch++) {
            int idx = tid + ch*NTH;
            int row = idx >> 3, c = idx & 7;
            uint32_t dst = ab + row*128 + ((c ^ (row & 7)) << 4);
            cp16(dst, A + (size_t)(bm + row)*lda + k0 + c*8, true);
        }
#pragma unroll
        for (int ch = 0; ch < BCH; ch++) {
            int idx = tid + ch*NTH;
            int row = idx >> 3, c = idx & 7;
            int gn = bn + row;
            bool p = gn < N;
            uint32_t dst = bb + row*128 + ((c ^ (row & 7)) << 4);
            cp16(dst, W + (size_t)(p ? gn : 0)*ldw + k0 + c*8, p);
        }
        asm volatile("cp.async.commit_group;" ::: "memory");
    };

    // lane-derived fragment addressing (SW128)
    const int mi = lane >> 3;
    const int aRowLoc = (mi & 1)*8 + (lane & 7);
    const int aCb = mi >> 1;
    const int bRowLoc = lane & 7;
    const int bBlk = mi >> 1;
    const int bCb = mi & 1;
    uint32_t aRowOff[MI], aS[MI];
#pragma unroll
    for (int i = 0; i < MI; i++) {
        int row = (mb0 + i)*16 + aRowLoc;
        aRowOff[i] = row*128;
        aS[i] = (row & 7) << 4;
    }
    uint32_t bRowOff[NI/2], bS[NI/2];
#pragma unroll
    for (int j = 0; j < NI/2; j++) {
        int nr = (nb0 + j*2 + bBlk)*8 + bRowLoc;
        bRowOff[j] = nr*128;
        bS[j] = (nr & 7) << 4;
    }

    fill(0);
    fill(1);

    for (int t = 0; t < T; t++) {
        if (t == T - 1)
            asm volatile("cp.async.wait_group 0;" ::: "memory");
        else
            asm volatile("cp.async.wait_group 1;" ::: "memory");
        __syncthreads();
        int st = t - (t/3)*3;
        uint32_t ab = sbase + st*STGB;
        uint32_t bb = ab + ASZB;
#pragma unroll
        for (int kb = 0; kb < 4; kb++) {
            uint32_t af[MI][4];
#pragma unroll
            for (int i = 0; i < MI; i++)
                ldsm4(af[i][0], af[i][1], af[i][2], af[i][3],
                      ab + aRowOff[i] + ((((kb*2 + aCb) << 4)) ^ aS[i]));
            uint32_t bf[NI][2];
#pragma unroll
            for (int j = 0; j < NI/2; j++)
                ldsm4(bf[j*2][0], bf[j*2][1], bf[j*2+1][0], bf[j*2+1][1],
                      bb + bRowOff[j] + ((((kb*2 + bCb) << 4)) ^ bS[j]));
#pragma unroll
            for (int i = 0; i < MI; i++)
#pragma unroll
                for (int n = 0; n < NI; n++)
                    mma_f16(acc[i][n], af[i], bf[n]);
        }
        if (t + 2 < T) fill(t + 2);
    }

    const int g = lane >> 2, tg = lane & 3;
#pragma unroll
    for (int i = 0; i < MI; i++) {
        int r0 = bm + (mb0 + i)*16 + g;
        int r1 = r0 + 8;
#pragma unroll
        for (int n = 0; n < NI; n++) {
            int gn = bn + (nb0 + n)*8 + tg*2;
            if (gn < N) {
                float b0 = 0.f, b1 = 0.f;
                if (bias) { b0 = bias[gn]; b1 = bias[gn+1]; }
                float v0 = acc[i][n][0] + b0, v1 = acc[i][n][1] + b1;
                float v2 = acc[i][n][2] + b0, v3 = acc[i][n][3] + b1;
                if (addend) {
                    float2 a0 = *(const float2*)(addend + (size_t)r0*ldad + gn);
                    float2 a1 = *(const float2*)(addend + (size_t)r1*ldad + gn);
                    v0 += a0.x; v1 += a0.y; v2 += a1.x; v3 += a1.y;
                }
                *(float2*)(C + (size_t)r0*ldc + gn) = make_float2(v0, v1);
                *(float2*)(C + (size_t)r1*ldc + gn) = make_float2(v2, v3);
            }
        }
    }
}

// ---------------- cascade self-attn (writes half) ----------------
__global__ void casc_attn_kernel() {
    __shared__ float ks[KK][DH+1];
    __shared__ float vs[KK][DH+1];
    int bh = blockIdx.x;
    int b = bh / NHH, nh = bh % NHH;
    int t = threadIdx.x;
    const float* base = g_qkv + ((size_t)(b*KK + t)) * (3*HH);
#pragma unroll
    for (int dd = 0; dd < DH; dd++) {
        ks[t][dd] = base[HH   + nh*DH + dd];
        vs[t][dd] = base[2*HH + nh*DH + dd];
    }
    __syncthreads();
    float q[DH];
#pragma unroll
    for (int dd = 0; dd < DH; dd++) q[dd] = base[nh*DH + dd];

    const float scale = 0.125f;
    float sc[KK];
    float mx = -1e30f;
    for (int j = 0; j <= t; j++) {
        float s = 0.f;
#pragma unroll
        for (int dd = 0; dd < DH; dd++) s += q[dd] * ks[j][dd];
        s *= scale;
        sc[j] = s;
        mx = fmaxf(mx, s);
    }
    float sum = 0.f;
    for (int j = 0; j <= t; j++) {
        float e = expf(sc[j] - mx);
        sc[j] = e;
        sum += e;
    }
    float inv = 1.0f / sum;
    __half* o = h_attn + ((size_t)(b*KK + t)) * HH + nh*DH;
#pragma unroll 4
    for (int dd = 0; dd < DH; dd++) {
        float acc = 0.f;
        for (int j = 0; j <= t; j++) acc += sc[j] * vs[j][dd];
        o[dd] = __float2half(acc * inv);
    }
}

// ---------------- decoder cross-attn (writes half; S split by z) ----------
__global__ void dec_attn_kernel() {
    __shared__ float ks[KK][DH+1];
    __shared__ float vs[KK][DH+1];
    __shared__ float qs[8][DH];
    __shared__ float probs[8][KK];
    int nh = blockIdx.x, b = blockIdx.y, z = blockIdx.z;
    int tid = threadIdx.x;
    for (int i = tid; i < KK*DH; i += 256) {
        int c = i / DH, dd = i % DH;
        const float* kvrow = g_kv + ((size_t)(b*KK + c)) * (2*HH);
        ks[c][dd] = kvrow[nh*DH + dd];
        vs[c][dd] = kvrow[HH + nh*DH + dd];
    }
    __syncthreads();
    int w = tid >> 5, lane = tid & 31;
    const float scale = 0.125f;
    const int s0b = z * (SS/8), s1b = s0b + (SS/8);
    for (int s = s0b + w; s < s1b; s += 8) {
        int nallow = min(KK, s/32 + 2);
        const float* qrow = g_q + ((size_t)b*SS + s) * HH + nh*DH;
        qs[w][lane]      = qrow[lane];
        qs[w][lane + 32] = qrow[lane + 32];
        __syncwarp();
        float s0 = -INFINITY, s1 = -INFINITY;
        if (lane < nallow) {
            float acc = 0.f;
#pragma unroll
            for (int dd = 0; dd < DH; dd++) acc += qs[w][dd] * ks[lane][dd];
            s0 = acc * scale;
        }
        if (lane + 32 < nallow) {
            float acc = 0.f;
#pragma unroll
            for (int dd = 0; dd < DH; dd++) acc += qs[w][dd] * ks[lane + 32][dd];
            s1 = acc * scale;
        }
        float mx = fmaxf(s0, s1);
#pragma unroll
        for (int ofs = 16; ofs > 0; ofs >>= 1)
            mx = fmaxf(mx, __shfl_xor_sync(0xffffffffu, mx, ofs));
        float e0 = expf(s0 - mx);
        float e1 = expf(s1 - mx);
        float sum = e0 + e1;
#pragma unroll
        for (int ofs = 16; ofs > 0; ofs >>= 1)
            sum += __shfl_xor_sync(0xffffffffu, sum, ofs);
        float inv = 1.0f / sum;
        probs[w][lane]      = e0 * inv;
        probs[w][lane + 32] = e1 * inv;
        __syncwarp();
        __half* orow = h_dec + ((size_t)b*SS + s) * HH + nh*DH;
#pragma unroll
        for (int half2i = 0; half2i < 2; half2i++) {
            int dd = lane + half2i*32;
            float acc = 0.f;
            for (int j = 0; j < nallow; j++) acc += probs[w][j] * vs[j][dd];
            orow[dd] = __float2half(acc);
        }
        __syncwarp();
    }
}

// ---------------- host ----------------
template<typename T>
static T* symaddr(const void* sym) {
    void* p = nullptr;
    cudaGetSymbolAddress(&p, sym);
    return (T*)p;
}

#define SMEM_D (3*(128 + 256)*128)   // 147456
#define SMEM_C (3*(64  + 128)*128)   // 73728

extern "C" void kernel_launch(void* const* d_in, const int* in_sizes, int n_in,
                              void* d_out, int out_size) {
    const float* token       = (const float*)d_in[0];
    const float* chunk_repr  = (const float*)d_in[1];
    const float* cw          = (const float*)d_in[2];
    const float* casc_norm1  = (const float*)d_in[3];
    const float* casc_qkv    = (const float*)d_in[4];
    const float* casc_o      = (const float*)d_in[5];
    const float* casc_norm2  = (const float*)d_in[6];
    const float* casc_w1     = (const float*)d_in[7];
    const float* casc_w2     = (const float*)d_in[8];
    const float* casc_w3     = (const float*)d_in[9];
    const float* dec_in_w    = (const float*)d_in[10];
    const float* dec_in_b    = (const float*)d_in[11];
    const float* dec_out_w   = (const float*)d_in[12];
    const float* dec_out_b   = (const float*)d_in[13];
    const float* dec_norm_w  = (const float*)d_in[14];
    const float* dec_ffn_nw  = (const float*)d_in[15];
    const float* dec_w1      = (const float*)d_in[16];
    const float* dec_w2      = (const float*)d_in[17];
    const float* dec_w3      = (const float*)d_in[18];
    float* out = (float*)d_out;

    float* px    = symaddr<float>(g_x);
    float* pqkv  = symaddr<float>(g_qkv);
    float* pff13 = symaddr<float>(g_ff13);
    float* pq    = symaddr<float>(g_q);
    float* pkv   = symaddr<float>(g_kv);
    float* py    = symaddr<float>(g_y);
    float* pyn   = symaddr<float>(g_yn);
    float* pu13  = symaddr<float>(g_u13);

    __half* ph_tok  = symaddr<__half>(h_tok);
    __half* ph_h    = symaddr<__half>(h_h);
    __half* ph_attn = symaddr<__half>(h_attn);
    __half* ph_proc = symaddr<__half>(h_proc);
    __half* ph_ff   = symaddr<__half>(h_ff);
    __half* ph_dec  = symaddr<__half>(h_dec);
    __half* ph_yn   = symaddr<__half>(h_yn);
    __half* ph_u    = symaddr<__half>(h_u);

    __half* pw_qkv  = symaddr<__half>(wh_qkv);
    __half* pw_o    = symaddr<__half>(wh_o);
    __half* pw_w13  = symaddr<__half>(wh_w13);
    __half* pw_w2   = symaddr<__half>(wh_w2);
    __half* pw_din  = symaddr<__half>(wh_din);
    __half* pw_dout = symaddr<__half>(wh_dout);
    __half* pw_dw13 = symaddr<__half>(wh_dw13);
    __half* pw_dw2  = symaddr<__half>(wh_dw2);

    cudaFuncSetAttribute((const void*)hgemm<128,256,2,8>,
                         cudaFuncAttributeMaxDynamicSharedMemorySize, SMEM_D);
    cudaFuncSetAttribute((const void*)hgemm<64,128,2,8>,
                         cudaFuncAttributeMaxDynamicSharedMemorySize, SMEM_C);

    auto gemmD = [&](const __half* A, int lda, const __half* W, int ldw,
                     const float* bias, const float* addend, int ldad,
                     float* C, int ldc, int M, int N, int Kd) {
        dim3 grid((N + 255)/256, M/128);
        hgemm<128,256,2,8><<<grid, NTH, SMEM_D>>>(A, lda, W, ldw, bias, addend, ldad,
                                                  C, ldc, M, N, Kd);
    };
    auto gemmC = [&](const __half* A, int lda, const __half* W, int ldw,
                     const float* bias, const float* addend, int ldad,
                     float* C, int ldc, int M, int N, int Kd) {
        dim3 grid((N + 127)/128, M/64);
        hgemm<64,128,2,8><<<grid, NTH, SMEM_C>>>(A, lda, W, ldw, bias, addend, ldad,
                                                 C, ldc, M, N, Kd);
    };

    // --- weight + token conversion (per launch; deterministic) ---
    halfcopy_kernel<<<2048, 256>>>(casc_qkv, pw_qkv, LL*3*HH*HH);
    halfcopy_kernel<<<2048, 256>>>(casc_o,   pw_o,   LL*HH*HH);
    for (int l = 0; l < LL; l++) {
        w13half_kernel<<<FF2, 256>>>(casc_w1 + (size_t)l*FFD*HH,
                                     casc_w3 + (size_t)l*FFD*HH,
                                     pw_w13 + (size_t)l*FF2*HH);
        w2half_kernel<<<HH, 256>>>(casc_w2 + (size_t)l*HH*FFD,
                                   pw_w2 + (size_t)l*HH*FFH);
    }
    halfcopy_kernel<<<2048, 256>>>(dec_in_w,  pw_din,  3*HH*HH);
    halfcopy_kernel<<<2048, 256>>>(dec_out_w, pw_dout, HH*HH);
    w13half_kernel<<<FF2, 256>>>(dec_w1, dec_w3, pw_dw13);
    w2half_kernel<<<HH, 256>>>(dec_w2, pw_dw2);
    halfcopy_kernel<<<4096, 256>>>(token, ph_tok, BB*SS*HH);

    // --- cascade ---
    rank_kernel<<<BB, KK>>>(cw);
    scatter_kernel<<<BB*KK, 256>>>(chunk_repr);

    const int MC = BB*KK;          // 256
    for (int l = 0; l < LL; l++) {
        rms_kernel<__half><<<MC, 256>>>(px, casc_norm1 + l*HH, ph_h);
        gemmC(ph_h, HH, pw_qkv + (size_t)l*3*HH*HH, HH,
              nullptr, nullptr, 0, pqkv, 3*HH, MC, 3*HH, HH);
        casc_attn_kernel<<<BB*NHH, KK>>>();
        gemmC(ph_attn, HH, pw_o + (size_t)l*HH*HH, HH,
              nullptr, px, HH, px, HH, MC, HH, HH);
        rms_kernel<__half><<<MC, 256>>>(px, casc_norm2 + l*HH, ph_h);
        gemmC(ph_h, HH, pw_w13 + (size_t)l*FF2*HH, HH,
              nullptr, nullptr, 0, pff13, FF2, MC, FF2, HH);
        glu_kernel<<<2048, 256>>>(pff13, ph_ff, MC);
        gemmC(ph_ff, FFH, pw_w2 + (size_t)l*HH*FFH, FFH,
              nullptr, px, HH, px, HH, MC, HH, FFH);
    }
    gather_kernel<<<BB*KK, 256>>>();

    // --- decoder ---
    const int MT = BB*SS;          // 8192
    gemmD(ph_tok, HH, pw_din, HH,
          dec_in_b, nullptr, 0, pq, HH, MT, HH, HH);
    gemmC(ph_proc, HH, pw_din + (size_t)HH*HH, HH,
          dec_in_b + HH, nullptr, 0, pkv, 2*HH, MC, 2*HH, HH);
    dec_attn_kernel<<<dim3(NHH, BB, 8), 256>>>();
    gemmD(ph_dec, HH, pw_dout, HH,
          dec_out_b, token, HH, pyn, HH, MT, HH, HH);
    rms_kernel<float><<<MT, 256>>>(pyn, dec_norm_w, py);
    rms_kernel<__half><<<MT, 256>>>(py, dec_ffn_nw, ph_yn);
    gemmD(ph_yn, HH, pw_dw13, HH,
          nullptr, nullptr, 0, pu13, FF2, MT, FF2, HH);
    glu_kernel<<<8192, 256>>>(pu13, ph_u, MT);
    gemmD(ph_u, FFH, pw_dw2, FFH,
          nullptr, py, HH, out, HH, MT, HH, FFH);
}

// round 11
// speedup vs baseline: 6.9587x; 1.0381x over previous
#include <cuda_runtime.h>
#include <cuda_bf16.h>
#include <cuda_fp16.h>
#include <math.h>
#include <stdint.h>

#define BB 4
#define SS 2048
#define HH 1024
#define KK 64
#define NHH 16
#define DH 64
#define LL 2
#define FFD 2730
#define FFH 2752        // ff dim padded to multiple of 64
#define FI2 (2*FFH)     // interleaved w1/w3 N dim = 5504
#define EPSV 1e-6f

// ---------------- scratch (fp32) ----------------
__device__ float g_x[BB*KK*HH];
__device__ float g_qkv[BB*KK*3*HH];
__device__ int   g_rank[BB*KK];
__device__ float g_q[BB*SS*HH];
__device__ float g_kv[BB*KK*2*HH];
__device__ float g_y[BB*SS*HH];
__device__ float g_yn[BB*SS*HH];

// ---------------- scratch (half activations) ----------------
__device__ __half h_tok[BB*SS*HH];
__device__ __half h_h[BB*KK*HH];
__device__ __half h_attn[BB*KK*HH];
__device__ __half h_proc[BB*KK*HH];
__device__ __half h_ff[BB*KK*FFH];
__device__ __half h_dec[BB*SS*HH];
__device__ __half h_yn[BB*SS*HH];
__device__ __half h_u[BB*SS*FFH];

// ---------------- half weights ----------------
__device__ __half wh_qkv[LL*3*HH*HH];
__device__ __half wh_o[LL*HH*HH];
__device__ __half wh_w13[LL*FI2*HH];   // interleaved w1/w3 rows
__device__ __half wh_w2[LL*HH*FFH];
__device__ __half wh_din[3*HH*HH];
__device__ __half wh_dout[HH*HH];
__device__ __half wh_dw13[FI2*HH];     // interleaved
__device__ __half wh_dw2[HH*FFH];

// ---------------- small kernels ----------------
__global__ void rank_kernel(const float* __restrict__ cw) {
    int b = blockIdx.x, k = threadIdx.x;
    float wk = cw[b*KK + k];
    int r = 0;
    for (int j = 0; j < KK; j++) {
        float wj = cw[b*KK + j];
        if (wj > wk || (wj == wk && j < k)) r++;
    }
    g_rank[b*KK + k] = r;
}

__global__ void scatter_kernel(const float* __restrict__ src) {
    int row = blockIdx.x;
    int b = row / KK;
    int r = g_rank[row];
    const float* s = src + (size_t)row * HH;
    float* d = g_x + ((size_t)(b*KK + r)) * HH;
    for (int i = threadIdx.x; i < HH; i += blockDim.x) d[i] = s[i];
}

__global__ void gather_kernel() {
    int row = blockIdx.x;
    int b = row / KK;
    int r = g_rank[row];
    const float* s = g_x + ((size_t)(b*KK + r)) * HH;
    __half* d = h_proc + (size_t)row * HH;
    for (int i = threadIdx.x; i < HH; i += blockDim.x) d[i] = __float2half(s[i]);
}

// vectorized fp32 -> half copy (n multiple of 2)
__global__ void halfcopy_kernel(const float* __restrict__ src, __half* __restrict__ dst, int n2) {
    for (int i = blockIdx.x * blockDim.x + threadIdx.x; i < n2; i += gridDim.x * blockDim.x) {
        float2 v = *(const float2*)(src + i*2);
        *(__half2*)(dst + i*2) = __floats2half2_rn(v.x, v.y);
    }
}

// interleaved [FI2][HH] half: row 2c = w1[c], row 2c+1 = w3[c], zero for c>=FFD
__global__ void w13i_kernel(const float* __restrict__ w1, const float* __restrict__ w3,
                            __half* __restrict__ dst) {
    int row = blockIdx.x;                 // 0..FI2-1
    int c = row >> 1;
    const float* src = nullptr;
    if (c < FFD) src = ((row & 1) ? w3 : w1) + (size_t)c * HH;
    __half* d = dst + (size_t)row * HH;
    for (int i = threadIdx.x; i < HH; i += blockDim.x)
        d[i] = src ? __float2half(src[i]) : __half(0.f);
}

// [HH][FFD] -> [HH][FFH] half, zero pad
__global__ void w2half_kernel(const float* __restrict__ src, __half* __restrict__ dst) {
    int row = blockIdx.x;
    for (int i = threadIdx.x; i < FFH; i += blockDim.x)
        dst[(size_t)row*FFH + i] = (i < FFD) ? __float2half(src[(size_t)row*FFD + i]) : __half(0.f);
}

template<typename TOUT>
__global__ void rms_kernel(const float* __restrict__ in, const float* __restrict__ w,
                           TOUT* __restrict__ out) {
    __shared__ float red[256];
    int row = blockIdx.x;
    const float* x = in + (size_t)row * HH;
    TOUT* o = out + (size_t)row * HH;
    int t = threadIdx.x;
    float v[4];
    float ss = 0.f;
#pragma unroll
    for (int i = 0; i < 4; i++) { v[i] = x[t + i*256]; ss += v[i]*v[i]; }
    red[t] = ss;
    __syncthreads();
    for (int ofs = 128; ofs > 0; ofs >>= 1) {
        if (t < ofs) red[t] += red[t + ofs];
        __syncthreads();
    }
    float inv = rsqrtf(red[0] * (1.0f/HH) + EPSV);
#pragma unroll
    for (int i = 0; i < 4; i++) {
        int c = t + i*256;
        o[c] = (TOUT)(v[i] * inv * w[c]);
    }
}

// ---------------- half GEMM: cp.async + SW128 + ldmatrix + HMMA ----------
__device__ __forceinline__ void cp16(uint32_t dst, const void* src, bool pred) {
    int p = pred ? 1 : 0;
    asm volatile(
        "{\n.reg .pred p;\nsetp.ne.b32 p, %2, 0;\n"
        "@p  cp.async.cg.shared.global [%0], [%1], 16;\n"
        "@!p cp.async.cg.shared.global [%0], [%1], 16, 0;\n}"
        :: "r"(dst), "l"(src), "r"(p));
}

__device__ __forceinline__ void ldsm4(uint32_t& r0, uint32_t& r1, uint32_t& r2, uint32_t& r3,
                                      uint32_t addr) {
    asm volatile("ldmatrix.sync.aligned.m8n8.x4.shared.b16 {%0,%1,%2,%3}, [%4];"
                 : "=r"(r0), "=r"(r1), "=r"(r2), "=r"(r3) : "r"(addr));
}

__device__ __forceinline__ void mma_f16(float* d, const uint32_t* a, const uint32_t* b) {
    asm volatile(
        "mma.sync.aligned.m16n8k16.row.col.f32.f16.f16.f32 "
        "{%0,%1,%2,%3}, {%4,%5,%6,%7}, {%8,%9}, {%0,%1,%2,%3};\n"
        : "+f"(d[0]), "+f"(d[1]), "+f"(d[2]), "+f"(d[3])
        : "r"(a[0]), "r"(a[1]), "r"(a[2]), "r"(a[3]), "r"(b[0]), "r"(b[1]));
}

__device__ __forceinline__ float siluf(float x) {
    return x / (1.0f + __expf(-x));
}

#define NTH 512

// GLU=0: C fp32 [M][ldc] = A@W^T (+bias)(+addend)
// GLU=1: C half [M][ldc] : C[m][gn/2] = silu(acc[gn]) * acc[gn+1]  (interleaved W)
template<int MB, int NB, int WR, int WC, int GLU>
__global__ __launch_bounds__(NTH) void hgemm(
    const __half* __restrict__ A, int lda,
    const __half* __restrict__ W, int ldw,
    const float* __restrict__ bias, const float* __restrict__ addend, int ldad,
    void* __restrict__ Cv, int ldc, int M, int N, int Kd)
{
    constexpr int MI  = MB / WR / 16;
    constexpr int NI  = NB / WC / 8;
    constexpr int ACH = MB * 8 / NTH;
    constexpr int BCH = NB * 8 / NTH;
    constexpr int ASZB = MB * 128;
    constexpr int BSZB = NB * 128;
    constexpr int STGB = ASZB + BSZB;

    extern __shared__ char smc[];
    const uint32_t sbase = (uint32_t)__cvta_generic_to_shared(smc);
    const int tid  = threadIdx.x;
    const int lane = tid & 31;
    const int wid  = tid >> 5;
    const int wr   = wid / WC, wc = wid % WC;
    const int mb0  = wr * MI;
    const int nb0  = wc * NI;
    const int bm = blockIdx.y * MB, bn = blockIdx.x * NB;

    float acc[MI][NI][4];
#pragma unroll
    for (int i = 0; i < MI; i++)
#pragma unroll
        for (int n = 0; n < NI; n++)
#pragma unroll
            for (int q = 0; q < 4; q++) acc[i][n][q] = 0.f;

    const int T = Kd >> 6;

    auto fill = [&](int t) {
        int st = t - (t/3)*3;
        uint32_t ab = sbase + st*STGB;
        uint32_t bb = ab + ASZB;
        int k0 = t * 64;
#pragma unroll
        for (int ch = 0; ch < ACH; ch++) {
            int idx = tid + ch*NTH;
            int row = idx >> 3, c = idx & 7;
            uint32_t dst = ab + row*128 + ((c ^ (row & 7)) << 4);
            cp16(dst, A + (size_t)(bm + row)*lda + k0 + c*8, true);
        }
#pragma unroll
        for (int ch = 0; ch < BCH; ch++) {
            int idx = tid + ch*NTH;
            int row = idx >> 3, c = idx & 7;
            int gn = bn + row;
            bool p = gn < N;
            uint32_t dst = bb + row*128 + ((c ^ (row & 7)) << 4);
            cp16(dst, W + (size_t)(p ? gn : 0)*ldw + k0 + c*8, p);
        }
        asm volatile("cp.async.commit_group;" ::: "memory");
    };

    const int mi = lane >> 3;
    const int aRowLoc = (mi & 1)*8 + (lane & 7);
    const int aCb = mi >> 1;
    const int bRowLoc = lane & 7;
    const int bBlk = mi >> 1;
    const int bCb = mi & 1;
    uint32_t aRowOff[MI], aS[MI];
#pragma unroll
    for (int i = 0; i < MI; i++) {
        int row = (mb0 + i)*16 + aRowLoc;
        aRowOff[i] = row*128;
        aS[i] = (row & 7) << 4;
    }
    uint32_t bRowOff[NI/2], bS[NI/2];
#pragma unroll
    for (int j = 0; j < NI/2; j++) {
        int nr = (nb0 + j*2 + bBlk)*8 + bRowLoc;
        bRowOff[j] = nr*128;
        bS[j] = (nr & 7) << 4;
    }

    fill(0);
    fill(1);

    for (int t = 0; t < T; t++) {
        if (t == T - 1)
            asm volatile("cp.async.wait_group 0;" ::: "memory");
        else
            asm volatile("cp.async.wait_group 1;" ::: "memory");
        __syncthreads();
        int st = t - (t/3)*3;
        uint32_t ab = sbase + st*STGB;
        uint32_t bb = ab + ASZB;
#pragma unroll
        for (int kb = 0; kb < 4; kb++) {
            uint32_t af[MI][4];
#pragma unroll
            for (int i = 0; i < MI; i++)
                ldsm4(af[i][0], af[i][1], af[i][2], af[i][3],
                      ab + aRowOff[i] + ((((kb*2 + aCb) << 4)) ^ aS[i]));
            uint32_t bf[NI][2];
#pragma unroll
            for (int j = 0; j < NI/2; j++)
                ldsm4(bf[j*2][0], bf[j*2][1], bf[j*2+1][0], bf[j*2+1][1],
                      bb + bRowOff[j] + ((((kb*2 + bCb) << 4)) ^ bS[j]));
#pragma unroll
            for (int i = 0; i < MI; i++)
#pragma unroll
                for (int n = 0; n < NI; n++)
                    mma_f16(acc[i][n], af[i], bf[n]);
        }
        if (t + 2 < T) fill(t + 2);
    }

    const int g = lane >> 2, tg = lane & 3;
    if (GLU) {
        __half* Ch = (__half*)Cv;
#pragma unroll
        for (int i = 0; i < MI; i++) {
            int r0 = bm + (mb0 + i)*16 + g;
            int r1 = r0 + 8;
#pragma unroll
            for (int n = 0; n < NI; n++) {
                int gn = bn + (nb0 + n)*8 + tg*2;    // even
                if (gn < N) {
                    int col = gn >> 1;
                    Ch[(size_t)r0*ldc + col] = __float2half(siluf(acc[i][n][0]) * acc[i][n][1]);
                    Ch[(size_t)r1*ldc + col] = __float2half(siluf(acc[i][n][2]) * acc[i][n][3]);
                }
            }
        }
    } else {
        float* C = (float*)Cv;
#pragma unroll
        for (int i = 0; i < MI; i++) {
            int r0 = bm + (mb0 + i)*16 + g;
            int r1 = r0 + 8;
#pragma unroll
            for (int n = 0; n < NI; n++) {
                int gn = bn + (nb0 + n)*8 + tg*2;
                if (gn < N) {
                    float b0 = 0.f, b1 = 0.f;
                    if (bias) { b0 = bias[gn]; b1 = bias[gn+1]; }
                    float v0 = acc[i][n][0] + b0, v1 = acc[i][n][1] + b1;
                    float v2 = acc[i][n][2] + b0, v3 = acc[i][n][3] + b1;
                    if (addend) {
                        float2 a0 = *(const float2*)(addend + (size_t)r0*ldad + gn);
                        float2 a1 = *(const float2*)(addend + (size_t)r1*ldad + gn);
                        v0 += a0.x; v1 += a0.y; v2 += a1.x; v3 += a1.y;
                    }
                    *(float2*)(C + (size_t)r0*ldc + gn) = make_float2(v0, v1);
                    *(float2*)(C + (size_t)r1*ldc + gn) = make_float2(v2, v3);
                }
            }
        }
    }
}

// ---------------- cascade self-attn (writes half) ----------------
__global__ void casc_attn_kernel() {
    __shared__ float ks[KK][DH+1];
    __shared__ float vs[KK][DH+1];
    int bh = blockIdx.x;
    int b = bh / NHH, nh = bh % NHH;
    int t = threadIdx.x;
    const float* base = g_qkv + ((size_t)(b*KK + t)) * (3*HH);
#pragma unroll
    for (int dd = 0; dd < DH; dd++) {
        ks[t][dd] = base[HH   + nh*DH + dd];
        vs[t][dd] = base[2*HH + nh*DH + dd];
    }
    __syncthreads();
    float q[DH];
#pragma unroll
    for (int dd = 0; dd < DH; dd++) q[dd] = base[nh*DH + dd];

    const float scale = 0.125f;
    float sc[KK];
    float mx = -1e30f;
    for (int j = 0; j <= t; j++) {
        float s = 0.f;
#pragma unroll
        for (int dd = 0; dd < DH; dd++) s += q[dd] * ks[j][dd];
        s *= scale;
        sc[j] = s;
        mx = fmaxf(mx, s);
    }
    float sum = 0.f;
    for (int j = 0; j <= t; j++) {
        float e = expf(sc[j] - mx);
        sc[j] = e;
        sum += e;
    }
    float inv = 1.0f / sum;
    __half* o = h_attn + ((size_t)(b*KK + t)) * HH + nh*DH;
#pragma unroll 4
    for (int dd = 0; dd < DH; dd++) {
        float acc = 0.f;
        for (int j = 0; j <= t; j++) acc += sc[j] * vs[j][dd];
        o[dd] = __float2half(acc * inv);
    }
}

// ---------------- decoder cross-attn (writes half; S split by z) ----------
__global__ void dec_attn_kernel() {
    __shared__ float ks[KK][DH+1];
    __shared__ float vs[KK][DH+1];
    __shared__ float qs[8][DH];
    __shared__ float probs[8][KK];
    int nh = blockIdx.x, b = blockIdx.y, z = blockIdx.z;
    int tid = threadIdx.x;
    for (int i = tid; i < KK*DH; i += 256) {
        int c = i / DH, dd = i % DH;
        const float* kvrow = g_kv + ((size_t)(b*KK + c)) * (2*HH);
        ks[c][dd] = kvrow[nh*DH + dd];
        vs[c][dd] = kvrow[HH + nh*DH + dd];
    }
    __syncthreads();
    int w = tid >> 5, lane = tid & 31;
    const float scale = 0.125f;
    const int s0b = z * (SS/8), s1b = s0b + (SS/8);
    for (int s = s0b + w; s < s1b; s += 8) {
        int nallow = min(KK, s/32 + 2);
        const float* qrow = g_q + ((size_t)b*SS + s) * HH + nh*DH;
        qs[w][lane]      = qrow[lane];
        qs[w][lane + 32] = qrow[lane + 32];
        __syncwarp();
        float s0 = -INFINITY, s1 = -INFINITY;
        if (lane < nallow) {
            float acc = 0.f;
#pragma unroll
            for (int dd = 0; dd < DH; dd++) acc += qs[w][dd] * ks[lane][dd];
            s0 = acc * scale;
        }
        if (lane + 32 < nallow) {
            float acc = 0.f;
#pragma unroll
            for (int dd = 0; dd < DH; dd++) acc += qs[w][dd] * ks[lane + 32][dd];
            s1 = acc * scale;
        }
        float mx = fmaxf(s0, s1);
#pragma unroll
        for (int ofs = 16; ofs > 0; ofs >>= 1)
            mx = fmaxf(mx, __shfl_xor_sync(0xffffffffu, mx, ofs));
        float e0 = expf(s0 - mx);
        float e1 = expf(s1 - mx);
        float sum = e0 + e1;
#pragma unroll
        for (int ofs = 16; ofs > 0; ofs >>= 1)
            sum += __shfl_xor_sync(0xffffffffu, sum, ofs);
        float inv = 1.0f / sum;
        probs[w][lane]      = e0 * inv;
        probs[w][lane + 32] = e1 * inv;
        __syncwarp();
        __half* orow = h_dec + ((size_t)b*SS + s) * HH + nh*DH;
#pragma unroll
        for (int half2i = 0; half2i < 2; half2i++) {
            int dd = lane + half2i*32;
            float acc = 0.f;
            for (int j = 0; j < nallow; j++) acc += probs[w][j] * vs[j][dd];
            orow[dd] = __float2half(acc);
        }
        __syncwarp();
    }
}

// ---------------- host ----------------
template<typename T>
static T* symaddr(const void* sym) {
    void* p = nullptr;
    cudaGetSymbolAddress(&p, sym);
    return (T*)p;
}

#define SMEM_D (3*(128 + 256)*128)   // 147456
#define SMEM_C (3*(64  + 128)*128)   // 73728

extern "C" void kernel_launch(void* const* d_in, const int* in_sizes, int n_in,
                              void* d_out, int out_size) {
    const float* token       = (const float*)d_in[0];
    const float* chunk_repr  = (const float*)d_in[1];
    const float* cw          = (const float*)d_in[2];
    const float* casc_norm1  = (const float*)d_in[3];
    const float* casc_qkv    = (const float*)d_in[4];
    const float* casc_o      = (const float*)d_in[5];
    const float* casc_norm2  = (const float*)d_in[6];
    const float* casc_w1     = (const float*)d_in[7];
    const float* casc_w2     = (const float*)d_in[8];
    const float* casc_w3     = (const float*)d_in[9];
    const float* dec_in_w    = (const float*)d_in[10];
    const float* dec_in_b    = (const float*)d_in[11];
    const float* dec_out_w   = (const float*)d_in[12];
    const float* dec_out_b   = (const float*)d_in[13];
    const float* dec_norm_w  = (const float*)d_in[14];
    const float* dec_ffn_nw  = (const float*)d_in[15];
    const float* dec_w1      = (const float*)d_in[16];
    const float* dec_w2      = (const float*)d_in[17];
    const float* dec_w3      = (const float*)d_in[18];
    float* out = (float*)d_out;

    float* px    = symaddr<float>(g_x);
    float* pqkv  = symaddr<float>(g_qkv);
    float* pq    = symaddr<float>(g_q);
    float* pkv   = symaddr<float>(g_kv);
    float* py    = symaddr<float>(g_y);
    float* pyn   = symaddr<float>(g_yn);

    __half* ph_tok  = symaddr<__half>(h_tok);
    __half* ph_h    = symaddr<__half>(h_h);
    __half* ph_attn = symaddr<__half>(h_attn);
    __half* ph_proc = symaddr<__half>(h_proc);
    __half* ph_ff   = symaddr<__half>(h_ff);
    __half* ph_dec  = symaddr<__half>(h_dec);
    __half* ph_yn   = symaddr<__half>(h_yn);
    __half* ph_u    = symaddr<__half>(h_u);

    __half* pw_qkv  = symaddr<__half>(wh_qkv);
    __half* pw_o    = symaddr<__half>(wh_o);
    __half* pw_w13  = symaddr<__half>(wh_w13);
    __half* pw_w2   = symaddr<__half>(wh_w2);
    __half* pw_din  = symaddr<__half>(wh_din);
    __half* pw_dout = symaddr<__half>(wh_dout);
    __half* pw_dw13 = symaddr<__half>(wh_dw13);
    __half* pw_dw2  = symaddr<__half>(wh_dw2);

    cudaFuncSetAttribute((const void*)hgemm<128,256,2,8,0>,
                         cudaFuncAttributeMaxDynamicSharedMemorySize, SMEM_D);
    cudaFuncSetAttribute((const void*)hgemm<128,256,2,8,1>,
                         cudaFuncAttributeMaxDynamicSharedMemorySize, SMEM_D);
    cudaFuncSetAttribute((const void*)hgemm<64,128,2,8,0>,
                         cudaFuncAttributeMaxDynamicSharedMemorySize, SMEM_C);
    cudaFuncSetAttribute((const void*)hgemm<64,128,2,8,1>,
                         cudaFuncAttributeMaxDynamicSharedMemorySize, SMEM_C);

    auto gemmD = [&](const __half* A, int lda, const __half* W, int ldw,
                     const float* bias, const float* addend, int ldad,
                     void* C, int ldc, int M, int N, int Kd, bool glu) {
        dim3 grid((N + 255)/256, M/128);
        if (glu)
            hgemm<128,256,2,8,1><<<grid, NTH, SMEM_D>>>(A, lda, W, ldw, bias, addend, ldad,
                                                        C, ldc, M, N, Kd);
        else
            hgemm<128,256,2,8,0><<<grid, NTH, SMEM_D>>>(A, lda, W, ldw, bias, addend, ldad,
                                                        C, ldc, M, N, Kd);
    };
    auto gemmC = [&](const __half* A, int lda, const __half* W, int ldw,
                     const float* bias, const float* addend, int ldad,
                     void* C, int ldc, int M, int N, int Kd, bool glu) {
        dim3 grid((N + 127)/128, M/64);
        if (glu)
            hgemm<64,128,2,8,1><<<grid, NTH, SMEM_C>>>(A, lda, W, ldw, bias, addend, ldad,
                                                       C, ldc, M, N, Kd);
        else
            hgemm<64,128,2,8,0><<<grid, NTH, SMEM_C>>>(A, lda, W, ldw, bias, addend, ldad,
                                                       C, ldc, M, N, Kd);
    };

    // --- weight + token conversion (per launch) ---
    halfcopy_kernel<<<2048, 256>>>(casc_qkv, pw_qkv, LL*3*HH*HH/2);
    halfcopy_kernel<<<2048, 256>>>(casc_o,   pw_o,   LL*HH*HH/2);
    for (int l = 0; l < LL; l++) {
        w13i_kernel<<<FI2, 256>>>(casc_w1 + (size_t)l*FFD*HH,
                                  casc_w3 + (size_t)l*FFD*HH,
                                  pw_w13 + (size_t)l*FI2*HH);
        w2half_kernel<<<HH, 256>>>(casc_w2 + (size_t)l*HH*FFD,
                                   pw_w2 + (size_t)l*HH*FFH);
    }
    halfcopy_kernel<<<2048, 256>>>(dec_in_w,  pw_din,  3*HH*HH/2);
    halfcopy_kernel<<<2048, 256>>>(dec_out_w, pw_dout, HH*HH/2);
    w13i_kernel<<<FI2, 256>>>(dec_w1, dec_w3, pw_dw13);
    w2half_kernel<<<HH, 256>>>(dec_w2, pw_dw2);
    halfcopy_kernel<<<4096, 256>>>(token, ph_tok, BB*SS*HH/2);

    // --- cascade ---
    rank_kernel<<<BB, KK>>>(cw);
    scatter_kernel<<<BB*KK, 256>>>(chunk_repr);

    const int MC = BB*KK;          // 256
    for (int l = 0; l < LL; l++) {
        rms_kernel<__half><<<MC, 256>>>(px, casc_norm1 + l*HH, ph_h);
        gemmC(ph_h, HH, pw_qkv + (size_t)l*3*HH*HH, HH,
              nullptr, nullptr, 0, pqkv, 3*HH, MC, 3*HH, HH, false);
        casc_attn_kernel<<<BB*NHH, KK>>>();
        gemmC(ph_attn, HH, pw_o + (size_t)l*HH*HH, HH,
              nullptr, px, HH, px, HH, MC, HH, HH, false);
        rms_kernel<__half><<<MC, 256>>>(px, casc_norm2 + l*HH, ph_h);
        gemmC(ph_h, HH, pw_w13 + (size_t)l*FI2*HH, HH,
              nullptr, nullptr, 0, ph_ff, FFH, MC, FI2, HH, true);
        gemmC(ph_ff, FFH, pw_w2 + (size_t)l*HH*FFH, FFH,
              nullptr, px, HH, px, HH, MC, HH, FFH, false);
    }
    gather_kernel<<<BB*KK, 256>>>();

    // --- decoder ---
    const int MT = BB*SS;          // 8192
    gemmD(ph_tok, HH, pw_din, HH,
          dec_in_b, nullptr, 0, pq, HH, MT, HH, HH, false);
    gemmC(ph_proc, HH, pw_din + (size_t)HH*HH, HH,
          dec_in_b + HH, nullptr, 0, pkv, 2*HH, MC, 2*HH, HH, false);
    dec_attn_kernel<<<dim3(NHH, BB, 8), 256>>>();
    gemmD(ph_dec, HH, pw_dout, HH,
          dec_out_b, token, HH, pyn, HH, MT, HH, HH, false);
    rms_kernel<float><<<MT, 256>>>(pyn, dec_norm_w, py);
    rms_kernel<__half><<<MT, 256>>>(py, dec_ffn_nw, ph_yn);
    gemmD(ph_yn, HH, pw_dw13, HH,
          nullptr, nullptr, 0, ph_u, FFH, MT, FI2, HH, true);
    gemmD(ph_u, FFH, pw_dw2, FFH,
          nullptr, py, HH, out, HH, MT, HH, FFH, false);
}

// round 12
// speedup vs baseline: 7.1580x; 1.0286x over previous
#include <cuda_runtime.h>
#include <cuda_bf16.h>
#include <cuda_fp16.h>
#include <math.h>
#include <stdint.h>

#define BB 4
#define SS 2048
#define HH 1024
#define KK 64
#define NHH 16
#define DH 64
#define LL 2
#define FFD 2730
#define FFH 2752
#define FI2 (2*FFH)
#define EPSV 1e-6f

__device__ float g_x[BB*KK*HH];
__device__ float g_qkv[BB*KK*3*HH];
__device__ int   g_rank[BB*KK];
__device__ float g_q[BB*SS*HH];
__device__ float g_kv[BB*KK*2*HH];
__device__ float g_y[BB*SS*HH];
__device__ float g_yn[BB*SS*HH];

__device__ __half h_tok[BB*SS*HH];
__device__ __half h_h[BB*KK*HH];
__device__ __half h_attn[BB*KK*HH];
__device__ __half h_proc[BB*KK*HH];
__device__ __half h_ff[BB*KK*FFH];
__device__ __half h_dec[BB*SS*HH];
__device__ __half h_yn[BB*SS*HH];
__device__ __half h_u[BB*SS*FFH];

__device__ __half wh_qkv[LL*3*HH*HH];
__device__ __half wh_o[LL*HH*HH];
__device__ __half wh_w13[LL*FI2*HH];
__device__ __half wh_w2[LL*HH*FFH];
__device__ __half wh_din[3*HH*HH];
__device__ __half wh_dout[HH*HH];
__device__ __half wh_dw13[FI2*HH];
__device__ __half wh_dw2[HH*FFH];

__global__ void rank_kernel(const float* __restrict__ cw) {
    int b = blockIdx.x, k = threadIdx.x;
    float wk = cw[b*KK + k];
    int r = 0;
    for (int j = 0; j < KK; j++) {
        float wj = cw[b*KK + j];
        if (wj > wk || (wj == wk && j < k)) r++;
    }
    g_rank[b*KK + k] = r;
}

__global__ void scatter_kernel(const float* __restrict__ src) {
    int row = blockIdx.x;
    int b = row / KK;
    int r = g_rank[row];
    const float* s = src + (size_t)row * HH;
    float* d = g_x + ((size_t)(b*KK + r)) * HH;
    for (int i = threadIdx.x; i < HH; i += blockDim.x) d[i] = s[i];
}

__global__ void gather_kernel() {
    int row = blockIdx.x;
    int b = row / KK;
    int r = g_rank[row];
    const float* s = g_x + ((size_t)(b*KK + r)) * HH;
    __half* d = h_proc + (size_t)row * HH;
    for (int i = threadIdx.x; i < HH; i += blockDim.x) d[i] = __float2half(s[i]);
}

__global__ void halfcopy_kernel(const float* __restrict__ src, __half* __restrict__ dst, int n2) {
    for (int i = blockIdx.x * blockDim.x + threadIdx.x; i < n2; i += gridDim.x * blockDim.x) {
        float2 v = *(const float2*)(src + i*2);
        *(__half2*)(dst + i*2) = __floats2half2_rn(v.x, v.y);
    }
}

__global__ void w13i_kernel(const float* __restrict__ w1, const float* __restrict__ w3,
                            __half* __restrict__ dst) {
    int row = blockIdx.x;
    int c = row >> 1;
    __half* d = dst + (size_t)row * HH;
    if (c < FFD) {
        const float* src = ((row & 1) ? w3 : w1) + (size_t)c * HH;
        for (int i = threadIdx.x*4; i < HH; i += blockDim.x*4) {
            float4 v = *(const float4*)(src + i);
            *(__half2*)(d + i)     = __floats2half2_rn(v.x, v.y);
            *(__half2*)(d + i + 2) = __floats2half2_rn(v.z, v.w);
        }
    } else {
        for (int i = threadIdx.x*4; i < HH; i += blockDim.x*4)
            *(uint2*)(d + i) = make_uint2(0u, 0u);
    }
}

__global__ void w2half_kernel(const float* __restrict__ src, __half* __restrict__ dst) {
    int row = blockIdx.x;
    const float* s = src + (size_t)row * FFD;
    __half* d = dst + (size_t)row * FFH;
    for (int i = threadIdx.x*2; i < FFH; i += blockDim.x*2) {
        float x = 0.f, y = 0.f;
        if (i + 1 < FFD) {
            float2 v = *(const float2*)(s + i);
            x = v.x; y = v.y;
        } else if (i < FFD) {
            x = s[i];
        }
        *(__half2*)(d + i) = __floats2half2_rn(x, y);
    }
}

template<typename TOUT>
__global__ void rms_kernel(const float* __restrict__ in, const float* __restrict__ w,
                           TOUT* __restrict__ out) {
    __shared__ float red[256];
    int row = blockIdx.x;
    const float* x = in + (size_t)row * HH;
    TOUT* o = out + (size_t)row * HH;
    int t = threadIdx.x;
    float v[4];
    float ss = 0.f;
#pragma unroll
    for (int i = 0; i < 4; i++) { v[i] = x[t + i*256]; ss += v[i]*v[i]; }
    red[t] = ss;
    __syncthreads();
    for (int ofs = 128; ofs > 0; ofs >>= 1) {
        if (t < ofs) red[t] += red[t + ofs];
        __syncthreads();
    }
    float inv = rsqrtf(red[0] * (1.0f/HH) + EPSV);
#pragma unroll
    for (int i = 0; i < 4; i++) {
        int c = t + i*256;
        o[c] = (TOUT)(v[i] * inv * w[c]);
    }
}

__global__ void rms2_kernel(const float* __restrict__ in, const float* __restrict__ w1,
                            const float* __restrict__ w2n,
                            float* __restrict__ outy, __half* __restrict__ outh) {
    __shared__ float red[256];
    int row = blockIdx.x;
    const float* x = in + (size_t)row * HH;
    int t = threadIdx.x;
    float v[4];
    float ss = 0.f;
#pragma unroll
    for (int i = 0; i < 4; i++) { v[i] = x[t + i*256]; ss += v[i]*v[i]; }
    red[t] = ss;
    __syncthreads();
    for (int ofs = 128; ofs > 0; ofs >>= 1) {
        if (t < ofs) red[t] += red[t + ofs];
        __syncthreads();
    }
    float inv1 = rsqrtf(red[0] * (1.0f/HH) + EPSV);
    __syncthreads();
    float y[4];
    float ss2 = 0.f;
#pragma unroll
    for (int i = 0; i < 4; i++) {
        int c = t + i*256;
        y[i] = v[i] * inv1 * w1[c];
        ss2 += y[i]*y[i];
    }
    red[t] = ss2;
    __syncthreads();
    for (int ofs = 128; ofs > 0; ofs >>= 1) {
        if (t < ofs) red[t] += red[t + ofs];
        __syncthreads();
    }
    float inv2 = rsqrtf(red[0] * (1.0f/HH) + EPSV);
    float* oy = outy + (size_t)row * HH;
    __half* oh = outh + (size_t)row * HH;
#pragma unroll
    for (int i = 0; i < 4; i++) {
        int c = t + i*256;
        oy[c] = y[i];
        oh[c] = __float2half(y[i] * inv2 * w2n[c]);
    }
}

__device__ __forceinline__ void cp16(uint32_t dst, const void* src, bool pred) {
    int p = pred ? 1 : 0;
    asm volatile(
        "{\n.reg .pred p;\nsetp.ne.b32 p, %2, 0;\n"
        "@p  cp.async.cg.shared.global [%0], [%1], 16;\n"
        "@!p cp.async.cg.shared.global [%0], [%1], 16, 0;\n}"
        :: "r"(dst), "l"(src), "r"(p));
}

__device__ __forceinline__ void ldsm4(uint32_t& r0, uint32_t& r1, uint32_t& r2, uint32_t& r3,
                                      uint32_t addr) {
    asm volatile("ldmatrix.sync.aligned.m8n8.x4.shared.b16 {%0,%1,%2,%3}, [%4];"
                 : "=r"(r0), "=r"(r1), "=r"(r2), "=r"(r3) : "r"(addr));
}

__device__ __forceinline__ void mma_f16(float* d, const uint32_t* a, const uint32_t* b) {
    asm volatile(
        "mma.sync.aligned.m16n8k16.row.col.f32.f16.f16.f32 "
        "{%0,%1,%2,%3}, {%4,%5,%6,%7}, {%8,%9}, {%0,%1,%2,%3};\n"
        : "+f"(d[0]), "+f"(d[1]), "+f"(d[2]), "+f"(d[3])
        : "r"(a[0]), "r"(a[1]), "r"(a[2]), "r"(a[3]), "r"(b[0]), "r"(b[1]));
}

__device__ __forceinline__ float siluf(float x) {
    return x / (1.0f + __expf(-x));
}

#define NTH 512

template<int MB, int NB, int WR, int WC, int GLU>
__global__ __launch_bounds__(NTH) void hgemm(
    const __half* __restrict__ A, int lda,
    const __half* __restrict__ W, int ldw,
    const float* __restrict__ bias, const float* __restrict__ addend, int ldad,
    void* __restrict__ Cv, int ldc, int M, int N, int Kd)
{
    constexpr int MI  = MB / WR / 16;
    constexpr int NI  = NB / WC / 8;
    constexpr int ACH = MB * 8 / NTH;
    constexpr int BCH = NB * 8 / NTH;
    constexpr int ASZB = MB * 128;
    constexpr int BSZB = NB * 128;
    constexpr int STGB = ASZB + BSZB;

    extern __shared__ char smc[];
    const uint32_t sbase = (uint32_t)__cvta_generic_to_shared(smc);
    const int tid  = threadIdx.x;
    const int lane = tid & 31;
    const int wid  = tid >> 5;
    const int wr   = wid / WC, wc = wid % WC;
    const int mb0  = wr * MI;
    const int nb0  = wc * NI;
    const int bm = blockIdx.y * MB, bn = blockIdx.x * NB;

    float acc[MI][NI][4];
#pragma unroll
    for (int i = 0; i < MI; i++)
#pragma unroll
        for (int n = 0; n < NI; n++)
#pragma unroll
            for (int q = 0; q < 4; q++) acc[i][n][q] = 0.f;

    const int T = Kd >> 6;

    auto fill = [&](int t) {
        int st = t - (t/3)*3;
        uint32_t ab = sbase + st*STGB;
        uint32_t bb = ab + ASZB;
        int k0 = t * 64;
#pragma unroll
        for (int ch = 0; ch < ACH; ch++) {
            int idx = tid + ch*NTH;
            int row = idx >> 3, c = idx & 7;
            uint32_t dst = ab + row*128 + ((c ^ (row & 7)) << 4);
            cp16(dst, A + (size_t)(bm + row)*lda + k0 + c*8, true);
        }
#pragma unroll
        for (int ch = 0; ch < BCH; ch++) {
            int idx = tid + ch*NTH;
            int row = idx >> 3, c = idx & 7;
            int gn = bn + row;
            bool p = gn < N;
            uint32_t dst = bb + row*128 + ((c ^ (row & 7)) << 4);
            cp16(dst, W + (size_t)(p ? gn : 0)*ldw + k0 + c*8, p);
        }
        asm volatile("cp.async.commit_group;" ::: "memory");
    };

    const int mi = lane >> 3;
    const int aRowLoc = (mi & 1)*8 + (lane & 7);
    const int aCb = mi >> 1;
    const int bRowLoc = lane & 7;
    const int bBlk = mi >> 1;
    const int bCb = mi & 1;
    uint32_t aRowOff[MI], aS[MI];
#pragma unroll
    for (int i = 0; i < MI; i++) {
        int row = (mb0 + i)*16 + aRowLoc;
        aRowOff[i] = row*128;
        aS[i] = (row & 7) << 4;
    }
    uint32_t bRowOff[NI/2], bS[NI/2];
#pragma unroll
    for (int j = 0; j < NI/2; j++) {
        int nr = (nb0 + j*2 + bBlk)*8 + bRowLoc;
        bRowOff[j] = nr*128;
        bS[j] = (nr & 7) << 4;
    }

    fill(0);
    fill(1);

    for (int t = 0; t < T; t++) {
        if (t == T - 1)
            asm volatile("cp.async.wait_group 0;" ::: "memory");
        else
            asm volatile("cp.async.wait_group 1;" ::: "memory");
        __syncthreads();
        int st = t - (t/3)*3;
        uint32_t ab = sbase + st*STGB;
        uint32_t bb = ab + ASZB;
#pragma unroll
        for (int kb = 0; kb < 4; kb++) {
            uint32_t af[MI][4];
#pragma unroll
            for (int i = 0; i < MI; i++)
                ldsm4(af[i][0], af[i][1], af[i][2], af[i][3],
                      ab + aRowOff[i] + ((((kb*2 + aCb) << 4)) ^ aS[i]));
            uint32_t bf[NI][2];
#pragma unroll
            for (int j = 0; j < NI/2; j++)
                ldsm4(bf[j*2][0], bf[j*2][1], bf[j*2+1][0], bf[j*2+1][1],
                      bb + bRowOff[j] + ((((kb*2 + bCb) << 4)) ^ bS[j]));
#pragma unroll
            for (int i = 0; i < MI; i++)
#pragma unroll
                for (int n = 0; n < NI; n++)
                    mma_f16(acc[i][n], af[i], bf[n]);
        }
        if (t + 2 < T) fill(t + 2);
    }

    const int g = lane >> 2, tg = lane & 3;
    if (GLU) {
        __half* Ch = (__half*)Cv;
#pragma unroll
        for (int i = 0; i < MI; i++) {
            int r0 = bm + (mb0 + i)*16 + g;
            int r1 = r0 + 8;
#pragma unroll
            for (int n = 0; n < NI; n++) {
                int gn = bn + (nb0 + n)*8 + tg*2;
                if (gn < N) {
                    int col = gn >> 1;
                    Ch[(size_t)r0*ldc + col] = __float2half(siluf(acc[i][n][0]) * acc[i][n][1]);
                    Ch[(size_t)r1*ldc + col] = __float2half(siluf(acc[i][n][2]) * acc[i][n][3]);
                }
            }
        }
    } else {
        float* C = (float*)Cv;
#pragma unroll
        for (int i = 0; i < MI; i++) {
            int r0 = bm + (mb0 + i)*16 + g;
            int r1 = r0 + 8;
#pragma unroll
            for (int n = 0; n < NI; n++) {
                int gn = bn + (nb0 + n)*8 + tg*2;
                if (gn < N) {
                    float b0 = 0.f, b1 = 0.f;
                    if (bias) { b0 = bias[gn]; b1 = bias[gn+1]; }
                    float v0 = acc[i][n][0] + b0, v1 = acc[i][n][1] + b1;
                    float v2 = acc[i][n][2] + b0, v3 = acc[i][n][3] + b1;
                    if (addend) {
                        float2 a0 = *(const float2*)(addend + (size_t)r0*ldad + gn);
                        float2 a1 = *(const float2*)(addend + (size_t)r1*ldad + gn);
                        v0 += a0.x; v1 += a0.y; v2 += a1.x; v3 += a1.y;
                    }
                    *(float2*)(C + (size_t)r0*ldc + gn) = make_float2(v0, v1);
                    *(float2*)(C + (size_t)r1*ldc + gn) = make_float2(v2, v3);
                }
            }
        }
    }
}

__global__ void casc_attn_kernel() {
    __shared__ float ks[KK][DH+1];
    __shared__ float vs[KK][DH+1];
    int bh = blockIdx.x;
    int b = bh / NHH, nh = bh % NHH;
    int t = threadIdx.x;
    const float* base = g_qkv + ((size_t)(b*KK + t)) * (3*HH);
#pragma unroll
    for (int dd = 0; dd < DH; dd++) {
        ks[t][dd] = base[HH   + nh*DH + dd];
        vs[t][dd] = base[2*HH + nh*DH + dd];
    }
    __syncthreads();
    float q[DH];
#pragma unroll
    for (int dd = 0; dd < DH; dd++) q[dd] = base[nh*DH + dd];

    const float scale = 0.125f;
    float sc[KK];
    float mx = -1e30f;
    for (int j = 0; j <= t; j++) {
        float s = 0.f;
#pragma unroll
        for (int dd = 0; dd < DH; dd++) s += q[dd] * ks[j][dd];
        s *= scale;
        sc[j] = s;
        mx = fmaxf(mx, s);
    }
    float sum = 0.f;
    for (int j = 0; j <= t; j++) {
        float e = expf(sc[j] - mx);
        sc[j] = e;
        sum += e;
    }
    float inv = 1.0f / sum;
    __half* o = h_attn + ((size_t)(b*KK + t)) * HH + nh*DH;
#pragma unroll 4
    for (int dd = 0; dd < DH; dd++) {
        float acc = 0.f;
        for (int j = 0; j <= t; j++) acc += sc[j] * vs[j][dd];
        o[dd] = __float2half(acc * inv);
    }
}

__global__ void dec_attn_kernel() {
    __shared__ float ks[KK][DH+1];
    __shared__ float vs[KK][DH+1];
    __shared__ float qs[8][DH];
    __shared__ float probs[8][KK];
    int nh = blockIdx.x, b = blockIdx.y, z = blockIdx.z;
    int tid = threadIdx.x;
    for (int i = tid; i < KK*DH; i += 256) {
        int c = i / DH, dd = i % DH;
        const float* kvrow = g_kv + ((size_t)(b*KK + c)) * (2*HH);
        ks[c][dd] = kvrow[nh*DH + dd];
        vs[c][dd] = kvrow[HH + nh*DH + dd];
    }
    __syncthreads();
    int w = tid >> 5, lane = tid & 31;
    const float scale = 0.125f;
    const int s0b = z * (SS/8), s1b = s0b + (SS/8);
    for (int s = s0b + w; s < s1b; s += 8) {
        int nallow = min(KK, s/32 + 2);
        const float* qrow = g_q + ((size_t)b*SS + s) * HH + nh*DH;
        qs[w][lane]      = qrow[lane];
        qs[w][lane + 32] = qrow[lane + 32];
        __syncwarp();
        float s0 = -INFINITY, s1 = -INFINITY;
        if (lane < nallow) {
            float acc = 0.f;
#pragma unroll
            for (int dd = 0; dd < DH; dd++) acc += qs[w][dd] * ks[lane][dd];
            s0 = acc * scale;
        }
        if (lane + 32 < nallow) {
            float acc = 0.f;
#pragma unroll
            for (int dd = 0; dd < DH; dd++) acc += qs[w][dd] * ks[lane + 32][dd];
            s1 = acc * scale;
        }
        float mx = fmaxf(s0, s1);
#pragma unroll
        for (int ofs = 16; ofs > 0; ofs >>= 1)
            mx = fmaxf(mx, __shfl_xor_sync(0xffffffffu, mx, ofs));
        float e0 = expf(s0 - mx);
        float e1 = expf(s1 - mx);
        float sum = e0 + e1;
#pragma unroll
        for (int ofs = 16; ofs > 0; ofs >>= 1)
            sum += __shfl_xor_sync(0xffffffffu, sum, ofs);
        float inv = 1.0f / sum;
        probs[w][lane]      = e0 * inv;
        probs[w][lane + 32] = e1 * inv;
        __syncwarp();
        __half* orow = h_dec + ((size_t)b*SS + s) * HH + nh*DH;
#pragma unroll
        for (int half2i = 0; half2i < 2; half2i++) {
            int dd = lane + half2i*32;
            float acc = 0.f;
            for (int j = 0; j < nallow; j++) acc += probs[w][j] * vs[j][dd];
            orow[dd] = __float2half(acc);
        }
        __syncwarp();
    }
}

template<typename T>
static T* symaddr(const void* sym) {
    void* p = nullptr;
    cudaGetSymbolAddress(&p, sym);
    return (T*)p;
}

#define SMEM_D (3*(128 + 256)*128)
#define SMEM_C (3*(64  + 128)*128)

extern "C" void kernel_launch(void* const* d_in, const int* in_sizes, int n_in,
                              void* d_out, int out_size) {
    const float* token       = (const float*)d_in[0];
    const float* chunk_repr  = (const float*)d_in[1];
    const float* cw          = (const float*)d_in[2];
    const float* casc_norm1  = (const float*)d_in[3];
    const float* casc_qkv    = (const float*)d_in[4];
    const float* casc_o      = (const float*)d_in[5];
    const float* casc_norm2  = (const float*)d_in[6];
    const float* casc_w1     = (const float*)d_in[7];
    const float* casc_w2     = (const float*)d_in[8];
    const float* casc_w3     = (const float*)d_in[9];
    const float* dec_in_w    = (const float*)d_in[10];
    const float* dec_in_b    = (const float*)d_in[11];
    const float* dec_out_w   = (const float*)d_in[12];
    const float* dec_out_b   = (const float*)d_in[13];
    const float* dec_norm_w  = (const float*)d_in[14];
    const float* dec_ffn_nw  = (const float*)d_in[15];
    const float* dec_w1      = (const float*)d_in[16];
    const float* dec_w2      = (const float*)d_in[17];
    const float* dec_w3      = (const float*)d_in[18];
    float* out = (float*)d_out;

    float* px    = symaddr<float>(g_x);
    float* pqkv  = symaddr<float>(g_qkv);
    float* pq    = symaddr<float>(g_q);
    float* pkv   = symaddr<float>(g_kv);
    float* py    = symaddr<float>(g_y);
    float* pyn   = symaddr<float>(g_yn);

    __half* ph_tok  = symaddr<__half>(h_tok);
    __half* ph_h    = symaddr<__half>(h_h);
    __half* ph_attn = symaddr<__half>(h_attn);
    __half* ph_proc = symaddr<__half>(h_proc);
    __half* ph_ff   = symaddr<__half>(h_ff);
    __half* ph_dec  = symaddr<__half>(h_dec);
    __half* ph_yn   = symaddr<__half>(h_yn);
    __half* ph_u    = symaddr<__half>(h_u);

    __half* pw_qkv  = symaddr<__half>(wh_qkv);
    __half* pw_o    = symaddr<__half>(wh_o);
    __half* pw_w13  = symaddr<__half>(wh_w13);
    __half* pw_w2   = symaddr<__half>(wh_w2);
    __half* pw_din  = symaddr<__half>(wh_din);
    __half* pw_dout = symaddr<__half>(wh_dout);
    __half* pw_dw13 = symaddr<__half>(wh_dw13);
    __half* pw_dw2  = symaddr<__half>(wh_dw2);

    cudaFuncSetAttribute((const void*)hgemm<128,256,2,8,0>,
                         cudaFuncAttributeMaxDynamicSharedMemorySize, SMEM_D);
    cudaFuncSetAttribute((const void*)hgemm<128,256,2,8,1>,
                         cudaFuncAttributeMaxDynamicSharedMemorySize, SMEM_D);
    cudaFuncSetAttribute((const void*)hgemm<64,128,2,8,0>,
                         cudaFuncAttributeMaxDynamicSharedMemorySize, SMEM_C);
    cudaFuncSetAttribute((const void*)hgemm<64,128,2,8,1>,
                         cudaFuncAttributeMaxDynamicSharedMemorySize, SMEM_C);

    auto gemmD = [&](cudaStream_t st, const __half* A, int lda, const __half* W, int ldw,
                     const float* bias, const float* addend, int ldad,
                     void* C, int ldc, int M, int N, int Kd, bool glu) {
        dim3 grid((N + 255)/256, M/128);
        if (glu)
            hgemm<128,256,2,8,1><<<grid, NTH, SMEM_D, st>>>(A, lda, W, ldw, bias, addend, ldad,
                                                            C, ldc, M, N, Kd);
        else
            hgemm<128,256,2,8,0><<<grid, NTH, SMEM_D, st>>>(A, lda, W, ldw, bias, addend, ldad,
                                                            C, ldc, M, N, Kd);
    };
    auto gemmC = [&](cudaStream_t st, const __half* A, int lda, const __half* W, int ldw,
                     const float* bias, const float* addend, int ldad,
                     void* C, int ldc, int M, int N, int Kd, bool glu) {
        dim3 grid((N + 127)/128, M/64);
        if (glu)
            hgemm<64,128,2,8,1><<<grid, NTH, SMEM_C, st>>>(A, lda, W, ldw, bias, addend, ldad,
                                                           C, ldc, M, N, Kd);
        else
            hgemm<64,128,2,8,0><<<grid, NTH, SMEM_C, st>>>(A, lda, W, ldw, bias, addend, ldad,
                                                           C, ldc, M, N, Kd);
    };

    cudaStream_t main0 = 0;
    cudaStream_t side;
    cudaStreamCreateWithFlags(&side, cudaStreamNonBlocking);
    cudaEvent_t evFork, evJoin;
    cudaEventCreateWithFlags(&evFork, cudaEventDisableTiming);
    cudaEventCreateWithFlags(&evJoin, cudaEventDisableTiming);

    // ---- fork: side = decoder prep + q projection (independent of cascade) ----
    cudaEventRecord(evFork, main0);
    cudaStreamWaitEvent(side, evFork, 0);
    halfcopy_kernel<<<2048, 256, 0, side>>>(dec_in_w,  pw_din,  3*HH*HH/2);
    halfcopy_kernel<<<2048, 256, 0, side>>>(dec_out_w, pw_dout, HH*HH/2);
    w13i_kernel<<<FI2, 256, 0, side>>>(dec_w1, dec_w3, pw_dw13);
    w2half_kernel<<<HH, 256, 0, side>>>(dec_w2, pw_dw2);
    halfcopy_kernel<<<4096, 256, 0, side>>>(token, ph_tok, BB*SS*HH/2);
    gemmD(side, ph_tok, HH, pw_din, HH,
          dec_in_b, nullptr, 0, pq, HH, BB*SS, HH, HH, false);
    cudaEventRecord(evJoin, side);

    // ---- main: cascade weight prep + cascade ----
    halfcopy_kernel<<<2048, 256>>>(casc_qkv, pw_qkv, LL*3*HH*HH/2);
    halfcopy_kernel<<<2048, 256>>>(casc_o,   pw_o,   LL*HH*HH/2);
    for (int l = 0; l < LL; l++) {
        w13i_kernel<<<FI2, 256>>>(casc_w1 + (size_t)l*FFD*HH,
                                  casc_w3 + (size_t)l*FFD*HH,
                                  pw_w13 + (size_t)l*FI2*HH);
        w2half_kernel<<<HH, 256>>>(casc_w2 + (size_t)l*HH*FFD,
                                   pw_w2 + (size_t)l*HH*FFH);
    }
    rank_kernel<<<BB, KK>>>(cw);
    scatter_kernel<<<BB*KK, 256>>>(chunk_repr);

    const int MC = BB*KK;
    for (int l = 0; l < LL; l++) {
        rms_kernel<__half><<<MC, 256>>>(px, casc_norm1 + l*HH, ph_h);
        gemmC(main0, ph_h, HH, pw_qkv + (size_t)l*3*HH*HH, HH,
              nullptr, nullptr, 0, pqkv, 3*HH, MC, 3*HH, HH, false);
        casc_attn_kernel<<<BB*NHH, KK>>>();
        gemmC(main0, ph_attn, HH, pw_o + (size_t)l*HH*HH, HH,
              nullptr, px, HH, px, HH, MC, HH, HH, false);
        rms_kernel<__half><<<MC, 256>>>(px, casc_norm2 + l*HH, ph_h);
        gemmC(main0, ph_h, HH, pw_w13 + (size_t)l*FI2*HH, HH,
              nullptr, nullptr, 0, ph_ff, FFH, MC, FI2, HH, true);
        gemmC(main0, ph_ff, FFH, pw_w2 + (size_t)l*HH*FFH, FFH,
              nullptr, px, HH, px, HH, MC, HH, FFH, false);
    }
    gather_kernel<<<BB*KK, 256>>>();

    // ---- join BEFORE kv gemm (it reads pw_din produced on side) ----
    cudaStreamWaitEvent(main0, evJoin, 0);
    gemmC(main0, ph_proc, HH, pw_din + (size_t)HH*HH, HH,
          dec_in_b + HH, nullptr, 0, pkv, 2*HH, MC, 2*HH, HH, false);
    dec_attn_kernel<<<dim3(NHH, BB, 8), 256>>>();

    const int MT = BB*SS;
    gemmD(main0, ph_dec, HH, pw_dout, HH,
          dec_out_b, token, HH, pyn, HH, MT, HH, HH, false);
    rms2_kernel<<<MT, 256>>>(pyn, dec_norm_w, dec_ffn_nw, py, ph_yn);
    gemmD(main0, ph_yn, HH, pw_dw13, HH,
          nullptr, nullptr, 0, ph_u, FFH, MT, FI2, HH, true);
    gemmD(main0, ph_u, FFH, pw_dw2, FFH,
          nullptr, py, HH, out, HH, MT, HH, FFH, false);
}